// round 9
// baseline (speedup 1.0000x reference)
#include <cuda_runtime.h>
#include <cuda_bf16.h>
#include <math.h>
#include <stdint.h>

#define Bb 4
#define Ss 2048
#define Ee 1024
#define Hh 16
#define Dk 64
#define Mm (Bb*Ss)   /* 8192 */

// ------------------------- device scratch (no allocs) ----------------------
__device__ __nv_bfloat16 g_xhi[Mm*Ee];
__device__ __nv_bfloat16 g_xlo[Mm*Ee];
__device__ __nv_bfloat16 g_qkvhi[3*Mm*Ee];   // q | k | v
__device__ __nv_bfloat16 g_qkvlo[3*Mm*Ee];
__device__ __nv_bfloat16 g_chi[Mm*Ee];
__device__ __nv_bfloat16 g_clo[Mm*Ee];
__device__ __nv_bfloat16 g_whi[4*Ee*Ee];
__device__ __nv_bfloat16 g_wlo[4*Ee*Ee];

// ------------------------- helpers ------------------------------------------
__device__ __forceinline__ void mma16816(float* d, const uint32_t* a,
                                         const uint32_t* b)
{
    asm volatile(
        "mma.sync.aligned.m16n8k16.row.col.f32.bf16.bf16.f32 "
        "{%0,%1,%2,%3}, {%4,%5,%6,%7}, {%8,%9}, {%0,%1,%2,%3};"
        : "+f"(d[0]), "+f"(d[1]), "+f"(d[2]), "+f"(d[3])
        : "r"(a[0]), "r"(a[1]), "r"(a[2]), "r"(a[3]), "r"(b[0]), "r"(b[1]));
}
__device__ __forceinline__ void ldsm_x4(uint32_t* r, uint32_t addr) {
    asm volatile("ldmatrix.sync.aligned.m8n8.x4.shared.b16 {%0,%1,%2,%3}, [%4];"
        : "=r"(r[0]), "=r"(r[1]), "=r"(r[2]), "=r"(r[3]) : "r"(addr));
}
__device__ __forceinline__ void ldsm_x4_t(uint32_t* r, uint32_t addr) {
    asm volatile("ldmatrix.sync.aligned.m8n8.x4.trans.shared.b16 {%0,%1,%2,%3}, [%4];"
        : "=r"(r[0]), "=r"(r[1]), "=r"(r[2]), "=r"(r[3]) : "r"(addr));
}
__device__ __forceinline__ uint32_t smem_u32(const void* p) {
    uint32_t a;
    asm("{ .reg .u64 t; cvta.to.shared.u64 t, %1; cvt.u32.u64 %0, t; }"
        : "=r"(a) : "l"(p));
    return a;
}
__device__ __forceinline__ void cpa16(uint32_t s, const void* g) {
    asm volatile("cp.async.cg.shared.global [%0], [%1], 16;" :: "r"(s), "l"(g));
}
#define CPA_COMMIT() asm volatile("cp.async.commit_group;" ::: "memory")
#define CPA_WAIT1()  asm volatile("cp.async.wait_group 1;" ::: "memory")
#define CPA_WAIT0()  asm volatile("cp.async.wait_group 0;" ::: "memory")

__device__ __forceinline__ uint32_t pack_hi(float x, float y) {
    __nv_bfloat162 h = __floats2bfloat162_rn(x, y);
    return *(uint32_t*)&h;
}
__device__ __forceinline__ uint32_t pack_lo(float x, float y, uint32_t hiu) {
    __nv_bfloat162 h = *(__nv_bfloat162*)&hiu;
    __nv_bfloat162 l = __floats2bfloat162_rn(x - __bfloat162float(h.x),
                                             y - __bfloat162float(h.y));
    return *(uint32_t*)&l;
}
__device__ __forceinline__ float unp_lo(uint32_t u) {
    return __uint_as_float(u << 16);
}
__device__ __forceinline__ float unp_hi(uint32_t u) {
    return __uint_as_float(u & 0xffff0000u);
}

// ------------------------- fp32 -> bf16 hi/lo splits -------------------------
__global__ __launch_bounds__(256) void split_kernel(const float4* __restrict__ src,
                                                    __nv_bfloat16* __restrict__ hi,
                                                    __nv_bfloat16* __restrict__ lo,
                                                    int n4)
{
    int i = blockIdx.x * 256 + threadIdx.x;
    if (i >= n4) return;
    float4 v = src[i];
    uint32_t h0 = pack_hi(v.x, v.y), h1 = pack_hi(v.z, v.w);
    uint32_t l0 = pack_lo(v.x, v.y, h0), l1 = pack_lo(v.z, v.w, h1);
    uint32_t* hp = (uint32_t*)(hi + (size_t)i * 4);
    uint32_t* lp = (uint32_t*)(lo + (size_t)i * 4);
    hp[0] = h0; hp[1] = h1; lp[0] = l0; lp[1] = l1;
}

__global__ __launch_bounds__(256) void split4_kernel(
    const float4* __restrict__ s0, const float4* __restrict__ s1,
    const float4* __restrict__ s2, const float4* __restrict__ s3,
    __nv_bfloat16* __restrict__ hi, __nv_bfloat16* __restrict__ lo, int n4)
{
    int z = blockIdx.y;
    const float4* src = (z == 0) ? s0 : (z == 1) ? s1 : (z == 2) ? s2 : s3;
    int i = blockIdx.x * 256 + threadIdx.x;
    if (i >= n4) return;
    float4 v = src[i];
    uint32_t h0 = pack_hi(v.x, v.y), h1 = pack_hi(v.z, v.w);
    uint32_t l0 = pack_lo(v.x, v.y, h0), l1 = pack_lo(v.z, v.w, h1);
    size_t off = (size_t)z * Ee * Ee + (size_t)i * 4;
    uint32_t* hp = (uint32_t*)(hi + off);
    uint32_t* lp = (uint32_t*)(lo + off);
    hp[0] = h0; hp[1] = h1; lp[0] = l0; lp[1] = l1;
}

// ------------------------- HMMA split-bf16 GEMM (unchanged, 3-term) ----------
#define PCH 72
#define TA_B (256 * PCH * 2)              /* 36864 */
#define TW_B (128 * PCH * 2)              /* 18432 */
#define GSTAGE (2*TA_B + 2*TW_B)          /* 110592 */
#define GEMM_SMEM (GSTAGE * 2)            /* 221184 */

template<bool DO_COS>
__global__ __launch_bounds__(512, 1) void hmma_gemm(
    const __nv_bfloat16* __restrict__ Ahi, const __nv_bfloat16* __restrict__ Alo,
    const __nv_bfloat16* __restrict__ WhiB, const __nv_bfloat16* __restrict__ WloB,
    const float* __restrict__ theta,
    float* __restrict__ C,
    __nv_bfloat16* __restrict__ OHB, __nv_bfloat16* __restrict__ OLB)
{
    extern __shared__ __align__(16) char smem[];
    uint32_t sb = smem_u32(smem);

    int z = blockIdx.z;
    const __nv_bfloat16* Whi = WhiB + (size_t)z * Ee * Ee;
    const __nv_bfloat16* Wlo = WloB + (size_t)z * Ee * Ee;

    int tid = threadIdx.x, wid = tid >> 5, lane = tid & 31;
    int wm = wid & 3, wn = wid >> 2;
    int g = lane >> 2, t = lane & 3;
    int lm = lane >> 3, li = lane & 7;
    int m0 = blockIdx.y * 256, n0 = blockIdx.x * 128;

    float acc[4][4][4] = {};

    auto issue = [&](int c, int bs) {
        uint32_t b0 = sb + bs * GSTAGE;
#pragma unroll
        for (int u = 0; u < 4; u++) {
            int unit = tid + u * 512;
            int row = unit >> 3, seg = unit & 7;
            size_t gA = (size_t)(m0 + row) * Ee + c * 64 + seg * 8;
            uint32_t so = (uint32_t)(row * PCH + seg * 8) * 2;
            cpa16(b0 + so,        Ahi + gA);
            cpa16(b0 + TA_B + so, Alo + gA);
        }
#pragma unroll
        for (int u = 0; u < 2; u++) {
            int unit = tid + u * 512;
            int row = unit >> 3, seg = unit & 7;
            size_t gW = (size_t)(n0 + row) * Ee + c * 64 + seg * 8;
            uint32_t so = (uint32_t)(row * PCH + seg * 8) * 2;
            cpa16(b0 + 2 * TA_B + so,        Whi + gW);
            cpa16(b0 + 2 * TA_B + TW_B + so, Wlo + gW);
        }
    };

    issue(0, 0); CPA_COMMIT();
    issue(1, 1); CPA_COMMIT();

    for (int c = 0; c < 16; c++) {
        if (c == 15) CPA_WAIT0(); else CPA_WAIT1();
        __syncthreads();

        uint32_t bufA = sb + (c & 1) * GSTAGE;
        uint32_t bufW = bufA + 2 * TA_B;

#pragma unroll
        for (int ks = 0; ks < 4; ks++) {
            uint32_t ah[4][4], al[4][4];
#pragma unroll
            for (int mf = 0; mf < 4; mf++) {
                uint32_t ad = bufA +
                    (uint32_t)(((wm * 64 + mf * 16 + (lm & 1) * 8 + li) * PCH)
                               + ks * 16 + (lm >> 1) * 8) * 2;
                ldsm_x4(ah[mf], ad);
                ldsm_x4(al[mf], ad + TA_B);
            }
#pragma unroll
            for (int nfp = 0; nfp < 2; nfp++) {
                uint32_t bd = bufW +
                    (uint32_t)(((wn * 32 + (nfp * 2 + (lm >> 1)) * 8 + li) * PCH)
                               + ks * 16 + (lm & 1) * 8) * 2;
                uint32_t bh[4], bl[4];
                ldsm_x4(bh, bd);
                ldsm_x4(bl, bd + TW_B);
#pragma unroll
                for (int mf = 0; mf < 4; mf++) {
                    mma16816(acc[mf][nfp*2],   ah[mf], bh);
                    mma16816(acc[mf][nfp*2+1], ah[mf], bh + 2);
                }
#pragma unroll
                for (int mf = 0; mf < 4; mf++) {
                    mma16816(acc[mf][nfp*2],   ah[mf], bl);
                    mma16816(acc[mf][nfp*2+1], ah[mf], bl + 2);
                }
#pragma unroll
                for (int mf = 0; mf < 4; mf++) {
                    mma16816(acc[mf][nfp*2],   al[mf], bh);
                    mma16816(acc[mf][nfp*2+1], al[mf], bh + 2);
                }
            }
        }
        __syncthreads();
        if (c < 14) { issue(c + 2, c & 1); CPA_COMMIT(); }
    }

    __nv_bfloat16* OH = DO_COS ? OHB + (size_t)z * Mm * Ee : nullptr;
    __nv_bfloat16* OL = DO_COS ? OLB + (size_t)z * Mm * Ee : nullptr;
#pragma unroll
    for (int mf = 0; mf < 4; mf++) {
#pragma unroll
        for (int nf = 0; nf < 4; nf++) {
            int r = m0 + wm * 64 + mf * 16 + g;
            int cb = n0 + wn * 32 + nf * 8 + 2 * t;
            float v0 = acc[mf][nf][0], v1 = acc[mf][nf][1];
            float v2 = acc[mf][nf][2], v3 = acc[mf][nf][3];
            if (DO_COS) {
                float t0 = theta[cb & 63], t1 = theta[(cb + 1) & 63];
                v0 = cosf(v0 + t0); v1 = cosf(v1 + t1);
                v2 = cosf(v2 + t0); v3 = cosf(v3 + t1);
                uint32_t h0 = pack_hi(v0, v1), h1 = pack_hi(v2, v3);
                *(uint32_t*)&OH[(size_t)r * Ee + cb]       = h0;
                *(uint32_t*)&OH[(size_t)(r + 8) * Ee + cb] = h1;
                *(uint32_t*)&OL[(size_t)r * Ee + cb]       = pack_lo(v0, v1, h0);
                *(uint32_t*)&OL[(size_t)(r + 8) * Ee + cb] = pack_lo(v2, v3, h1);
            } else {
                *(float2*)&C[(size_t)r * Ee + cb]       = float2{v0, v1};
                *(float2*)&C[(size_t)(r + 8) * Ee + cb] = float2{v2, v3};
            }
        }
    }
}

// ------------------------- HMMA flash attention (1-term QK, 1-term PV) -------
// Per stage: Kh | Vh, each 128 rows x 64 d, pitch 72 bf16.
#define PKV 72
#define KVB (128 * PKV * 2)              /* 18432 */
#define STAGEB (KVB * 2)                 /* 36864 */
#define ATT_SMEM (STAGEB * 3)            /* 110592 */

__global__ __launch_bounds__(256, 1) void attn_mma(
    const __nv_bfloat16* __restrict__ qhi,
    const __nv_bfloat16* __restrict__ khi,
    const __nv_bfloat16* __restrict__ vhi,
    __nv_bfloat16* __restrict__ chi, __nv_bfloat16* __restrict__ clo)
{
    extern __shared__ __align__(16) char smem[];
    uint32_t sb = smem_u32(smem);

    int tid = threadIdx.x, wid = tid >> 5, lane = tid & 31;
    int g = lane >> 2, t = lane & 3;
    int lm = lane >> 3, li = lane & 7;
    int bh_ = blockIdx.y;
    int b = bh_ >> 4, h = bh_ & 15;
    int q0 = blockIdx.x * 128;
    size_t base = (size_t)b * Ss * Ee + (size_t)h * Dk;

    uint32_t qh[4][4];
    {
        size_t r0 = base + (size_t)(q0 + wid * 16 + g) * Ee;
        size_t r1 = r0 + 8 * (size_t)Ee;
#pragma unroll
        for (int ks = 0; ks < 4; ks++) {
            int c0 = ks * 16 + 2 * t;
            qh[ks][0] = *(const uint32_t*)&qhi[r0 + c0];
            qh[ks][1] = *(const uint32_t*)&qhi[r1 + c0];
            qh[ks][2] = *(const uint32_t*)&qhi[r0 + c0 + 8];
            qh[ks][3] = *(const uint32_t*)&qhi[r1 + c0 + 8];
        }
    }

    auto issue = [&](int j0, int s) {
        uint32_t b0 = sb + s * STAGEB;
#pragma unroll
        for (int u = 0; u < 4; u++) {
            int unit = tid + u * 256;
            int row = unit >> 3, seg = unit & 7;
            size_t gk = base + (size_t)(j0 + row) * Ee + seg * 8;
            uint32_t so = (uint32_t)(row * PKV + seg * 8) * 2;
            cpa16(b0 + so,       khi + gk);
            cpa16(b0 + KVB + so, vhi + gk);
        }
    };

    float m0 = -1e30f, m1 = -1e30f, l0 = 0.0f, l1 = 0.0f;
    float out[8][4] = {};

    issue(0, 0);   CPA_COMMIT();
    issue(128, 1); CPA_COMMIT();

    for (int tile = 0; tile < 16; tile++) {
        if (tile == 15) CPA_WAIT0(); else CPA_WAIT1();
        __syncthreads();
        if (tile < 14) { issue((tile + 2) * 128, (tile + 2) % 3); CPA_COMMIT(); }

        uint32_t kb = sb + (tile % 3) * STAGEB;
        uint32_t vb = kb + KVB;

        // QK^T (1-term: qh * kh) -> s[16][4]
        float s[16][4] = {};
#pragma unroll
        for (int ks = 0; ks < 4; ks++) {
#pragma unroll
            for (int nfp = 0; nfp < 8; nfp++) {
                uint32_t ad = kb +
                    (uint32_t)(((nfp * 2 + (lm >> 1)) * 8 + li) * PKV
                               + ks * 16 + (lm & 1) * 8) * 2;
                uint32_t bhv[4];
                ldsm_x4(bhv, ad);
                mma16816(s[nfp*2],   qh[ks], bhv);
                mma16816(s[nfp*2+1], qh[ks], bhv + 2);
            }
        }

        float mx0 = -1e30f, mx1 = -1e30f;
#pragma unroll
        for (int nf = 0; nf < 16; nf++) {
            mx0 = fmaxf(mx0, fmaxf(s[nf][0], s[nf][1]));
            mx1 = fmaxf(mx1, fmaxf(s[nf][2], s[nf][3]));
        }
        mx0 = fmaxf(mx0, __shfl_xor_sync(0xffffffffu, mx0, 1));
        mx0 = fmaxf(mx0, __shfl_xor_sync(0xffffffffu, mx0, 2));
        mx1 = fmaxf(mx1, __shfl_xor_sync(0xffffffffu, mx1, 1));
        mx1 = fmaxf(mx1, __shfl_xor_sync(0xffffffffu, mx1, 2));
        float mn0 = fmaxf(m0, mx0), mn1 = fmaxf(m1, mx1);
        float sc0 = __expf(0.125f * (m0 - mn0));
        float sc1 = __expf(0.125f * (m1 - mn1));
#pragma unroll
        for (int nf = 0; nf < 16; nf++) {
            s[nf][0] = __expf(0.125f * (s[nf][0] - mn0));
            s[nf][1] = __expf(0.125f * (s[nf][1] - mn0));
            s[nf][2] = __expf(0.125f * (s[nf][2] - mn1));
            s[nf][3] = __expf(0.125f * (s[nf][3] - mn1));
        }

        // pack P to bf16; normalizer computed from ROUNDED p values
        uint32_t pa[8][4];
        float sum0 = 0.0f, sum1 = 0.0f;
#pragma unroll
        for (int k2 = 0; k2 < 8; k2++) {
            pa[k2][0] = pack_hi(s[2*k2][0],   s[2*k2][1]);
            pa[k2][1] = pack_hi(s[2*k2][2],   s[2*k2][3]);
            pa[k2][2] = pack_hi(s[2*k2+1][0], s[2*k2+1][1]);
            pa[k2][3] = pack_hi(s[2*k2+1][2], s[2*k2+1][3]);
            sum0 += unp_lo(pa[k2][0]) + unp_hi(pa[k2][0])
                  + unp_lo(pa[k2][2]) + unp_hi(pa[k2][2]);
            sum1 += unp_lo(pa[k2][1]) + unp_hi(pa[k2][1])
                  + unp_lo(pa[k2][3]) + unp_hi(pa[k2][3]);
        }
        sum0 += __shfl_xor_sync(0xffffffffu, sum0, 1);
        sum0 += __shfl_xor_sync(0xffffffffu, sum0, 2);
        sum1 += __shfl_xor_sync(0xffffffffu, sum1, 1);
        sum1 += __shfl_xor_sync(0xffffffffu, sum1, 2);
        l0 = l0 * sc0 + sum0;
        l1 = l1 * sc1 + sum1;
        m0 = mn0; m1 = mn1;
#pragma unroll
        for (int nfo = 0; nfo < 8; nfo++) {
            out[nfo][0] *= sc0; out[nfo][1] *= sc0;
            out[nfo][2] *= sc1; out[nfo][3] *= sc1;
        }

        // PV (1-term: p_hat * vh), B via ldmatrix.trans
#pragma unroll
        for (int ks2 = 0; ks2 < 8; ks2++) {
#pragma unroll
            for (int nfp = 0; nfp < 4; nfp++) {
                uint32_t ad = vb +
                    (uint32_t)((ks2 * 16 + (lm & 1) * 8 + li) * PKV
                               + (nfp * 2 + (lm >> 1)) * 8) * 2;
                uint32_t bvh[4];
                ldsm_x4_t(bvh, ad);
                mma16816(out[nfp*2],   pa[ks2], bvh);
                mma16816(out[nfp*2+1], pa[ks2], bvh + 2);
            }
        }
    }

    float inv0 = 1.0f / l0, inv1 = 1.0f / l1;
    size_t r0 = base + (size_t)(q0 + wid * 16 + g) * Ee;
    size_t r1 = r0 + 8 * (size_t)Ee;
#pragma unroll
    for (int nfo = 0; nfo < 8; nfo++) {
        int d = nfo * 8 + 2 * t;
        float v0 = out[nfo][0] * inv0, v1 = out[nfo][1] * inv0;
        float v2 = out[nfo][2] * inv1, v3 = out[nfo][3] * inv1;
        uint32_t h0 = pack_hi(v0, v1), h1 = pack_hi(v2, v3);
        *(uint32_t*)&chi[r0 + d] = h0;
        *(uint32_t*)&chi[r1 + d] = h1;
        *(uint32_t*)&clo[r0 + d] = pack_lo(v0, v1, h0);
        *(uint32_t*)&clo[r1 + d] = pack_lo(v2, v3, h1);
    }
}

// ---------------------------------------------------------------------------
extern "C" void kernel_launch(void* const* d_in, const int* in_sizes, int n_in,
                              void* d_out, int out_size)
{
    const float* x     = (const float*)d_in[0];
    const float* Wq    = (const float*)d_in[1];
    const float* Wk    = (const float*)d_in[2];
    const float* Wv    = (const float*)d_in[3];
    const float* Wo    = (const float*)d_in[4];
    const float* theta = (const float*)d_in[5];
    float* out = (float*)d_out;

    __nv_bfloat16 *xhi, *xlo, *qkvhi, *qkvlo, *chi, *clo, *whi, *wlo;
    cudaGetSymbolAddress((void**)&xhi, g_xhi);
    cudaGetSymbolAddress((void**)&xlo, g_xlo);
    cudaGetSymbolAddress((void**)&qkvhi, g_qkvhi);
    cudaGetSymbolAddress((void**)&qkvlo, g_qkvlo);
    cudaGetSymbolAddress((void**)&chi, g_chi);
    cudaGetSymbolAddress((void**)&clo, g_clo);
    cudaGetSymbolAddress((void**)&whi, g_whi);
    cudaGetSymbolAddress((void**)&wlo, g_wlo);

    cudaFuncSetAttribute(hmma_gemm<true>,
        cudaFuncAttributeMaxDynamicSharedMemorySize, GEMM_SMEM);
    cudaFuncSetAttribute(hmma_gemm<false>,
        cudaFuncAttributeMaxDynamicSharedMemorySize, GEMM_SMEM);
    cudaFuncSetAttribute(attn_mma,
        cudaFuncAttributeMaxDynamicSharedMemorySize, ATT_SMEM);

    int n4x = Mm * Ee / 4;
    int n4w = Ee * Ee / 4;
    split_kernel<<<(n4x + 255) / 256, 256>>>((const float4*)x, xhi, xlo, n4x);
    dim3 gw((n4w + 255) / 256, 4);
    split4_kernel<<<gw, 256>>>((const float4*)Wq, (const float4*)Wk,
                               (const float4*)Wv, (const float4*)Wo,
                               whi, wlo, n4w);

    dim3 g1(Ee / 128, Mm / 256, 3);
    hmma_gemm<true><<<g1, 512, GEMM_SMEM>>>(xhi, xlo, whi, wlo, theta,
                                            nullptr, qkvhi, qkvlo);

    size_t off = (size_t)Mm * Ee;
    dim3 g2(Ss / 128, Bb * Hh);
    attn_mma<<<g2, 256, ATT_SMEM>>>(qkvhi,
                                    qkvhi + off,
                                    qkvhi + 2*off,
                                    chi, clo);

    dim3 g3(Ee / 128, Mm / 256, 1);
    hmma_gemm<false><<<g3, 512, GEMM_SMEM>>>(chi, clo,
        whi + 3*(size_t)Ee*Ee, wlo + 3*(size_t)Ee*Ee, nullptr, out,
        nullptr, nullptr);
}

// round 10
// speedup vs baseline: 1.5494x; 1.5494x over previous
#include <cuda_runtime.h>
#include <cuda_bf16.h>
#include <math.h>
#include <stdint.h>

#define Bb 4
#define Ss 2048
#define Ee 1024
#define Hh 16
#define Dk 64
#define Mm (Bb*Ss)   /* 8192 */

// ------------------------- device scratch (no allocs) ----------------------
__device__ __nv_bfloat16 g_xhi[Mm*Ee];
__device__ __nv_bfloat16 g_xlo[Mm*Ee];
__device__ __nv_bfloat16 g_qkvhi[3*Mm*Ee];   // q | k | v
__device__ __nv_bfloat16 g_qkvlo[3*Mm*Ee];
__device__ __nv_bfloat16 g_chi[Mm*Ee];
__device__ __nv_bfloat16 g_clo[Mm*Ee];
__device__ __nv_bfloat16 g_whi[4*Ee*Ee];
__device__ __nv_bfloat16 g_wlo[4*Ee*Ee];

// ------------------------- helpers ------------------------------------------
__device__ __forceinline__ void mma16816(float* d, const uint32_t* a,
                                         const uint32_t* b)
{
    asm volatile(
        "mma.sync.aligned.m16n8k16.row.col.f32.bf16.bf16.f32 "
        "{%0,%1,%2,%3}, {%4,%5,%6,%7}, {%8,%9}, {%0,%1,%2,%3};"
        : "+f"(d[0]), "+f"(d[1]), "+f"(d[2]), "+f"(d[3])
        : "r"(a[0]), "r"(a[1]), "r"(a[2]), "r"(a[3]), "r"(b[0]), "r"(b[1]));
}
__device__ __forceinline__ void ldsm_x4(uint32_t* r, uint32_t addr) {
    asm volatile("ldmatrix.sync.aligned.m8n8.x4.shared.b16 {%0,%1,%2,%3}, [%4];"
        : "=r"(r[0]), "=r"(r[1]), "=r"(r[2]), "=r"(r[3]) : "r"(addr));
}
__device__ __forceinline__ void ldsm_x4_t(uint32_t* r, uint32_t addr) {
    asm volatile("ldmatrix.sync.aligned.m8n8.x4.trans.shared.b16 {%0,%1,%2,%3}, [%4];"
        : "=r"(r[0]), "=r"(r[1]), "=r"(r[2]), "=r"(r[3]) : "r"(addr));
}
__device__ __forceinline__ uint32_t smem_u32(const void* p) {
    uint32_t a;
    asm("{ .reg .u64 t; cvta.to.shared.u64 t, %1; cvt.u32.u64 %0, t; }"
        : "=r"(a) : "l"(p));
    return a;
}
__device__ __forceinline__ void cpa16(uint32_t s, const void* g) {
    asm volatile("cp.async.cg.shared.global [%0], [%1], 16;" :: "r"(s), "l"(g));
}
#define CPA_COMMIT() asm volatile("cp.async.commit_group;" ::: "memory")
#define CPA_WAIT1()  asm volatile("cp.async.wait_group 1;" ::: "memory")
#define CPA_WAIT0()  asm volatile("cp.async.wait_group 0;" ::: "memory")

__device__ __forceinline__ uint32_t pack_hi(float x, float y) {
    __nv_bfloat162 h = __floats2bfloat162_rn(x, y);
    return *(uint32_t*)&h;
}
__device__ __forceinline__ uint32_t pack_lo(float x, float y, uint32_t hiu) {
    __nv_bfloat162 h = *(__nv_bfloat162*)&hiu;
    __nv_bfloat162 l = __floats2bfloat162_rn(x - __bfloat162float(h.x),
                                             y - __bfloat162float(h.y));
    return *(uint32_t*)&l;
}
__device__ __forceinline__ float unp_lo(uint32_t u) {
    return __uint_as_float(u << 16);
}
__device__ __forceinline__ float unp_hi(uint32_t u) {
    return __uint_as_float(u & 0xffff0000u);
}

// ------------------------- fp32 -> bf16 hi/lo splits -------------------------
__global__ __launch_bounds__(256) void split_kernel(const float4* __restrict__ src,
                                                    __nv_bfloat16* __restrict__ hi,
                                                    __nv_bfloat16* __restrict__ lo,
                                                    int n4)
{
    int i = blockIdx.x * 256 + threadIdx.x;
    if (i >= n4) return;
    float4 v = src[i];
    uint32_t h0 = pack_hi(v.x, v.y), h1 = pack_hi(v.z, v.w);
    uint32_t l0 = pack_lo(v.x, v.y, h0), l1 = pack_lo(v.z, v.w, h1);
    uint32_t* hp = (uint32_t*)(hi + (size_t)i * 4);
    uint32_t* lp = (uint32_t*)(lo + (size_t)i * 4);
    hp[0] = h0; hp[1] = h1; lp[0] = l0; lp[1] = l1;
}

__global__ __launch_bounds__(256) void split4_kernel(
    const float4* __restrict__ s0, const float4* __restrict__ s1,
    const float4* __restrict__ s2, const float4* __restrict__ s3,
    __nv_bfloat16* __restrict__ hi, __nv_bfloat16* __restrict__ lo, int n4)
{
    int z = blockIdx.y;
    const float4* src = (z == 0) ? s0 : (z == 1) ? s1 : (z == 2) ? s2 : s3;
    int i = blockIdx.x * 256 + threadIdx.x;
    if (i >= n4) return;
    float4 v = src[i];
    uint32_t h0 = pack_hi(v.x, v.y), h1 = pack_hi(v.z, v.w);
    uint32_t l0 = pack_lo(v.x, v.y, h0), l1 = pack_lo(v.z, v.w, h1);
    size_t off = (size_t)z * Ee * Ee + (size_t)i * 4;
    uint32_t* hp = (uint32_t*)(hi + off);
    uint32_t* lp = (uint32_t*)(lo + off);
    hp[0] = h0; hp[1] = h1; lp[0] = l0; lp[1] = l1;
}

// ------------------------- HMMA split-bf16 GEMM (unchanged, 3-term) ----------
#define PCH 72
#define TA_B (256 * PCH * 2)              /* 36864 */
#define TW_B (128 * PCH * 2)              /* 18432 */
#define GSTAGE (2*TA_B + 2*TW_B)          /* 110592 */
#define GEMM_SMEM (GSTAGE * 2)            /* 221184 */

template<bool DO_COS>
__global__ __launch_bounds__(512, 1) void hmma_gemm(
    const __nv_bfloat16* __restrict__ Ahi, const __nv_bfloat16* __restrict__ Alo,
    const __nv_bfloat16* __restrict__ WhiB, const __nv_bfloat16* __restrict__ WloB,
    const float* __restrict__ theta,
    float* __restrict__ C,
    __nv_bfloat16* __restrict__ OHB, __nv_bfloat16* __restrict__ OLB)
{
    extern __shared__ __align__(16) char smem[];
    uint32_t sb = smem_u32(smem);

    int z = blockIdx.z;
    const __nv_bfloat16* Whi = WhiB + (size_t)z * Ee * Ee;
    const __nv_bfloat16* Wlo = WloB + (size_t)z * Ee * Ee;

    int tid = threadIdx.x, wid = tid >> 5, lane = tid & 31;
    int wm = wid & 3, wn = wid >> 2;
    int g = lane >> 2, t = lane & 3;
    int lm = lane >> 3, li = lane & 7;
    int m0 = blockIdx.y * 256, n0 = blockIdx.x * 128;

    float acc[4][4][4] = {};

    auto issue = [&](int c, int bs) {
        uint32_t b0 = sb + bs * GSTAGE;
#pragma unroll
        for (int u = 0; u < 4; u++) {
            int unit = tid + u * 512;
            int row = unit >> 3, seg = unit & 7;
            size_t gA = (size_t)(m0 + row) * Ee + c * 64 + seg * 8;
            uint32_t so = (uint32_t)(row * PCH + seg * 8) * 2;
            cpa16(b0 + so,        Ahi + gA);
            cpa16(b0 + TA_B + so, Alo + gA);
        }
#pragma unroll
        for (int u = 0; u < 2; u++) {
            int unit = tid + u * 512;
            int row = unit >> 3, seg = unit & 7;
            size_t gW = (size_t)(n0 + row) * Ee + c * 64 + seg * 8;
            uint32_t so = (uint32_t)(row * PCH + seg * 8) * 2;
            cpa16(b0 + 2 * TA_B + so,        Whi + gW);
            cpa16(b0 + 2 * TA_B + TW_B + so, Wlo + gW);
        }
    };

    issue(0, 0); CPA_COMMIT();
    issue(1, 1); CPA_COMMIT();

    for (int c = 0; c < 16; c++) {
        if (c == 15) CPA_WAIT0(); else CPA_WAIT1();
        __syncthreads();

        uint32_t bufA = sb + (c & 1) * GSTAGE;
        uint32_t bufW = bufA + 2 * TA_B;

#pragma unroll
        for (int ks = 0; ks < 4; ks++) {
            uint32_t ah[4][4], al[4][4];
#pragma unroll
            for (int mf = 0; mf < 4; mf++) {
                uint32_t ad = bufA +
                    (uint32_t)(((wm * 64 + mf * 16 + (lm & 1) * 8 + li) * PCH)
                               + ks * 16 + (lm >> 1) * 8) * 2;
                ldsm_x4(ah[mf], ad);
                ldsm_x4(al[mf], ad + TA_B);
            }
#pragma unroll
            for (int nfp = 0; nfp < 2; nfp++) {
                uint32_t bd = bufW +
                    (uint32_t)(((wn * 32 + (nfp * 2 + (lm >> 1)) * 8 + li) * PCH)
                               + ks * 16 + (lm & 1) * 8) * 2;
                uint32_t bh[4], bl[4];
                ldsm_x4(bh, bd);
                ldsm_x4(bl, bd + TW_B);
#pragma unroll
                for (int mf = 0; mf < 4; mf++) {
                    mma16816(acc[mf][nfp*2],   ah[mf], bh);
                    mma16816(acc[mf][nfp*2+1], ah[mf], bh + 2);
                }
#pragma unroll
                for (int mf = 0; mf < 4; mf++) {
                    mma16816(acc[mf][nfp*2],   ah[mf], bl);
                    mma16816(acc[mf][nfp*2+1], ah[mf], bl + 2);
                }
#pragma unroll
                for (int mf = 0; mf < 4; mf++) {
                    mma16816(acc[mf][nfp*2],   al[mf], bh);
                    mma16816(acc[mf][nfp*2+1], al[mf], bh + 2);
                }
            }
        }
        __syncthreads();
        if (c < 14) { issue(c + 2, c & 1); CPA_COMMIT(); }
    }

    __nv_bfloat16* OH = DO_COS ? OHB + (size_t)z * Mm * Ee : nullptr;
    __nv_bfloat16* OL = DO_COS ? OLB + (size_t)z * Mm * Ee : nullptr;
#pragma unroll
    for (int mf = 0; mf < 4; mf++) {
#pragma unroll
        for (int nf = 0; nf < 4; nf++) {
            int r = m0 + wm * 64 + mf * 16 + g;
            int cb = n0 + wn * 32 + nf * 8 + 2 * t;
            float v0 = acc[mf][nf][0], v1 = acc[mf][nf][1];
            float v2 = acc[mf][nf][2], v3 = acc[mf][nf][3];
            if (DO_COS) {
                float t0 = theta[cb & 63], t1 = theta[(cb + 1) & 63];
                v0 = cosf(v0 + t0); v1 = cosf(v1 + t1);
                v2 = cosf(v2 + t0); v3 = cosf(v3 + t1);
                uint32_t h0 = pack_hi(v0, v1), h1 = pack_hi(v2, v3);
                *(uint32_t*)&OH[(size_t)r * Ee + cb]       = h0;
                *(uint32_t*)&OH[(size_t)(r + 8) * Ee + cb] = h1;
                *(uint32_t*)&OL[(size_t)r * Ee + cb]       = pack_lo(v0, v1, h0);
                *(uint32_t*)&OL[(size_t)(r + 8) * Ee + cb] = pack_lo(v2, v3, h1);
            } else {
                *(float2*)&C[(size_t)r * Ee + cb]       = float2{v0, v1};
                *(float2*)&C[(size_t)(r + 8) * Ee + cb] = float2{v2, v3};
            }
        }
    }
}

// ------------------------- HMMA flash attention -------------------------------
// 1-term QK / 1-term PV, KV tile = 64 keys, 2 CTAs/SM (regs<=128, smem 55KB).
#define PKV 72
#define KVB (64 * PKV * 2)               /* 9216 */
#define STAGEB (KVB * 2)                 /* 18432 */
#define ATT_SMEM (STAGEB * 3)            /* 55296 */

__global__ __launch_bounds__(256, 2) void attn_mma(
    const __nv_bfloat16* __restrict__ qhi,
    const __nv_bfloat16* __restrict__ khi,
    const __nv_bfloat16* __restrict__ vhi,
    __nv_bfloat16* __restrict__ chi, __nv_bfloat16* __restrict__ clo)
{
    extern __shared__ __align__(16) char smem[];
    uint32_t sb = smem_u32(smem);

    int tid = threadIdx.x, wid = tid >> 5, lane = tid & 31;
    int g = lane >> 2, t = lane & 3;
    int lm = lane >> 3, li = lane & 7;
    int bh_ = blockIdx.y;
    int b = bh_ >> 4, h = bh_ & 15;
    int q0 = blockIdx.x * 128;
    size_t base = (size_t)b * Ss * Ee + (size_t)h * Dk;

    uint32_t qh[4][4];
    {
        size_t r0 = base + (size_t)(q0 + wid * 16 + g) * Ee;
        size_t r1 = r0 + 8 * (size_t)Ee;
#pragma unroll
        for (int ks = 0; ks < 4; ks++) {
            int c0 = ks * 16 + 2 * t;
            qh[ks][0] = *(const uint32_t*)&qhi[r0 + c0];
            qh[ks][1] = *(const uint32_t*)&qhi[r1 + c0];
            qh[ks][2] = *(const uint32_t*)&qhi[r0 + c0 + 8];
            qh[ks][3] = *(const uint32_t*)&qhi[r1 + c0 + 8];
        }
    }

    auto issue = [&](int j0, int s) {
        uint32_t b0 = sb + s * STAGEB;
#pragma unroll
        for (int u = 0; u < 2; u++) {
            int unit = tid + u * 256;          // 0..511
            int row = unit >> 3, seg = unit & 7;
            size_t gk = base + (size_t)(j0 + row) * Ee + seg * 8;
            uint32_t so = (uint32_t)(row * PKV + seg * 8) * 2;
            cpa16(b0 + so,       khi + gk);
            cpa16(b0 + KVB + so, vhi + gk);
        }
    };

    float m0 = -1e30f, m1 = -1e30f, l0 = 0.0f, l1 = 0.0f;
    float out[8][4] = {};

    issue(0, 0);  CPA_COMMIT();
    issue(64, 1); CPA_COMMIT();

    for (int tile = 0; tile < 32; tile++) {
        if (tile == 31) CPA_WAIT0(); else CPA_WAIT1();
        __syncthreads();
        if (tile < 30) { issue((tile + 2) * 64, (tile + 2) % 3); CPA_COMMIT(); }

        uint32_t kb = sb + (tile % 3) * STAGEB;
        uint32_t vb = kb + KVB;

        // QK^T (1-term) -> s[8][4] over 64 keys
        float s[8][4] = {};
#pragma unroll
        for (int ks = 0; ks < 4; ks++) {
#pragma unroll
            for (int nfp = 0; nfp < 4; nfp++) {
                uint32_t ad = kb +
                    (uint32_t)(((nfp * 2 + (lm >> 1)) * 8 + li) * PKV
                               + ks * 16 + (lm & 1) * 8) * 2;
                uint32_t bhv[4];
                ldsm_x4(bhv, ad);
                mma16816(s[nfp*2],   qh[ks], bhv);
                mma16816(s[nfp*2+1], qh[ks], bhv + 2);
            }
        }

        float mx0 = -1e30f, mx1 = -1e30f;
#pragma unroll
        for (int nf = 0; nf < 8; nf++) {
            mx0 = fmaxf(mx0, fmaxf(s[nf][0], s[nf][1]));
            mx1 = fmaxf(mx1, fmaxf(s[nf][2], s[nf][3]));
        }
        mx0 = fmaxf(mx0, __shfl_xor_sync(0xffffffffu, mx0, 1));
        mx0 = fmaxf(mx0, __shfl_xor_sync(0xffffffffu, mx0, 2));
        mx1 = fmaxf(mx1, __shfl_xor_sync(0xffffffffu, mx1, 1));
        mx1 = fmaxf(mx1, __shfl_xor_sync(0xffffffffu, mx1, 2));
        float mn0 = fmaxf(m0, mx0), mn1 = fmaxf(m1, mx1);
        float sc0 = __expf(0.125f * (m0 - mn0));
        float sc1 = __expf(0.125f * (m1 - mn1));
#pragma unroll
        for (int nf = 0; nf < 8; nf++) {
            s[nf][0] = __expf(0.125f * (s[nf][0] - mn0));
            s[nf][1] = __expf(0.125f * (s[nf][1] - mn0));
            s[nf][2] = __expf(0.125f * (s[nf][2] - mn1));
            s[nf][3] = __expf(0.125f * (s[nf][3] - mn1));
        }

        // pack P to bf16; normalizer from ROUNDED p values
        uint32_t pa[4][4];
        float sum0 = 0.0f, sum1 = 0.0f;
#pragma unroll
        for (int k2 = 0; k2 < 4; k2++) {
            pa[k2][0] = pack_hi(s[2*k2][0],   s[2*k2][1]);
            pa[k2][1] = pack_hi(s[2*k2][2],   s[2*k2][3]);
            pa[k2][2] = pack_hi(s[2*k2+1][0], s[2*k2+1][1]);
            pa[k2][3] = pack_hi(s[2*k2+1][2], s[2*k2+1][3]);
            sum0 += unp_lo(pa[k2][0]) + unp_hi(pa[k2][0])
                  + unp_lo(pa[k2][2]) + unp_hi(pa[k2][2]);
            sum1 += unp_lo(pa[k2][1]) + unp_hi(pa[k2][1])
                  + unp_lo(pa[k2][3]) + unp_hi(pa[k2][3]);
        }
        sum0 += __shfl_xor_sync(0xffffffffu, sum0, 1);
        sum0 += __shfl_xor_sync(0xffffffffu, sum0, 2);
        sum1 += __shfl_xor_sync(0xffffffffu, sum1, 1);
        sum1 += __shfl_xor_sync(0xffffffffu, sum1, 2);
        l0 = l0 * sc0 + sum0;
        l1 = l1 * sc1 + sum1;
        m0 = mn0; m1 = mn1;
#pragma unroll
        for (int nfo = 0; nfo < 8; nfo++) {
            out[nfo][0] *= sc0; out[nfo][1] *= sc0;
            out[nfo][2] *= sc1; out[nfo][3] *= sc1;
        }

        // PV (1-term), B via ldmatrix.trans; 64 keys = 4 k-steps
#pragma unroll
        for (int ks2 = 0; ks2 < 4; ks2++) {
#pragma unroll
            for (int nfp = 0; nfp < 4; nfp++) {
                uint32_t ad = vb +
                    (uint32_t)((ks2 * 16 + (lm & 1) * 8 + li) * PKV
                               + (nfp * 2 + (lm >> 1)) * 8) * 2;
                uint32_t bvh[4];
                ldsm_x4_t(bvh, ad);
                mma16816(out[nfp*2],   pa[ks2], bvh);
                mma16816(out[nfp*2+1], pa[ks2], bvh + 2);
            }
        }
    }

    float inv0 = 1.0f / l0, inv1 = 1.0f / l1;
    size_t r0 = base + (size_t)(q0 + wid * 16 + g) * Ee;
    size_t r1 = r0 + 8 * (size_t)Ee;
#pragma unroll
    for (int nfo = 0; nfo < 8; nfo++) {
        int d = nfo * 8 + 2 * t;
        float v0 = out[nfo][0] * inv0, v1 = out[nfo][1] * inv0;
        float v2 = out[nfo][2] * inv1, v3 = out[nfo][3] * inv1;
        uint32_t h0 = pack_hi(v0, v1), h1 = pack_hi(v2, v3);
        *(uint32_t*)&chi[r0 + d] = h0;
        *(uint32_t*)&chi[r1 + d] = h1;
        *(uint32_t*)&clo[r0 + d] = pack_lo(v0, v1, h0);
        *(uint32_t*)&clo[r1 + d] = pack_lo(v2, v3, h1);
    }
}

// ---------------------------------------------------------------------------
extern "C" void kernel_launch(void* const* d_in, const int* in_sizes, int n_in,
                              void* d_out, int out_size)
{
    const float* x     = (const float*)d_in[0];
    const float* Wq    = (const float*)d_in[1];
    const float* Wk    = (const float*)d_in[2];
    const float* Wv    = (const float*)d_in[3];
    const float* Wo    = (const float*)d_in[4];
    const float* theta = (const float*)d_in[5];
    float* out = (float*)d_out;

    __nv_bfloat16 *xhi, *xlo, *qkvhi, *qkvlo, *chi, *clo, *whi, *wlo;
    cudaGetSymbolAddress((void**)&xhi, g_xhi);
    cudaGetSymbolAddress((void**)&xlo, g_xlo);
    cudaGetSymbolAddress((void**)&qkvhi, g_qkvhi);
    cudaGetSymbolAddress((void**)&qkvlo, g_qkvlo);
    cudaGetSymbolAddress((void**)&chi, g_chi);
    cudaGetSymbolAddress((void**)&clo, g_clo);
    cudaGetSymbolAddress((void**)&whi, g_whi);
    cudaGetSymbolAddress((void**)&wlo, g_wlo);

    cudaFuncSetAttribute(hmma_gemm<true>,
        cudaFuncAttributeMaxDynamicSharedMemorySize, GEMM_SMEM);
    cudaFuncSetAttribute(hmma_gemm<false>,
        cudaFuncAttributeMaxDynamicSharedMemorySize, GEMM_SMEM);
    cudaFuncSetAttribute(attn_mma,
        cudaFuncAttributeMaxDynamicSharedMemorySize, ATT_SMEM);

    int n4x = Mm * Ee / 4;
    int n4w = Ee * Ee / 4;
    split_kernel<<<(n4x + 255) / 256, 256>>>((const float4*)x, xhi, xlo, n4x);
    dim3 gw((n4w + 255) / 256, 4);
    split4_kernel<<<gw, 256>>>((const float4*)Wq, (const float4*)Wk,
                               (const float4*)Wv, (const float4*)Wo,
                               whi, wlo, n4w);

    dim3 g1(Ee / 128, Mm / 256, 3);
    hmma_gemm<true><<<g1, 512, GEMM_SMEM>>>(xhi, xlo, whi, wlo, theta,
                                            nullptr, qkvhi, qkvlo);

    size_t off = (size_t)Mm * Ee;
    dim3 g2(Ss / 128, Bb * Hh);
    attn_mma<<<g2, 256, ATT_SMEM>>>(qkvhi,
                                    qkvhi + off,
                                    qkvhi + 2*off,
                                    chi, clo);

    dim3 g3(Ee / 128, Mm / 256, 1);
    hmma_gemm<false><<<g3, 512, GEMM_SMEM>>>(chi, clo,
        whi + 3*(size_t)Ee*Ee, wlo + 3*(size_t)Ee*Ee, nullptr, out,
        nullptr, nullptr);
}

// round 11
// speedup vs baseline: 1.5797x; 1.0195x over previous
#include <cuda_runtime.h>
#include <cuda_bf16.h>
#include <math.h>
#include <stdint.h>

#define Bb 4
#define Ss 2048
#define Ee 1024
#define Hh 16
#define Dk 64
#define Mm (Bb*Ss)   /* 8192 */

#define QSCALE 0.1803368801111204f   /* 0.125 * log2(e) */

// ------------------------- device scratch (no allocs) ----------------------
__device__ __nv_bfloat16 g_xhi[Mm*Ee];
__device__ __nv_bfloat16 g_xlo[Mm*Ee];
__device__ __nv_bfloat16 g_qkvhi[3*Mm*Ee];   // q(scaled) | k | v
__device__ __nv_bfloat16 g_qkvlo[3*Mm*Ee];
__device__ __nv_bfloat16 g_chi[Mm*Ee];
__device__ __nv_bfloat16 g_clo[Mm*Ee];
__device__ __nv_bfloat16 g_whi[4*Ee*Ee];
__device__ __nv_bfloat16 g_wlo[4*Ee*Ee];

// ------------------------- helpers ------------------------------------------
__device__ __forceinline__ void mma16816(float* d, const uint32_t* a,
                                         const uint32_t* b)
{
    asm volatile(
        "mma.sync.aligned.m16n8k16.row.col.f32.bf16.bf16.f32 "
        "{%0,%1,%2,%3}, {%4,%5,%6,%7}, {%8,%9}, {%0,%1,%2,%3};"
        : "+f"(d[0]), "+f"(d[1]), "+f"(d[2]), "+f"(d[3])
        : "r"(a[0]), "r"(a[1]), "r"(a[2]), "r"(a[3]), "r"(b[0]), "r"(b[1]));
}
__device__ __forceinline__ void ldsm_x4(uint32_t* r, uint32_t addr) {
    asm volatile("ldmatrix.sync.aligned.m8n8.x4.shared.b16 {%0,%1,%2,%3}, [%4];"
        : "=r"(r[0]), "=r"(r[1]), "=r"(r[2]), "=r"(r[3]) : "r"(addr));
}
__device__ __forceinline__ void ldsm_x4_t(uint32_t* r, uint32_t addr) {
    asm volatile("ldmatrix.sync.aligned.m8n8.x4.trans.shared.b16 {%0,%1,%2,%3}, [%4];"
        : "=r"(r[0]), "=r"(r[1]), "=r"(r[2]), "=r"(r[3]) : "r"(addr));
}
__device__ __forceinline__ uint32_t smem_u32(const void* p) {
    uint32_t a;
    asm("{ .reg .u64 t; cvta.to.shared.u64 t, %1; cvt.u32.u64 %0, t; }"
        : "=r"(a) : "l"(p));
    return a;
}
__device__ __forceinline__ void cpa16(uint32_t s, const void* g) {
    asm volatile("cp.async.cg.shared.global [%0], [%1], 16;" :: "r"(s), "l"(g));
}
#define CPA_COMMIT() asm volatile("cp.async.commit_group;" ::: "memory")
#define CPA_WAIT1()  asm volatile("cp.async.wait_group 1;" ::: "memory")
#define CPA_WAIT0()  asm volatile("cp.async.wait_group 0;" ::: "memory")

__device__ __forceinline__ float ex2(float x) {
    float r;
    asm("ex2.approx.f32 %0, %1;" : "=f"(r) : "f"(x));
    return r;
}
__device__ __forceinline__ uint32_t pack_hi(float x, float y) {
    __nv_bfloat162 h = __floats2bfloat162_rn(x, y);
    return *(uint32_t*)&h;
}
__device__ __forceinline__ uint32_t pack_lo(float x, float y, uint32_t hiu) {
    __nv_bfloat162 h = *(__nv_bfloat162*)&hiu;
    __nv_bfloat162 l = __floats2bfloat162_rn(x - __bfloat162float(h.x),
                                             y - __bfloat162float(h.y));
    return *(uint32_t*)&l;
}

// ------------------------- fp32 -> bf16 hi/lo splits -------------------------
__global__ __launch_bounds__(256) void split_kernel(const float4* __restrict__ src,
                                                    __nv_bfloat16* __restrict__ hi,
                                                    __nv_bfloat16* __restrict__ lo,
                                                    int n4)
{
    int i = blockIdx.x * 256 + threadIdx.x;
    if (i >= n4) return;
    float4 v = src[i];
    uint32_t h0 = pack_hi(v.x, v.y), h1 = pack_hi(v.z, v.w);
    uint32_t l0 = pack_lo(v.x, v.y, h0), l1 = pack_lo(v.z, v.w, h1);
    uint32_t* hp = (uint32_t*)(hi + (size_t)i * 4);
    uint32_t* lp = (uint32_t*)(lo + (size_t)i * 4);
    hp[0] = h0; hp[1] = h1; lp[0] = l0; lp[1] = l1;
}

__global__ __launch_bounds__(256) void split4_kernel(
    const float4* __restrict__ s0, const float4* __restrict__ s1,
    const float4* __restrict__ s2, const float4* __restrict__ s3,
    __nv_bfloat16* __restrict__ hi, __nv_bfloat16* __restrict__ lo, int n4)
{
    int z = blockIdx.y;
    const float4* src = (z == 0) ? s0 : (z == 1) ? s1 : (z == 2) ? s2 : s3;
    int i = blockIdx.x * 256 + threadIdx.x;
    if (i >= n4) return;
    float4 v = src[i];
    uint32_t h0 = pack_hi(v.x, v.y), h1 = pack_hi(v.z, v.w);
    uint32_t l0 = pack_lo(v.x, v.y, h0), l1 = pack_lo(v.z, v.w, h1);
    size_t off = (size_t)z * Ee * Ee + (size_t)i * 4;
    uint32_t* hp = (uint32_t*)(hi + off);
    uint32_t* lp = (uint32_t*)(lo + off);
    hp[0] = h0; hp[1] = h1; lp[0] = l0; lp[1] = l1;
}

// ------------------------- HMMA split-bf16 GEMM (3-term) ---------------------
#define PCH 72
#define TA_B (256 * PCH * 2)              /* 36864 */
#define TW_B (128 * PCH * 2)              /* 18432 */
#define GSTAGE (2*TA_B + 2*TW_B)          /* 110592 */
#define GEMM_SMEM (GSTAGE * 2)            /* 221184 */

template<bool DO_COS>
__global__ __launch_bounds__(512, 1) void hmma_gemm(
    const __nv_bfloat16* __restrict__ Ahi, const __nv_bfloat16* __restrict__ Alo,
    const __nv_bfloat16* __restrict__ WhiB, const __nv_bfloat16* __restrict__ WloB,
    const float* __restrict__ theta,
    float* __restrict__ C,
    __nv_bfloat16* __restrict__ OHB, __nv_bfloat16* __restrict__ OLB)
{
    extern __shared__ __align__(16) char smem[];
    uint32_t sb = smem_u32(smem);

    int z = blockIdx.z;
    const __nv_bfloat16* Whi = WhiB + (size_t)z * Ee * Ee;
    const __nv_bfloat16* Wlo = WloB + (size_t)z * Ee * Ee;

    int tid = threadIdx.x, wid = tid >> 5, lane = tid & 31;
    int wm = wid & 3, wn = wid >> 2;
    int g = lane >> 2, t = lane & 3;
    int lm = lane >> 3, li = lane & 7;
    int m0 = blockIdx.y * 256, n0 = blockIdx.x * 128;

    float acc[4][4][4] = {};

    auto issue = [&](int c, int bs) {
        uint32_t b0 = sb + bs * GSTAGE;
#pragma unroll
        for (int u = 0; u < 4; u++) {
            int unit = tid + u * 512;
            int row = unit >> 3, seg = unit & 7;
            size_t gA = (size_t)(m0 + row) * Ee + c * 64 + seg * 8;
            uint32_t so = (uint32_t)(row * PCH + seg * 8) * 2;
            cpa16(b0 + so,        Ahi + gA);
            cpa16(b0 + TA_B + so, Alo + gA);
        }
#pragma unroll
        for (int u = 0; u < 2; u++) {
            int unit = tid + u * 512;
            int row = unit >> 3, seg = unit & 7;
            size_t gW = (size_t)(n0 + row) * Ee + c * 64 + seg * 8;
            uint32_t so = (uint32_t)(row * PCH + seg * 8) * 2;
            cpa16(b0 + 2 * TA_B + so,        Whi + gW);
            cpa16(b0 + 2 * TA_B + TW_B + so, Wlo + gW);
        }
    };

    issue(0, 0); CPA_COMMIT();
    issue(1, 1); CPA_COMMIT();

    for (int c = 0; c < 16; c++) {
        if (c == 15) CPA_WAIT0(); else CPA_WAIT1();
        __syncthreads();

        uint32_t bufA = sb + (c & 1) * GSTAGE;
        uint32_t bufW = bufA + 2 * TA_B;

#pragma unroll
        for (int ks = 0; ks < 4; ks++) {
            uint32_t ah[4][4], al[4][4];
#pragma unroll
            for (int mf = 0; mf < 4; mf++) {
                uint32_t ad = bufA +
                    (uint32_t)(((wm * 64 + mf * 16 + (lm & 1) * 8 + li) * PCH)
                               + ks * 16 + (lm >> 1) * 8) * 2;
                ldsm_x4(ah[mf], ad);
                ldsm_x4(al[mf], ad + TA_B);
            }
#pragma unroll
            for (int nfp = 0; nfp < 2; nfp++) {
                uint32_t bd = bufW +
                    (uint32_t)(((wn * 32 + (nfp * 2 + (lm >> 1)) * 8 + li) * PCH)
                               + ks * 16 + (lm & 1) * 8) * 2;
                uint32_t bh[4], bl[4];
                ldsm_x4(bh, bd);
                ldsm_x4(bl, bd + TW_B);
#pragma unroll
                for (int mf = 0; mf < 4; mf++) {
                    mma16816(acc[mf][nfp*2],   ah[mf], bh);
                    mma16816(acc[mf][nfp*2+1], ah[mf], bh + 2);
                }
#pragma unroll
                for (int mf = 0; mf < 4; mf++) {
                    mma16816(acc[mf][nfp*2],   ah[mf], bl);
                    mma16816(acc[mf][nfp*2+1], ah[mf], bl + 2);
                }
#pragma unroll
                for (int mf = 0; mf < 4; mf++) {
                    mma16816(acc[mf][nfp*2],   al[mf], bh);
                    mma16816(acc[mf][nfp*2+1], al[mf], bh + 2);
                }
            }
        }
        __syncthreads();
        if (c < 14) { issue(c + 2, c & 1); CPA_COMMIT(); }
    }

    __nv_bfloat16* OH = DO_COS ? OHB + (size_t)z * Mm * Ee : nullptr;
    __nv_bfloat16* OL = DO_COS ? OLB + (size_t)z * Mm * Ee : nullptr;
    float osc = (DO_COS && z == 0) ? QSCALE : 1.0f;   // pre-scale Q for softmax
#pragma unroll
    for (int mf = 0; mf < 4; mf++) {
#pragma unroll
        for (int nf = 0; nf < 4; nf++) {
            int r = m0 + wm * 64 + mf * 16 + g;
            int cb = n0 + wn * 32 + nf * 8 + 2 * t;
            float v0 = acc[mf][nf][0], v1 = acc[mf][nf][1];
            float v2 = acc[mf][nf][2], v3 = acc[mf][nf][3];
            if (DO_COS) {
                float t0 = theta[cb & 63], t1 = theta[(cb + 1) & 63];
                v0 = __cosf(v0 + t0) * osc; v1 = __cosf(v1 + t1) * osc;
                v2 = __cosf(v2 + t0) * osc; v3 = __cosf(v3 + t1) * osc;
                uint32_t h0 = pack_hi(v0, v1), h1 = pack_hi(v2, v3);
                *(uint32_t*)&OH[(size_t)r * Ee + cb]       = h0;
                *(uint32_t*)&OH[(size_t)(r + 8) * Ee + cb] = h1;
                *(uint32_t*)&OL[(size_t)r * Ee + cb]       = pack_lo(v0, v1, h0);
                *(uint32_t*)&OL[(size_t)(r + 8) * Ee + cb] = pack_lo(v2, v3, h1);
            } else {
                *(float2*)&C[(size_t)r * Ee + cb]       = float2{v0, v1};
                *(float2*)&C[(size_t)(r + 8) * Ee + cb] = float2{v2, v3};
            }
        }
    }
}

// ------------------------- HMMA flash attention -------------------------------
// 1-term QK / 1-term PV; q pre-scaled by 0.125*log2e so exp = EX2(s - m).
// KV tile 64 keys, 2 CTAs/SM.
#define PKV 72
#define KVB (64 * PKV * 2)               /* 9216 */
#define STAGEB (KVB * 2)                 /* 18432 */
#define ATT_SMEM (STAGEB * 3)            /* 55296 */

__global__ __launch_bounds__(256, 2) void attn_mma(
    const __nv_bfloat16* __restrict__ qhi,
    const __nv_bfloat16* __restrict__ khi,
    const __nv_bfloat16* __restrict__ vhi,
    __nv_bfloat16* __restrict__ chi, __nv_bfloat16* __restrict__ clo)
{
    extern __shared__ __align__(16) char smem[];
    uint32_t sb = smem_u32(smem);

    int tid = threadIdx.x, wid = tid >> 5, lane = tid & 31;
    int g = lane >> 2, t = lane & 3;
    int lm = lane >> 3, li = lane & 7;
    int bh_ = blockIdx.y;
    int b = bh_ >> 4, h = bh_ & 15;
    int q0 = blockIdx.x * 128;
    size_t base = (size_t)b * Ss * Ee + (size_t)h * Dk;

    uint32_t qh[4][4];
    {
        size_t r0 = base + (size_t)(q0 + wid * 16 + g) * Ee;
        size_t r1 = r0 + 8 * (size_t)Ee;
#pragma unroll
        for (int ks = 0; ks < 4; ks++) {
            int c0 = ks * 16 + 2 * t;
            qh[ks][0] = *(const uint32_t*)&qhi[r0 + c0];
            qh[ks][1] = *(const uint32_t*)&qhi[r1 + c0];
            qh[ks][2] = *(const uint32_t*)&qhi[r0 + c0 + 8];
            qh[ks][3] = *(const uint32_t*)&qhi[r1 + c0 + 8];
        }
    }

    auto issue = [&](int j0, int s) {
        uint32_t b0 = sb + s * STAGEB;
#pragma unroll
        for (int u = 0; u < 2; u++) {
            int unit = tid + u * 256;
            int row = unit >> 3, seg = unit & 7;
            size_t gk = base + (size_t)(j0 + row) * Ee + seg * 8;
            uint32_t so = (uint32_t)(row * PKV + seg * 8) * 2;
            cpa16(b0 + so,       khi + gk);
            cpa16(b0 + KVB + so, vhi + gk);
        }
    };

    float m0 = -1e30f, m1 = -1e30f, l0 = 0.0f, l1 = 0.0f;
    float out[8][4] = {};

    issue(0, 0);  CPA_COMMIT();
    issue(64, 1); CPA_COMMIT();

    for (int tile = 0; tile < 32; tile++) {
        if (tile == 31) CPA_WAIT0(); else CPA_WAIT1();
        __syncthreads();
        if (tile < 30) { issue((tile + 2) * 64, (tile + 2) % 3); CPA_COMMIT(); }

        uint32_t kb = sb + (tile % 3) * STAGEB;
        uint32_t vb = kb + KVB;

        // QK^T (1-term, q pre-scaled) -> s[8][4]
        float s[8][4] = {};
#pragma unroll
        for (int ks = 0; ks < 4; ks++) {
#pragma unroll
            for (int nfp = 0; nfp < 4; nfp++) {
                uint32_t ad = kb +
                    (uint32_t)(((nfp * 2 + (lm >> 1)) * 8 + li) * PKV
                               + ks * 16 + (lm & 1) * 8) * 2;
                uint32_t bhv[4];
                ldsm_x4(bhv, ad);
                mma16816(s[nfp*2],   qh[ks], bhv);
                mma16816(s[nfp*2+1], qh[ks], bhv + 2);
            }
        }

        float mx0 = -1e30f, mx1 = -1e30f;
#pragma unroll
        for (int nf = 0; nf < 8; nf++) {
            mx0 = fmaxf(mx0, fmaxf(s[nf][0], s[nf][1]));
            mx1 = fmaxf(mx1, fmaxf(s[nf][2], s[nf][3]));
        }
        mx0 = fmaxf(mx0, __shfl_xor_sync(0xffffffffu, mx0, 1));
        mx0 = fmaxf(mx0, __shfl_xor_sync(0xffffffffu, mx0, 2));
        mx1 = fmaxf(mx1, __shfl_xor_sync(0xffffffffu, mx1, 1));
        mx1 = fmaxf(mx1, __shfl_xor_sync(0xffffffffu, mx1, 2));
        float mn0 = fmaxf(m0, mx0), mn1 = fmaxf(m1, mx1);

        // exp2 of scaled logits; sums accumulated from pre-pack values
        float sum0 = 0.0f, sum1 = 0.0f;
#pragma unroll
        for (int nf = 0; nf < 8; nf++) {
            s[nf][0] = ex2(s[nf][0] - mn0);
            s[nf][1] = ex2(s[nf][1] - mn0);
            s[nf][2] = ex2(s[nf][2] - mn1);
            s[nf][3] = ex2(s[nf][3] - mn1);
            sum0 += s[nf][0] + s[nf][1];
            sum1 += s[nf][2] + s[nf][3];
        }
        sum0 += __shfl_xor_sync(0xffffffffu, sum0, 1);
        sum0 += __shfl_xor_sync(0xffffffffu, sum0, 2);
        sum1 += __shfl_xor_sync(0xffffffffu, sum1, 1);
        sum1 += __shfl_xor_sync(0xffffffffu, sum1, 2);

        // rescale accumulators only if any lane's max moved
        bool upd = __any_sync(0xffffffffu, (mn0 != m0) | (mn1 != m1));
        if (upd) {
            float sc0 = ex2(m0 - mn0);
            float sc1 = ex2(m1 - mn1);
            l0 = l0 * sc0 + sum0;
            l1 = l1 * sc1 + sum1;
#pragma unroll
            for (int nfo = 0; nfo < 8; nfo++) {
                out[nfo][0] *= sc0; out[nfo][1] *= sc0;
                out[nfo][2] *= sc1; out[nfo][3] *= sc1;
            }
            m0 = mn0; m1 = mn1;
        } else {
            l0 += sum0;
            l1 += sum1;
        }

        // pack P to bf16
        uint32_t pa[4][4];
#pragma unroll
        for (int k2 = 0; k2 < 4; k2++) {
            pa[k2][0] = pack_hi(s[2*k2][0],   s[2*k2][1]);
            pa[k2][1] = pack_hi(s[2*k2][2],   s[2*k2][3]);
            pa[k2][2] = pack_hi(s[2*k2+1][0], s[2*k2+1][1]);
            pa[k2][3] = pack_hi(s[2*k2+1][2], s[2*k2+1][3]);
        }

        // PV (1-term), B via ldmatrix.trans
#pragma unroll
        for (int ks2 = 0; ks2 < 4; ks2++) {
#pragma unroll
            for (int nfp = 0; nfp < 4; nfp++) {
                uint32_t ad = vb +
                    (uint32_t)((ks2 * 16 + (lm & 1) * 8 + li) * PKV
                               + (nfp * 2 + (lm >> 1)) * 8) * 2;
                uint32_t bvh[4];
                ldsm_x4_t(bvh, ad);
                mma16816(out[nfp*2],   pa[ks2], bvh);
                mma16816(out[nfp*2+1], pa[ks2], bvh + 2);
            }
        }
    }

    float inv0 = 1.0f / l0, inv1 = 1.0f / l1;
    size_t r0 = base + (size_t)(q0 + wid * 16 + g) * Ee;
    size_t r1 = r0 + 8 * (size_t)Ee;
#pragma unroll
    for (int nfo = 0; nfo < 8; nfo++) {
        int d = nfo * 8 + 2 * t;
        float v0 = out[nfo][0] * inv0, v1 = out[nfo][1] * inv0;
        float v2 = out[nfo][2] * inv1, v3 = out[nfo][3] * inv1;
        uint32_t h0 = pack_hi(v0, v1), h1 = pack_hi(v2, v3);
        *(uint32_t*)&chi[r0 + d] = h0;
        *(uint32_t*)&chi[r1 + d] = h1;
        *(uint32_t*)&clo[r0 + d] = pack_lo(v0, v1, h0);
        *(uint32_t*)&clo[r1 + d] = pack_lo(v2, v3, h1);
    }
}

// ---------------------------------------------------------------------------
extern "C" void kernel_launch(void* const* d_in, const int* in_sizes, int n_in,
                              void* d_out, int out_size)
{
    const float* x     = (const float*)d_in[0];
    const float* Wq    = (const float*)d_in[1];
    const float* Wk    = (const float*)d_in[2];
    const float* Wv    = (const float*)d_in[3];
    const float* Wo    = (const float*)d_in[4];
    const float* theta = (const float*)d_in[5];
    float* out = (float*)d_out;

    __nv_bfloat16 *xhi, *xlo, *qkvhi, *qkvlo, *chi, *clo, *whi, *wlo;
    cudaGetSymbolAddress((void**)&xhi, g_xhi);
    cudaGetSymbolAddress((void**)&xlo, g_xlo);
    cudaGetSymbolAddress((void**)&qkvhi, g_qkvhi);
    cudaGetSymbolAddress((void**)&qkvlo, g_qkvlo);
    cudaGetSymbolAddress((void**)&chi, g_chi);
    cudaGetSymbolAddress((void**)&clo, g_clo);
    cudaGetSymbolAddress((void**)&whi, g_whi);
    cudaGetSymbolAddress((void**)&wlo, g_wlo);

    cudaFuncSetAttribute(hmma_gemm<true>,
        cudaFuncAttributeMaxDynamicSharedMemorySize, GEMM_SMEM);
    cudaFuncSetAttribute(hmma_gemm<false>,
        cudaFuncAttributeMaxDynamicSharedMemorySize, GEMM_SMEM);
    cudaFuncSetAttribute(attn_mma,
        cudaFuncAttributeMaxDynamicSharedMemorySize, ATT_SMEM);

    int n4x = Mm * Ee / 4;
    int n4w = Ee * Ee / 4;
    split_kernel<<<(n4x + 255) / 256, 256>>>((const float4*)x, xhi, xlo, n4x);
    dim3 gw((n4w + 255) / 256, 4);
    split4_kernel<<<gw, 256>>>((const float4*)Wq, (const float4*)Wk,
                               (const float4*)Wv, (const float4*)Wo,
                               whi, wlo, n4w);

    dim3 g1(Ee / 128, Mm / 256, 3);
    hmma_gemm<true><<<g1, 512, GEMM_SMEM>>>(xhi, xlo, whi, wlo, theta,
                                            nullptr, qkvhi, qkvlo);

    size_t off = (size_t)Mm * Ee;
    dim3 g2(Ss / 128, Bb * Hh);
    attn_mma<<<g2, 256, ATT_SMEM>>>(qkvhi,
                                    qkvhi + off,
                                    qkvhi + 2*off,
                                    chi, clo);

    dim3 g3(Ee / 128, Mm / 256, 1);
    hmma_gemm<false><<<g3, 512, GEMM_SMEM>>>(chi, clo,
        whi + 3*(size_t)Ee*Ee, wlo + 3*(size_t)Ee*Ee, nullptr, out,
        nullptr, nullptr);
}

// round 12
// speedup vs baseline: 1.6126x; 1.0209x over previous
#include <cuda_runtime.h>
#include <cuda_bf16.h>
#include <math.h>
#include <stdint.h>

#define Bb 4
#define Ss 2048
#define Ee 1024
#define Hh 16
#define Dk 64
#define Mm (Bb*Ss)   /* 8192 */

#define QSCALE 0.1803368801111204f   /* 0.125 * log2(e) */

// ------------------------- device scratch (no allocs) ----------------------
__device__ __nv_bfloat16 g_xhi[Mm*Ee];
__device__ __nv_bfloat16 g_xlo[Mm*Ee];
__device__ __nv_bfloat16 g_qkvhi[3*Mm*Ee];   // q(scaled) | k | v
__device__ __nv_bfloat16 g_qkvlo[3*Mm*Ee];
__device__ __nv_bfloat16 g_chi[Mm*Ee];
__device__ __nv_bfloat16 g_clo[Mm*Ee];
__device__ __nv_bfloat16 g_whi[4*Ee*Ee];
__device__ __nv_bfloat16 g_wlo[4*Ee*Ee];

// ------------------------- helpers ------------------------------------------
__device__ __forceinline__ void mma16816(float* d, const uint32_t* a,
                                         const uint32_t* b)
{
    asm volatile(
        "mma.sync.aligned.m16n8k16.row.col.f32.bf16.bf16.f32 "
        "{%0,%1,%2,%3}, {%4,%5,%6,%7}, {%8,%9}, {%0,%1,%2,%3};"
        : "+f"(d[0]), "+f"(d[1]), "+f"(d[2]), "+f"(d[3])
        : "r"(a[0]), "r"(a[1]), "r"(a[2]), "r"(a[3]), "r"(b[0]), "r"(b[1]));
}
__device__ __forceinline__ void ldsm_x4(uint32_t* r, uint32_t addr) {
    asm volatile("ldmatrix.sync.aligned.m8n8.x4.shared.b16 {%0,%1,%2,%3}, [%4];"
        : "=r"(r[0]), "=r"(r[1]), "=r"(r[2]), "=r"(r[3]) : "r"(addr));
}
__device__ __forceinline__ void ldsm_x4_t(uint32_t* r, uint32_t addr) {
    asm volatile("ldmatrix.sync.aligned.m8n8.x4.trans.shared.b16 {%0,%1,%2,%3}, [%4];"
        : "=r"(r[0]), "=r"(r[1]), "=r"(r[2]), "=r"(r[3]) : "r"(addr));
}
__device__ __forceinline__ uint32_t smem_u32(const void* p) {
    uint32_t a;
    asm("{ .reg .u64 t; cvta.to.shared.u64 t, %1; cvt.u32.u64 %0, t; }"
        : "=r"(a) : "l"(p));
    return a;
}
__device__ __forceinline__ void cpa16(uint32_t s, const void* g) {
    asm volatile("cp.async.cg.shared.global [%0], [%1], 16;" :: "r"(s), "l"(g));
}
#define CPA_COMMIT() asm volatile("cp.async.commit_group;" ::: "memory")
#define CPA_WAIT1()  asm volatile("cp.async.wait_group 1;" ::: "memory")
#define CPA_WAIT0()  asm volatile("cp.async.wait_group 0;" ::: "memory")

__device__ __forceinline__ float ex2(float x) {
    float r;
    asm("ex2.approx.f32 %0, %1;" : "=f"(r) : "f"(x));
    return r;
}
__device__ __forceinline__ uint32_t pack_hi(float x, float y) {
    __nv_bfloat162 h = __floats2bfloat162_rn(x, y);
    return *(uint32_t*)&h;
}
__device__ __forceinline__ uint32_t pack_lo(float x, float y, uint32_t hiu) {
    __nv_bfloat162 h = *(__nv_bfloat162*)&hiu;
    __nv_bfloat162 l = __floats2bfloat162_rn(x - __bfloat162float(h.x),
                                             y - __bfloat162float(h.y));
    return *(uint32_t*)&l;
}

// ------------------------- fp32 -> bf16 hi/lo splits -------------------------
__global__ __launch_bounds__(256) void split_kernel(const float4* __restrict__ src,
                                                    __nv_bfloat16* __restrict__ hi,
                                                    __nv_bfloat16* __restrict__ lo,
                                                    int n4)
{
    int i = blockIdx.x * 256 + threadIdx.x;
    if (i >= n4) return;
    float4 v = src[i];
    uint32_t h0 = pack_hi(v.x, v.y), h1 = pack_hi(v.z, v.w);
    uint32_t l0 = pack_lo(v.x, v.y, h0), l1 = pack_lo(v.z, v.w, h1);
    uint32_t* hp = (uint32_t*)(hi + (size_t)i * 4);
    uint32_t* lp = (uint32_t*)(lo + (size_t)i * 4);
    hp[0] = h0; hp[1] = h1; lp[0] = l0; lp[1] = l1;
}

__global__ __launch_bounds__(256) void split4_kernel(
    const float4* __restrict__ s0, const float4* __restrict__ s1,
    const float4* __restrict__ s2, const float4* __restrict__ s3,
    __nv_bfloat16* __restrict__ hi, __nv_bfloat16* __restrict__ lo, int n4)
{
    int z = blockIdx.y;
    const float4* src = (z == 0) ? s0 : (z == 1) ? s1 : (z == 2) ? s2 : s3;
    int i = blockIdx.x * 256 + threadIdx.x;
    if (i >= n4) return;
    float4 v = src[i];
    uint32_t h0 = pack_hi(v.x, v.y), h1 = pack_hi(v.z, v.w);
    uint32_t l0 = pack_lo(v.x, v.y, h0), l1 = pack_lo(v.z, v.w, h1);
    size_t off = (size_t)z * Ee * Ee + (size_t)i * 4;
    uint32_t* hp = (uint32_t*)(hi + off);
    uint32_t* lp = (uint32_t*)(lo + off);
    hp[0] = h0; hp[1] = h1; lp[0] = l0; lp[1] = l1;
}

// ------------------------- HMMA split-bf16 GEMM ------------------------------
// 256x128 CTA tile, 256 threads (8 warps, warp tile 64x64), K-chunk 64,
// 2-stage cp.async. 85 B/MMA smem traffic (vs 128 at 64x32 warp tile).
#define PCH 72
#define TA_B (256 * PCH * 2)              /* 36864 */
#define TW_B (128 * PCH * 2)              /* 18432 */
#define GSTAGE (2*TA_B + 2*TW_B)          /* 110592 */
#define GEMM_SMEM (GSTAGE * 2)            /* 221184 */

template<bool DO_COS>
__global__ __launch_bounds__(256, 1) void hmma_gemm(
    const __nv_bfloat16* __restrict__ Ahi, const __nv_bfloat16* __restrict__ Alo,
    const __nv_bfloat16* __restrict__ WhiB, const __nv_bfloat16* __restrict__ WloB,
    const float* __restrict__ theta,
    float* __restrict__ C,
    __nv_bfloat16* __restrict__ OHB, __nv_bfloat16* __restrict__ OLB)
{
    extern __shared__ __align__(16) char smem[];
    uint32_t sb = smem_u32(smem);

    int z = blockIdx.z;
    const __nv_bfloat16* Whi = WhiB + (size_t)z * Ee * Ee;
    const __nv_bfloat16* Wlo = WloB + (size_t)z * Ee * Ee;

    int tid = threadIdx.x, wid = tid >> 5, lane = tid & 31;
    int wm = wid & 3, wn = wid >> 2;          // 4 x 2 warp grid, tiles 64x64
    int g = lane >> 2, t = lane & 3;
    int lm = lane >> 3, li = lane & 7;
    int m0 = blockIdx.y * 256, n0 = blockIdx.x * 128;

    float acc[4][8][4] = {};                  // [mf][nf][reg]

    auto issue = [&](int c, int bs) {
        uint32_t b0 = sb + bs * GSTAGE;
#pragma unroll
        for (int u = 0; u < 8; u++) {
            int unit = tid + u * 256;         // 0..2047
            int row = unit >> 3, seg = unit & 7;
            size_t gA = (size_t)(m0 + row) * Ee + c * 64 + seg * 8;
            uint32_t so = (uint32_t)(row * PCH + seg * 8) * 2;
            cpa16(b0 + so,        Ahi + gA);
            cpa16(b0 + TA_B + so, Alo + gA);
        }
#pragma unroll
        for (int u = 0; u < 4; u++) {
            int unit = tid + u * 256;         // 0..1023
            int row = unit >> 3, seg = unit & 7;
            size_t gW = (size_t)(n0 + row) * Ee + c * 64 + seg * 8;
            uint32_t so = (uint32_t)(row * PCH + seg * 8) * 2;
            cpa16(b0 + 2 * TA_B + so,        Whi + gW);
            cpa16(b0 + 2 * TA_B + TW_B + so, Wlo + gW);
        }
    };

    issue(0, 0); CPA_COMMIT();
    issue(1, 1); CPA_COMMIT();

    for (int c = 0; c < 16; c++) {
        if (c == 15) CPA_WAIT0(); else CPA_WAIT1();
        __syncthreads();

        uint32_t bufA = sb + (c & 1) * GSTAGE;
        uint32_t bufW = bufA + 2 * TA_B;

#pragma unroll
        for (int ks = 0; ks < 4; ks++) {
            uint32_t ah[4][4], al[4][4];
#pragma unroll
            for (int mf = 0; mf < 4; mf++) {
                uint32_t ad = bufA +
                    (uint32_t)(((wm * 64 + mf * 16 + (lm & 1) * 8 + li) * PCH)
                               + ks * 16 + (lm >> 1) * 8) * 2;
                ldsm_x4(ah[mf], ad);
                ldsm_x4(al[mf], ad + TA_B);
            }
#pragma unroll
            for (int nfp = 0; nfp < 4; nfp++) {
                uint32_t bd = bufW +
                    (uint32_t)(((wn * 64 + (nfp * 2 + (lm >> 1)) * 8 + li) * PCH)
                               + ks * 16 + (lm & 1) * 8) * 2;
                uint32_t bh[4], bl[4];
                ldsm_x4(bh, bd);
                ldsm_x4(bl, bd + TW_B);
#pragma unroll
                for (int mf = 0; mf < 4; mf++) {
                    mma16816(acc[mf][nfp*2],   ah[mf], bh);
                    mma16816(acc[mf][nfp*2+1], ah[mf], bh + 2);
                }
#pragma unroll
                for (int mf = 0; mf < 4; mf++) {
                    mma16816(acc[mf][nfp*2],   ah[mf], bl);
                    mma16816(acc[mf][nfp*2+1], ah[mf], bl + 2);
                }
#pragma unroll
                for (int mf = 0; mf < 4; mf++) {
                    mma16816(acc[mf][nfp*2],   al[mf], bh);
                    mma16816(acc[mf][nfp*2+1], al[mf], bh + 2);
                }
            }
        }
        __syncthreads();
        if (c < 14) { issue(c + 2, c & 1); CPA_COMMIT(); }
    }

    __nv_bfloat16* OH = DO_COS ? OHB + (size_t)z * Mm * Ee : nullptr;
    __nv_bfloat16* OL = DO_COS ? OLB + (size_t)z * Mm * Ee : nullptr;
    float osc = (DO_COS && z == 0) ? QSCALE : 1.0f;   // pre-scale Q for softmax
#pragma unroll
    for (int mf = 0; mf < 4; mf++) {
#pragma unroll
        for (int nf = 0; nf < 8; nf++) {
            int r = m0 + wm * 64 + mf * 16 + g;
            int cb = n0 + wn * 64 + nf * 8 + 2 * t;
            float v0 = acc[mf][nf][0], v1 = acc[mf][nf][1];
            float v2 = acc[mf][nf][2], v3 = acc[mf][nf][3];
            if (DO_COS) {
                float t0 = theta[cb & 63], t1 = theta[(cb + 1) & 63];
                v0 = __cosf(v0 + t0) * osc; v1 = __cosf(v1 + t1) * osc;
                v2 = __cosf(v2 + t0) * osc; v3 = __cosf(v3 + t1) * osc;
                uint32_t h0 = pack_hi(v0, v1), h1 = pack_hi(v2, v3);
                *(uint32_t*)&OH[(size_t)r * Ee + cb]       = h0;
                *(uint32_t*)&OH[(size_t)(r + 8) * Ee + cb] = h1;
                *(uint32_t*)&OL[(size_t)r * Ee + cb]       = pack_lo(v0, v1, h0);
                *(uint32_t*)&OL[(size_t)(r + 8) * Ee + cb] = pack_lo(v2, v3, h1);
            } else {
                *(float2*)&C[(size_t)r * Ee + cb]       = float2{v0, v1};
                *(float2*)&C[(size_t)(r + 8) * Ee + cb] = float2{v2, v3};
            }
        }
    }
}

// ------------------------- HMMA flash attention (unchanged from R11) ---------
#define PKV 72
#define KVB (64 * PKV * 2)               /* 9216 */
#define STAGEB (KVB * 2)                 /* 18432 */
#define ATT_SMEM (STAGEB * 3)            /* 55296 */

__global__ __launch_bounds__(256, 2) void attn_mma(
    const __nv_bfloat16* __restrict__ qhi,
    const __nv_bfloat16* __restrict__ khi,
    const __nv_bfloat16* __restrict__ vhi,
    __nv_bfloat16* __restrict__ chi, __nv_bfloat16* __restrict__ clo)
{
    extern __shared__ __align__(16) char smem[];
    uint32_t sb = smem_u32(smem);

    int tid = threadIdx.x, wid = tid >> 5, lane = tid & 31;
    int g = lane >> 2, t = lane & 3;
    int lm = lane >> 3, li = lane & 7;
    int bh_ = blockIdx.y;
    int b = bh_ >> 4, h = bh_ & 15;
    int q0 = blockIdx.x * 128;
    size_t base = (size_t)b * Ss * Ee + (size_t)h * Dk;

    uint32_t qh[4][4];
    {
        size_t r0 = base + (size_t)(q0 + wid * 16 + g) * Ee;
        size_t r1 = r0 + 8 * (size_t)Ee;
#pragma unroll
        for (int ks = 0; ks < 4; ks++) {
            int c0 = ks * 16 + 2 * t;
            qh[ks][0] = *(const uint32_t*)&qhi[r0 + c0];
            qh[ks][1] = *(const uint32_t*)&qhi[r1 + c0];
            qh[ks][2] = *(const uint32_t*)&qhi[r0 + c0 + 8];
            qh[ks][3] = *(const uint32_t*)&qhi[r1 + c0 + 8];
        }
    }

    auto issue = [&](int j0, int s) {
        uint32_t b0 = sb + s * STAGEB;
#pragma unroll
        for (int u = 0; u < 2; u++) {
            int unit = tid + u * 256;
            int row = unit >> 3, seg = unit & 7;
            size_t gk = base + (size_t)(j0 + row) * Ee + seg * 8;
            uint32_t so = (uint32_t)(row * PKV + seg * 8) * 2;
            cpa16(b0 + so,       khi + gk);
            cpa16(b0 + KVB + so, vhi + gk);
        }
    };

    float m0 = -1e30f, m1 = -1e30f, l0 = 0.0f, l1 = 0.0f;
    float out[8][4] = {};

    issue(0, 0);  CPA_COMMIT();
    issue(64, 1); CPA_COMMIT();

    for (int tile = 0; tile < 32; tile++) {
        if (tile == 31) CPA_WAIT0(); else CPA_WAIT1();
        __syncthreads();
        if (tile < 30) { issue((tile + 2) * 64, (tile + 2) % 3); CPA_COMMIT(); }

        uint32_t kb = sb + (tile % 3) * STAGEB;
        uint32_t vb = kb + KVB;

        float s[8][4] = {};
#pragma unroll
        for (int ks = 0; ks < 4; ks++) {
#pragma unroll
            for (int nfp = 0; nfp < 4; nfp++) {
                uint32_t ad = kb +
                    (uint32_t)(((nfp * 2 + (lm >> 1)) * 8 + li) * PKV
                               + ks * 16 + (lm & 1) * 8) * 2;
                uint32_t bhv[4];
                ldsm_x4(bhv, ad);
                mma16816(s[nfp*2],   qh[ks], bhv);
                mma16816(s[nfp*2+1], qh[ks], bhv + 2);
            }
        }

        float mx0 = -1e30f, mx1 = -1e30f;
#pragma unroll
        for (int nf = 0; nf < 8; nf++) {
            mx0 = fmaxf(mx0, fmaxf(s[nf][0], s[nf][1]));
            mx1 = fmaxf(mx1, fmaxf(s[nf][2], s[nf][3]));
        }
        mx0 = fmaxf(mx0, __shfl_xor_sync(0xffffffffu, mx0, 1));
        mx0 = fmaxf(mx0, __shfl_xor_sync(0xffffffffu, mx0, 2));
        mx1 = fmaxf(mx1, __shfl_xor_sync(0xffffffffu, mx1, 1));
        mx1 = fmaxf(mx1, __shfl_xor_sync(0xffffffffu, mx1, 2));
        float mn0 = fmaxf(m0, mx0), mn1 = fmaxf(m1, mx1);

        float sum0 = 0.0f, sum1 = 0.0f;
#pragma unroll
        for (int nf = 0; nf < 8; nf++) {
            s[nf][0] = ex2(s[nf][0] - mn0);
            s[nf][1] = ex2(s[nf][1] - mn0);
            s[nf][2] = ex2(s[nf][2] - mn1);
            s[nf][3] = ex2(s[nf][3] - mn1);
            sum0 += s[nf][0] + s[nf][1];
            sum1 += s[nf][2] + s[nf][3];
        }
        sum0 += __shfl_xor_sync(0xffffffffu, sum0, 1);
        sum0 += __shfl_xor_sync(0xffffffffu, sum0, 2);
        sum1 += __shfl_xor_sync(0xffffffffu, sum1, 1);
        sum1 += __shfl_xor_sync(0xffffffffu, sum1, 2);

        bool upd = __any_sync(0xffffffffu, (mn0 != m0) | (mn1 != m1));
        if (upd) {
            float sc0 = ex2(m0 - mn0);
            float sc1 = ex2(m1 - mn1);
            l0 = l0 * sc0 + sum0;
            l1 = l1 * sc1 + sum1;
#pragma unroll
            for (int nfo = 0; nfo < 8; nfo++) {
                out[nfo][0] *= sc0; out[nfo][1] *= sc0;
                out[nfo][2] *= sc1; out[nfo][3] *= sc1;
            }
            m0 = mn0; m1 = mn1;
        } else {
            l0 += sum0;
            l1 += sum1;
        }

        uint32_t pa[4][4];
#pragma unroll
        for (int k2 = 0; k2 < 4; k2++) {
            pa[k2][0] = pack_hi(s[2*k2][0],   s[2*k2][1]);
            pa[k2][1] = pack_hi(s[2*k2][2],   s[2*k2][3]);
            pa[k2][2] = pack_hi(s[2*k2+1][0], s[2*k2+1][1]);
            pa[k2][3] = pack_hi(s[2*k2+1][2], s[2*k2+1][3]);
        }

#pragma unroll
        for (int ks2 = 0; ks2 < 4; ks2++) {
#pragma unroll
            for (int nfp = 0; nfp < 4; nfp++) {
                uint32_t ad = vb +
                    (uint32_t)((ks2 * 16 + (lm & 1) * 8 + li) * PKV
                               + (nfp * 2 + (lm >> 1)) * 8) * 2;
                uint32_t bvh[4];
                ldsm_x4_t(bvh, ad);
                mma16816(out[nfp*2],   pa[ks2], bvh);
                mma16816(out[nfp*2+1], pa[ks2], bvh + 2);
            }
        }
    }

    float inv0 = 1.0f / l0, inv1 = 1.0f / l1;
    size_t r0 = base + (size_t)(q0 + wid * 16 + g) * Ee;
    size_t r1 = r0 + 8 * (size_t)Ee;
#pragma unroll
    for (int nfo = 0; nfo < 8; nfo++) {
        int d = nfo * 8 + 2 * t;
        float v0 = out[nfo][0] * inv0, v1 = out[nfo][1] * inv0;
        float v2 = out[nfo][2] * inv1, v3 = out[nfo][3] * inv1;
        uint32_t h0 = pack_hi(v0, v1), h1 = pack_hi(v2, v3);
        *(uint32_t*)&chi[r0 + d] = h0;
        *(uint32_t*)&chi[r1 + d] = h1;
        *(uint32_t*)&clo[r0 + d] = pack_lo(v0, v1, h0);
        *(uint32_t*)&clo[r1 + d] = pack_lo(v2, v3, h1);
    }
}

// ---------------------------------------------------------------------------
extern "C" void kernel_launch(void* const* d_in, const int* in_sizes, int n_in,
                              void* d_out, int out_size)
{
    const float* x     = (const float*)d_in[0];
    const float* Wq    = (const float*)d_in[1];
    const float* Wk    = (const float*)d_in[2];
    const float* Wv    = (const float*)d_in[3];
    const float* Wo    = (const float*)d_in[4];
    const float* theta = (const float*)d_in[5];
    float* out = (float*)d_out;

    __nv_bfloat16 *xhi, *xlo, *qkvhi, *qkvlo, *chi, *clo, *whi, *wlo;
    cudaGetSymbolAddress((void**)&xhi, g_xhi);
    cudaGetSymbolAddress((void**)&xlo, g_xlo);
    cudaGetSymbolAddress((void**)&qkvhi, g_qkvhi);
    cudaGetSymbolAddress((void**)&qkvlo, g_qkvlo);
    cudaGetSymbolAddress((void**)&chi, g_chi);
    cudaGetSymbolAddress((void**)&clo, g_clo);
    cudaGetSymbolAddress((void**)&whi, g_whi);
    cudaGetSymbolAddress((void**)&wlo, g_wlo);

    cudaFuncSetAttribute(hmma_gemm<true>,
        cudaFuncAttributeMaxDynamicSharedMemorySize, GEMM_SMEM);
    cudaFuncSetAttribute(hmma_gemm<false>,
        cudaFuncAttributeMaxDynamicSharedMemorySize, GEMM_SMEM);
    cudaFuncSetAttribute(attn_mma,
        cudaFuncAttributeMaxDynamicSharedMemorySize, ATT_SMEM);

    int n4x = Mm * Ee / 4;
    int n4w = Ee * Ee / 4;
    split_kernel<<<(n4x + 255) / 256, 256>>>((const float4*)x, xhi, xlo, n4x);
    dim3 gw((n4w + 255) / 256, 4);
    split4_kernel<<<gw, 256>>>((const float4*)Wq, (const float4*)Wk,
                               (const float4*)Wv, (const float4*)Wo,
                               whi, wlo, n4w);

    dim3 g1(Ee / 128, Mm / 256, 3);
    hmma_gemm<true><<<g1, 256, GEMM_SMEM>>>(xhi, xlo, whi, wlo, theta,
                                            nullptr, qkvhi, qkvlo);

    size_t off = (size_t)Mm * Ee;
    dim3 g2(Ss / 128, Bb * Hh);
    attn_mma<<<g2, 256, ATT_SMEM>>>(qkvhi,
                                    qkvhi + off,
                                    qkvhi + 2*off,
                                    chi, clo);

    dim3 g3(Ee / 128, Mm / 256, 1);
    hmma_gemm<false><<<g3, 256, GEMM_SMEM>>>(chi, clo,
        whi + 3*(size_t)Ee*Ee, wlo + 3*(size_t)Ee*Ee, nullptr, out,
        nullptr, nullptr);
}

// round 13
// speedup vs baseline: 1.7069x; 1.0585x over previous
#include <cuda_runtime.h>
#include <cuda_bf16.h>
#include <math.h>
#include <stdint.h>

#define Bb 4
#define Ss 2048
#define Ee 1024
#define Hh 16
#define Dk 64
#define Mm (Bb*Ss)   /* 8192 */

#define QSCALE 0.1803368801111204f   /* 0.125 * log2(e) */

// ------------------------- device scratch (no allocs) ----------------------
__device__ __nv_bfloat16 g_xhi[Mm*Ee];
__device__ __nv_bfloat16 g_xlo[Mm*Ee];
__device__ __nv_bfloat16 g_qkvhi[3*Mm*Ee];   // q(scaled) | k | v
__device__ __nv_bfloat16 g_qkvlo[3*Mm*Ee];
__device__ __nv_bfloat16 g_chi[Mm*Ee];
__device__ __nv_bfloat16 g_clo[Mm*Ee];
__device__ __nv_bfloat16 g_whi[4*Ee*Ee];
__device__ __nv_bfloat16 g_wlo[4*Ee*Ee];

// ------------------------- helpers ------------------------------------------
__device__ __forceinline__ void mma16816(float* d, const uint32_t* a,
                                         const uint32_t* b)
{
    asm volatile(
        "mma.sync.aligned.m16n8k16.row.col.f32.bf16.bf16.f32 "
        "{%0,%1,%2,%3}, {%4,%5,%6,%7}, {%8,%9}, {%0,%1,%2,%3};"
        : "+f"(d[0]), "+f"(d[1]), "+f"(d[2]), "+f"(d[3])
        : "r"(a[0]), "r"(a[1]), "r"(a[2]), "r"(a[3]), "r"(b[0]), "r"(b[1]));
}
__device__ __forceinline__ void ldsm_x4(uint32_t* r, uint32_t addr) {
    asm volatile("ldmatrix.sync.aligned.m8n8.x4.shared.b16 {%0,%1,%2,%3}, [%4];"
        : "=r"(r[0]), "=r"(r[1]), "=r"(r[2]), "=r"(r[3]) : "r"(addr));
}
__device__ __forceinline__ void ldsm_x4_t(uint32_t* r, uint32_t addr) {
    asm volatile("ldmatrix.sync.aligned.m8n8.x4.trans.shared.b16 {%0,%1,%2,%3}, [%4];"
        : "=r"(r[0]), "=r"(r[1]), "=r"(r[2]), "=r"(r[3]) : "r"(addr));
}
__device__ __forceinline__ uint32_t smem_u32(const void* p) {
    uint32_t a;
    asm("{ .reg .u64 t; cvta.to.shared.u64 t, %1; cvt.u32.u64 %0, t; }"
        : "=r"(a) : "l"(p));
    return a;
}
__device__ __forceinline__ void cpa16(uint32_t s, const void* g) {
    asm volatile("cp.async.cg.shared.global [%0], [%1], 16;" :: "r"(s), "l"(g));
}
#define CPA_COMMIT() asm volatile("cp.async.commit_group;" ::: "memory")
#define CPA_WAIT1()  asm volatile("cp.async.wait_group 1;" ::: "memory")
#define CPA_WAIT0()  asm volatile("cp.async.wait_group 0;" ::: "memory")

__device__ __forceinline__ float ex2(float x) {
    float r;
    asm("ex2.approx.f32 %0, %1;" : "=f"(r) : "f"(x));
    return r;
}
__device__ __forceinline__ uint32_t pack_hi(float x, float y) {
    __nv_bfloat162 h = __floats2bfloat162_rn(x, y);
    return *(uint32_t*)&h;
}
__device__ __forceinline__ uint32_t pack_lo(float x, float y, uint32_t hiu) {
    __nv_bfloat162 h = *(__nv_bfloat162*)&hiu;
    __nv_bfloat162 l = __floats2bfloat162_rn(x - __bfloat162float(h.x),
                                             y - __bfloat162float(h.y));
    return *(uint32_t*)&l;
}

// ------------------------- fp32 -> bf16 hi/lo splits -------------------------
__global__ __launch_bounds__(256) void split_kernel(const float4* __restrict__ src,
                                                    __nv_bfloat16* __restrict__ hi,
                                                    __nv_bfloat16* __restrict__ lo,
                                                    int n4)
{
    int i = blockIdx.x * 256 + threadIdx.x;
    if (i >= n4) return;
    float4 v = src[i];
    uint32_t h0 = pack_hi(v.x, v.y), h1 = pack_hi(v.z, v.w);
    uint32_t l0 = pack_lo(v.x, v.y, h0), l1 = pack_lo(v.z, v.w, h1);
    uint32_t* hp = (uint32_t*)(hi + (size_t)i * 4);
    uint32_t* lp = (uint32_t*)(lo + (size_t)i * 4);
    hp[0] = h0; hp[1] = h1; lp[0] = l0; lp[1] = l1;
}

__global__ __launch_bounds__(256) void split4_kernel(
    const float4* __restrict__ s0, const float4* __restrict__ s1,
    const float4* __restrict__ s2, const float4* __restrict__ s3,
    __nv_bfloat16* __restrict__ hi, __nv_bfloat16* __restrict__ lo, int n4)
{
    int z = blockIdx.y;
    const float4* src = (z == 0) ? s0 : (z == 1) ? s1 : (z == 2) ? s2 : s3;
    int i = blockIdx.x * 256 + threadIdx.x;
    if (i >= n4) return;
    float4 v = src[i];
    uint32_t h0 = pack_hi(v.x, v.y), h1 = pack_hi(v.z, v.w);
    uint32_t l0 = pack_lo(v.x, v.y, h0), l1 = pack_lo(v.z, v.w, h1);
    size_t off = (size_t)z * Ee * Ee + (size_t)i * 4;
    uint32_t* hp = (uint32_t*)(hi + off);
    uint32_t* lp = (uint32_t*)(lo + off);
    hp[0] = h0; hp[1] = h1; lp[0] = l0; lp[1] = l1;
}

// ------------------------- HMMA split-bf16 GEMM (3-term, 64x64 warp tile) ----
#define PCH 72
#define TA_B (256 * PCH * 2)              /* 36864 */
#define TW_B (128 * PCH * 2)              /* 18432 */
#define GSTAGE (2*TA_B + 2*TW_B)          /* 110592 */
#define GEMM_SMEM (GSTAGE * 2)            /* 221184 */

template<bool DO_COS>
__global__ __launch_bounds__(256, 1) void hmma_gemm(
    const __nv_bfloat16* __restrict__ Ahi, const __nv_bfloat16* __restrict__ Alo,
    const __nv_bfloat16* __restrict__ WhiB, const __nv_bfloat16* __restrict__ WloB,
    const float* __restrict__ theta,
    float* __restrict__ C,
    __nv_bfloat16* __restrict__ OHB, __nv_bfloat16* __restrict__ OLB)
{
    extern __shared__ __align__(16) char smem[];
    uint32_t sb = smem_u32(smem);

    int z = blockIdx.z;
    const __nv_bfloat16* Whi = WhiB + (size_t)z * Ee * Ee;
    const __nv_bfloat16* Wlo = WloB + (size_t)z * Ee * Ee;

    int tid = threadIdx.x, wid = tid >> 5, lane = tid & 31;
    int wm = wid & 3, wn = wid >> 2;          // 4 x 2 warp grid, tiles 64x64
    int g = lane >> 2, t = lane & 3;
    int lm = lane >> 3, li = lane & 7;
    int m0 = blockIdx.y * 256, n0 = blockIdx.x * 128;

    float acc[4][8][4] = {};

    auto issue = [&](int c, int bs) {
        uint32_t b0 = sb + bs * GSTAGE;
#pragma unroll
        for (int u = 0; u < 8; u++) {
            int unit = tid + u * 256;
            int row = unit >> 3, seg = unit & 7;
            size_t gA = (size_t)(m0 + row) * Ee + c * 64 + seg * 8;
            uint32_t so = (uint32_t)(row * PCH + seg * 8) * 2;
            cpa16(b0 + so,        Ahi + gA);
            cpa16(b0 + TA_B + so, Alo + gA);
        }
#pragma unroll
        for (int u = 0; u < 4; u++) {
            int unit = tid + u * 256;
            int row = unit >> 3, seg = unit & 7;
            size_t gW = (size_t)(n0 + row) * Ee + c * 64 + seg * 8;
            uint32_t so = (uint32_t)(row * PCH + seg * 8) * 2;
            cpa16(b0 + 2 * TA_B + so,        Whi + gW);
            cpa16(b0 + 2 * TA_B + TW_B + so, Wlo + gW);
        }
    };

    issue(0, 0); CPA_COMMIT();
    issue(1, 1); CPA_COMMIT();

    for (int c = 0; c < 16; c++) {
        if (c == 15) CPA_WAIT0(); else CPA_WAIT1();
        __syncthreads();

        uint32_t bufA = sb + (c & 1) * GSTAGE;
        uint32_t bufW = bufA + 2 * TA_B;

#pragma unroll
        for (int ks = 0; ks < 4; ks++) {
            uint32_t ah[4][4], al[4][4];
#pragma unroll
            for (int mf = 0; mf < 4; mf++) {
                uint32_t ad = bufA +
                    (uint32_t)(((wm * 64 + mf * 16 + (lm & 1) * 8 + li) * PCH)
                               + ks * 16 + (lm >> 1) * 8) * 2;
                ldsm_x4(ah[mf], ad);
                ldsm_x4(al[mf], ad + TA_B);
            }
#pragma unroll
            for (int nfp = 0; nfp < 4; nfp++) {
                uint32_t bd = bufW +
                    (uint32_t)(((wn * 64 + (nfp * 2 + (lm >> 1)) * 8 + li) * PCH)
                               + ks * 16 + (lm & 1) * 8) * 2;
                uint32_t bh[4], bl[4];
                ldsm_x4(bh, bd);
                ldsm_x4(bl, bd + TW_B);
#pragma unroll
                for (int mf = 0; mf < 4; mf++) {
                    mma16816(acc[mf][nfp*2],   ah[mf], bh);
                    mma16816(acc[mf][nfp*2+1], ah[mf], bh + 2);
                }
#pragma unroll
                for (int mf = 0; mf < 4; mf++) {
                    mma16816(acc[mf][nfp*2],   ah[mf], bl);
                    mma16816(acc[mf][nfp*2+1], ah[mf], bl + 2);
                }
#pragma unroll
                for (int mf = 0; mf < 4; mf++) {
                    mma16816(acc[mf][nfp*2],   al[mf], bh);
                    mma16816(acc[mf][nfp*2+1], al[mf], bh + 2);
                }
            }
        }
        __syncthreads();
        if (c < 14) { issue(c + 2, c & 1); CPA_COMMIT(); }
    }

    __nv_bfloat16* OH = DO_COS ? OHB + (size_t)z * Mm * Ee : nullptr;
    __nv_bfloat16* OL = DO_COS ? OLB + (size_t)z * Mm * Ee : nullptr;
    float osc = (DO_COS && z == 0) ? QSCALE : 1.0f;   // pre-scale Q for softmax
#pragma unroll
    for (int mf = 0; mf < 4; mf++) {
#pragma unroll
        for (int nf = 0; nf < 8; nf++) {
            int r = m0 + wm * 64 + mf * 16 + g;
            int cb = n0 + wn * 64 + nf * 8 + 2 * t;
            float v0 = acc[mf][nf][0], v1 = acc[mf][nf][1];
            float v2 = acc[mf][nf][2], v3 = acc[mf][nf][3];
            if (DO_COS) {
                float t0 = theta[cb & 63], t1 = theta[(cb + 1) & 63];
                v0 = __cosf(v0 + t0) * osc; v1 = __cosf(v1 + t1) * osc;
                v2 = __cosf(v2 + t0) * osc; v3 = __cosf(v3 + t1) * osc;
                uint32_t h0 = pack_hi(v0, v1), h1 = pack_hi(v2, v3);
                *(uint32_t*)&OH[(size_t)r * Ee + cb]       = h0;
                *(uint32_t*)&OH[(size_t)(r + 8) * Ee + cb] = h1;
                *(uint32_t*)&OL[(size_t)r * Ee + cb]       = pack_lo(v0, v1, h0);
                *(uint32_t*)&OL[(size_t)(r + 8) * Ee + cb] = pack_lo(v2, v3, h1);
            } else {
                *(float2*)&C[(size_t)r * Ee + cb]       = float2{v0, v1};
                *(float2*)&C[(size_t)(r + 8) * Ee + cb] = float2{v2, v3};
            }
        }
    }
}

// ------------------------- HMMA flash attention -------------------------------
// Fixed-base softmax: logits bounded (|s|<=11.54 in exp2 units), so no running
// max, no rescale; lane-local normalizer reduced once after the loop.
#define PKV 72
#define KVB (64 * PKV * 2)               /* 9216 */
#define STAGEB (KVB * 2)                 /* 18432 */
#define ATT_SMEM (STAGEB * 3)            /* 55296 */

__global__ __launch_bounds__(256, 2) void attn_mma(
    const __nv_bfloat16* __restrict__ qhi,
    const __nv_bfloat16* __restrict__ khi,
    const __nv_bfloat16* __restrict__ vhi,
    __nv_bfloat16* __restrict__ chi, __nv_bfloat16* __restrict__ clo)
{
    extern __shared__ __align__(16) char smem[];
    uint32_t sb = smem_u32(smem);

    int tid = threadIdx.x, wid = tid >> 5, lane = tid & 31;
    int g = lane >> 2, t = lane & 3;
    int lm = lane >> 3, li = lane & 7;
    int bh_ = blockIdx.y;
    int b = bh_ >> 4, h = bh_ & 15;
    int q0 = blockIdx.x * 128;
    size_t base = (size_t)b * Ss * Ee + (size_t)h * Dk;

    uint32_t qh[4][4];
    {
        size_t r0 = base + (size_t)(q0 + wid * 16 + g) * Ee;
        size_t r1 = r0 + 8 * (size_t)Ee;
#pragma unroll
        for (int ks = 0; ks < 4; ks++) {
            int c0 = ks * 16 + 2 * t;
            qh[ks][0] = *(const uint32_t*)&qhi[r0 + c0];
            qh[ks][1] = *(const uint32_t*)&qhi[r1 + c0];
            qh[ks][2] = *(const uint32_t*)&qhi[r0 + c0 + 8];
            qh[ks][3] = *(const uint32_t*)&qhi[r1 + c0 + 8];
        }
    }

    auto issue = [&](int j0, int s) {
        uint32_t b0 = sb + s * STAGEB;
#pragma unroll
        for (int u = 0; u < 2; u++) {
            int unit = tid + u * 256;
            int row = unit >> 3, seg = unit & 7;
            size_t gk = base + (size_t)(j0 + row) * Ee + seg * 8;
            uint32_t so = (uint32_t)(row * PKV + seg * 8) * 2;
            cpa16(b0 + so,       khi + gk);
            cpa16(b0 + KVB + so, vhi + gk);
        }
    };

    float l0 = 0.0f, l1 = 0.0f;          // lane-local partial normalizers
    float out[8][4] = {};

    issue(0, 0);  CPA_COMMIT();
    issue(64, 1); CPA_COMMIT();

    for (int tile = 0; tile < 32; tile++) {
        if (tile == 31) CPA_WAIT0(); else CPA_WAIT1();
        __syncthreads();
        if (tile < 30) { issue((tile + 2) * 64, (tile + 2) % 3); CPA_COMMIT(); }

        uint32_t kb = sb + (tile % 3) * STAGEB;
        uint32_t vb = kb + KVB;

        // QK^T (1-term, q pre-scaled by 0.125*log2e)
        float s[8][4] = {};
#pragma unroll
        for (int ks = 0; ks < 4; ks++) {
#pragma unroll
            for (int nfp = 0; nfp < 4; nfp++) {
                uint32_t ad = kb +
                    (uint32_t)(((nfp * 2 + (lm >> 1)) * 8 + li) * PKV
                               + ks * 16 + (lm & 1) * 8) * 2;
                uint32_t bhv[4];
                ldsm_x4(bhv, ad);
                mma16816(s[nfp*2],   qh[ks], bhv);
                mma16816(s[nfp*2+1], qh[ks], bhv + 2);
            }
        }

        // fixed-base exp2: no max subtraction needed (bounded logits)
#pragma unroll
        for (int nf = 0; nf < 8; nf++) {
            s[nf][0] = ex2(s[nf][0]);
            s[nf][1] = ex2(s[nf][1]);
            s[nf][2] = ex2(s[nf][2]);
            s[nf][3] = ex2(s[nf][3]);
            l0 += s[nf][0] + s[nf][1];
            l1 += s[nf][2] + s[nf][3];
        }

        // pack P to bf16 for PV
        uint32_t pa[4][4];
#pragma unroll
        for (int k2 = 0; k2 < 4; k2++) {
            pa[k2][0] = pack_hi(s[2*k2][0],   s[2*k2][1]);
            pa[k2][1] = pack_hi(s[2*k2][2],   s[2*k2][3]);
            pa[k2][2] = pack_hi(s[2*k2+1][0], s[2*k2+1][1]);
            pa[k2][3] = pack_hi(s[2*k2+1][2], s[2*k2+1][3]);
        }

        // PV (1-term), B via ldmatrix.trans
#pragma unroll
        for (int ks2 = 0; ks2 < 4; ks2++) {
#pragma unroll
            for (int nfp = 0; nfp < 4; nfp++) {
                uint32_t ad = vb +
                    (uint32_t)((ks2 * 16 + (lm & 1) * 8 + li) * PKV
                               + (nfp * 2 + (lm >> 1)) * 8) * 2;
                uint32_t bvh[4];
                ldsm_x4_t(bvh, ad);
                mma16816(out[nfp*2],   pa[ks2], bvh);
                mma16816(out[nfp*2+1], pa[ks2], bvh + 2);
            }
        }
    }

    // single cross-lane normalizer reduction after the loop
    l0 += __shfl_xor_sync(0xffffffffu, l0, 1);
    l0 += __shfl_xor_sync(0xffffffffu, l0, 2);
    l1 += __shfl_xor_sync(0xffffffffu, l1, 1);
    l1 += __shfl_xor_sync(0xffffffffu, l1, 2);

    float inv0 = 1.0f / l0, inv1 = 1.0f / l1;
    size_t r0 = base + (size_t)(q0 + wid * 16 + g) * Ee;
    size_t r1 = r0 + 8 * (size_t)Ee;
#pragma unroll
    for (int nfo = 0; nfo < 8; nfo++) {
        int d = nfo * 8 + 2 * t;
        float v0 = out[nfo][0] * inv0, v1 = out[nfo][1] * inv0;
        float v2 = out[nfo][2] * inv1, v3 = out[nfo][3] * inv1;
        uint32_t h0 = pack_hi(v0, v1), h1 = pack_hi(v2, v3);
        *(uint32_t*)&chi[r0 + d] = h0;
        *(uint32_t*)&chi[r1 + d] = h1;
        *(uint32_t*)&clo[r0 + d] = pack_lo(v0, v1, h0);
        *(uint32_t*)&clo[r1 + d] = pack_lo(v2, v3, h1);
    }
}

// ---------------------------------------------------------------------------
extern "C" void kernel_launch(void* const* d_in, const int* in_sizes, int n_in,
                              void* d_out, int out_size)
{
    const float* x     = (const float*)d_in[0];
    const float* Wq    = (const float*)d_in[1];
    const float* Wk    = (const float*)d_in[2];
    const float* Wv    = (const float*)d_in[3];
    const float* Wo    = (const float*)d_in[4];
    const float* theta = (const float*)d_in[5];
    float* out = (float*)d_out;

    __nv_bfloat16 *xhi, *xlo, *qkvhi, *qkvlo, *chi, *clo, *whi, *wlo;
    cudaGetSymbolAddress((void**)&xhi, g_xhi);
    cudaGetSymbolAddress((void**)&xlo, g_xlo);
    cudaGetSymbolAddress((void**)&qkvhi, g_qkvhi);
    cudaGetSymbolAddress((void**)&qkvlo, g_qkvlo);
    cudaGetSymbolAddress((void**)&chi, g_chi);
    cudaGetSymbolAddress((void**)&clo, g_clo);
    cudaGetSymbolAddress((void**)&whi, g_whi);
    cudaGetSymbolAddress((void**)&wlo, g_wlo);

    cudaFuncSetAttribute(hmma_gemm<true>,
        cudaFuncAttributeMaxDynamicSharedMemorySize, GEMM_SMEM);
    cudaFuncSetAttribute(hmma_gemm<false>,
        cudaFuncAttributeMaxDynamicSharedMemorySize, GEMM_SMEM);
    cudaFuncSetAttribute(attn_mma,
        cudaFuncAttributeMaxDynamicSharedMemorySize, ATT_SMEM);

    int n4x = Mm * Ee / 4;
    int n4w = Ee * Ee / 4;
    split_kernel<<<(n4x + 255) / 256, 256>>>((const float4*)x, xhi, xlo, n4x);
    dim3 gw((n4w + 255) / 256, 4);
    split4_kernel<<<gw, 256>>>((const float4*)Wq, (const float4*)Wk,
                               (const float4*)Wv, (const float4*)Wo,
                               whi, wlo, n4w);

    dim3 g1(Ee / 128, Mm / 256, 3);
    hmma_gemm<true><<<g1, 256, GEMM_SMEM>>>(xhi, xlo, whi, wlo, theta,
                                            nullptr, qkvhi, qkvlo);

    size_t off = (size_t)Mm * Ee;
    dim3 g2(Ss / 128, Bb * Hh);
    attn_mma<<<g2, 256, ATT_SMEM>>>(qkvhi,
                                    qkvhi + off,
                                    qkvhi + 2*off,
                                    chi, clo);

    dim3 g3(Ee / 128, Mm / 256, 1);
    hmma_gemm<false><<<g3, 256, GEMM_SMEM>>>(chi, clo,
        whi + 3*(size_t)Ee*Ee, wlo + 3*(size_t)Ee*Ee, nullptr, out,
        nullptr, nullptr);
}

// round 14
// speedup vs baseline: 1.7344x; 1.0161x over previous
#include <cuda_runtime.h>
#include <cuda_bf16.h>
#include <math.h>
#include <stdint.h>

#define Bb 4
#define Ss 2048
#define Ee 1024
#define Hh 16
#define Dk 64
#define Mm (Bb*Ss)   /* 8192 */

#define QSCALE 0.1803368801111204f   /* 0.125 * log2(e) */

// ------------------------- device scratch (no allocs) ----------------------
__device__ __nv_bfloat16 g_xhi[Mm*Ee];
__device__ __nv_bfloat16 g_xlo[Mm*Ee];
__device__ __nv_bfloat16 g_qkvhi[3*Mm*Ee];   // q(scaled) | k | v
__device__ __nv_bfloat16 g_qkvlo[3*Mm*Ee];
__device__ __nv_bfloat16 g_chi[Mm*Ee];
__device__ __nv_bfloat16 g_clo[Mm*Ee];
__device__ __nv_bfloat16 g_whi[4*Ee*Ee];
__device__ __nv_bfloat16 g_wlo[4*Ee*Ee];

// ------------------------- helpers ------------------------------------------
__device__ __forceinline__ void mma16816(float* d, const uint32_t* a,
                                         const uint32_t* b)
{
    asm volatile(
        "mma.sync.aligned.m16n8k16.row.col.f32.bf16.bf16.f32 "
        "{%0,%1,%2,%3}, {%4,%5,%6,%7}, {%8,%9}, {%0,%1,%2,%3};"
        : "+f"(d[0]), "+f"(d[1]), "+f"(d[2]), "+f"(d[3])
        : "r"(a[0]), "r"(a[1]), "r"(a[2]), "r"(a[3]), "r"(b[0]), "r"(b[1]));
}
__device__ __forceinline__ void ldsm_x4(uint32_t* r, uint32_t addr) {
    asm volatile("ldmatrix.sync.aligned.m8n8.x4.shared.b16 {%0,%1,%2,%3}, [%4];"
        : "=r"(r[0]), "=r"(r[1]), "=r"(r[2]), "=r"(r[3]) : "r"(addr));
}
__device__ __forceinline__ void ldsm_x4_t(uint32_t* r, uint32_t addr) {
    asm volatile("ldmatrix.sync.aligned.m8n8.x4.trans.shared.b16 {%0,%1,%2,%3}, [%4];"
        : "=r"(r[0]), "=r"(r[1]), "=r"(r[2]), "=r"(r[3]) : "r"(addr));
}
__device__ __forceinline__ uint32_t smem_u32(const void* p) {
    uint32_t a;
    asm("{ .reg .u64 t; cvta.to.shared.u64 t, %1; cvt.u32.u64 %0, t; }"
        : "=r"(a) : "l"(p));
    return a;
}
__device__ __forceinline__ void cpa16(uint32_t s, const void* g) {
    asm volatile("cp.async.cg.shared.global [%0], [%1], 16;" :: "r"(s), "l"(g));
}
#define CPA_COMMIT() asm volatile("cp.async.commit_group;" ::: "memory")
#define CPA_WAIT1()  asm volatile("cp.async.wait_group 1;" ::: "memory")
#define CPA_WAIT0()  asm volatile("cp.async.wait_group 0;" ::: "memory")

__device__ __forceinline__ float ex2(float x) {
    float r;
    asm("ex2.approx.f32 %0, %1;" : "=f"(r) : "f"(x));
    return r;
}
__device__ __forceinline__ uint32_t pack_hi(float x, float y) {
    __nv_bfloat162 h = __floats2bfloat162_rn(x, y);
    return *(uint32_t*)&h;
}
__device__ __forceinline__ uint32_t pack_lo(float x, float y, uint32_t hiu) {
    __nv_bfloat162 h = *(__nv_bfloat162*)&hiu;
    __nv_bfloat162 l = __floats2bfloat162_rn(x - __bfloat162float(h.x),
                                             y - __bfloat162float(h.y));
    return *(uint32_t*)&l;
}

// ------------------------- fp32 -> bf16 hi/lo splits -------------------------
__global__ __launch_bounds__(256) void split_kernel(const float4* __restrict__ src,
                                                    __nv_bfloat16* __restrict__ hi,
                                                    __nv_bfloat16* __restrict__ lo,
                                                    int n4)
{
    int i = blockIdx.x * 256 + threadIdx.x;
    if (i >= n4) return;
    float4 v = src[i];
    uint32_t h0 = pack_hi(v.x, v.y), h1 = pack_hi(v.z, v.w);
    uint32_t l0 = pack_lo(v.x, v.y, h0), l1 = pack_lo(v.z, v.w, h1);
    uint32_t* hp = (uint32_t*)(hi + (size_t)i * 4);
    uint32_t* lp = (uint32_t*)(lo + (size_t)i * 4);
    hp[0] = h0; hp[1] = h1; lp[0] = l0; lp[1] = l1;
}

__global__ __launch_bounds__(256) void split4_kernel(
    const float4* __restrict__ s0, const float4* __restrict__ s1,
    const float4* __restrict__ s2, const float4* __restrict__ s3,
    __nv_bfloat16* __restrict__ hi, __nv_bfloat16* __restrict__ lo, int n4)
{
    int z = blockIdx.y;
    const float4* src = (z == 0) ? s0 : (z == 1) ? s1 : (z == 2) ? s2 : s3;
    int i = blockIdx.x * 256 + threadIdx.x;
    if (i >= n4) return;
    float4 v = src[i];
    uint32_t h0 = pack_hi(v.x, v.y), h1 = pack_hi(v.z, v.w);
    uint32_t l0 = pack_lo(v.x, v.y, h0), l1 = pack_lo(v.z, v.w, h1);
    size_t off = (size_t)z * Ee * Ee + (size_t)i * 4;
    uint32_t* hp = (uint32_t*)(hi + off);
    uint32_t* lp = (uint32_t*)(lo + off);
    hp[0] = h0; hp[1] = h1; lp[0] = l0; lp[1] = l1;
}

// ------------------------- HMMA split-bf16 GEMM ------------------------------
// 128x128 CTA tile, 256 threads (8 warps, warp tile 64x32), K-chunk 32,
// pitch 40 (80B rows, conflict-free ldmatrix), 2 stages, 2 CTAs/SM.
#define PG 40
#define GT_B (128 * PG * 2)               /* 10240 per array */
#define GSTAGE (GT_B * 4)                 /* 40960 */
#define GEMM_SMEM (GSTAGE * 2)            /* 81920 -> 2 CTAs/SM */

template<bool DO_COS>
__global__ __launch_bounds__(256, 2) void hmma_gemm(
    const __nv_bfloat16* __restrict__ Ahi, const __nv_bfloat16* __restrict__ Alo,
    const __nv_bfloat16* __restrict__ WhiB, const __nv_bfloat16* __restrict__ WloB,
    const float* __restrict__ theta,
    float* __restrict__ C,
    __nv_bfloat16* __restrict__ OHB, __nv_bfloat16* __restrict__ OLB)
{
    extern __shared__ __align__(16) char smem[];
    uint32_t sb = smem_u32(smem);

    int z = blockIdx.z;
    const __nv_bfloat16* Whi = WhiB + (size_t)z * Ee * Ee;
    const __nv_bfloat16* Wlo = WloB + (size_t)z * Ee * Ee;

    int tid = threadIdx.x, wid = tid >> 5, lane = tid & 31;
    int wm = wid & 1, wn = wid >> 1;          // 2 x 4 warp grid, tiles 64x32
    int g = lane >> 2, t = lane & 3;
    int lm = lane >> 3, li = lane & 7;
    int m0 = blockIdx.y * 128, n0 = blockIdx.x * 128;

    float acc[4][4][4] = {};

    // chunk c covers K cols c*32 .. c*32+31
    auto issue = [&](int c, int bs) {
        uint32_t b0 = sb + bs * GSTAGE;
#pragma unroll
        for (int u = 0; u < 2; u++) {
            int unit = tid + u * 256;         // 0..511
            int row = unit >> 2, seg = unit & 3;
            size_t gA = (size_t)(m0 + row) * Ee + c * 32 + seg * 8;
            size_t gW = (size_t)(n0 + row) * Ee + c * 32 + seg * 8;
            uint32_t so = (uint32_t)(row * PG + seg * 8) * 2;
            cpa16(b0 + so,            Ahi + gA);
            cpa16(b0 + GT_B + so,     Alo + gA);
            cpa16(b0 + 2 * GT_B + so, Whi + gW);
            cpa16(b0 + 3 * GT_B + so, Wlo + gW);
        }
    };

    issue(0, 0); CPA_COMMIT();
    issue(1, 1); CPA_COMMIT();

    for (int c = 0; c < 32; c++) {
        if (c == 31) CPA_WAIT0(); else CPA_WAIT1();
        __syncthreads();

        uint32_t bufA = sb + (c & 1) * GSTAGE;
        uint32_t bufW = bufA + 2 * GT_B;

#pragma unroll
        for (int ks = 0; ks < 2; ks++) {
            uint32_t ah[4][4], al[4][4];
#pragma unroll
            for (int mf = 0; mf < 4; mf++) {
                uint32_t ad = bufA +
                    (uint32_t)(((wm * 64 + mf * 16 + (lm & 1) * 8 + li) * PG)
                               + ks * 16 + (lm >> 1) * 8) * 2;
                ldsm_x4(ah[mf], ad);
                ldsm_x4(al[mf], ad + GT_B);
            }
#pragma unroll
            for (int nfp = 0; nfp < 2; nfp++) {
                uint32_t bd = bufW +
                    (uint32_t)(((wn * 32 + (nfp * 2 + (lm >> 1)) * 8 + li) * PG)
                               + ks * 16 + (lm & 1) * 8) * 2;
                uint32_t bh[4], bl[4];
                ldsm_x4(bh, bd);
                ldsm_x4(bl, bd + GT_B);
#pragma unroll
                for (int mf = 0; mf < 4; mf++) {
                    mma16816(acc[mf][nfp*2],   ah[mf], bh);
                    mma16816(acc[mf][nfp*2+1], ah[mf], bh + 2);
                }
#pragma unroll
                for (int mf = 0; mf < 4; mf++) {
                    mma16816(acc[mf][nfp*2],   ah[mf], bl);
                    mma16816(acc[mf][nfp*2+1], ah[mf], bl + 2);
                }
#pragma unroll
                for (int mf = 0; mf < 4; mf++) {
                    mma16816(acc[mf][nfp*2],   al[mf], bh);
                    mma16816(acc[mf][nfp*2+1], al[mf], bh + 2);
                }
            }
        }
        __syncthreads();
        if (c < 30) { issue(c + 2, c & 1); CPA_COMMIT(); }
    }

    __nv_bfloat16* OH = DO_COS ? OHB + (size_t)z * Mm * Ee : nullptr;
    __nv_bfloat16* OL = DO_COS ? OLB + (size_t)z * Mm * Ee : nullptr;
    float osc = (DO_COS && z == 0) ? QSCALE : 1.0f;   // pre-scale Q for softmax
#pragma unroll
    for (int mf = 0; mf < 4; mf++) {
#pragma unroll
        for (int nf = 0; nf < 4; nf++) {
            int r = m0 + wm * 64 + mf * 16 + g;
            int cb = n0 + wn * 32 + nf * 8 + 2 * t;
            float v0 = acc[mf][nf][0], v1 = acc[mf][nf][1];
            float v2 = acc[mf][nf][2], v3 = acc[mf][nf][3];
            if (DO_COS) {
                float t0 = theta[cb & 63], t1 = theta[(cb + 1) & 63];
                v0 = __cosf(v0 + t0) * osc; v1 = __cosf(v1 + t1) * osc;
                v2 = __cosf(v2 + t0) * osc; v3 = __cosf(v3 + t1) * osc;
                uint32_t h0 = pack_hi(v0, v1), h1 = pack_hi(v2, v3);
                *(uint32_t*)&OH[(size_t)r * Ee + cb]       = h0;
                *(uint32_t*)&OH[(size_t)(r + 8) * Ee + cb] = h1;
                *(uint32_t*)&OL[(size_t)r * Ee + cb]       = pack_lo(v0, v1, h0);
                *(uint32_t*)&OL[(size_t)(r + 8) * Ee + cb] = pack_lo(v2, v3, h1);
            } else {
                *(float2*)&C[(size_t)r * Ee + cb]       = float2{v0, v1};
                *(float2*)&C[(size_t)(r + 8) * Ee + cb] = float2{v2, v3};
            }
        }
    }
}

// ------------------------- HMMA flash attention (unchanged from R13) ---------
#define PKV 72
#define KVB (64 * PKV * 2)               /* 9216 */
#define STAGEB (KVB * 2)                 /* 18432 */
#define ATT_SMEM (STAGEB * 3)            /* 55296 */

__global__ __launch_bounds__(256, 2) void attn_mma(
    const __nv_bfloat16* __restrict__ qhi,
    const __nv_bfloat16* __restrict__ khi,
    const __nv_bfloat16* __restrict__ vhi,
    __nv_bfloat16* __restrict__ chi, __nv_bfloat16* __restrict__ clo)
{
    extern __shared__ __align__(16) char smem[];
    uint32_t sb = smem_u32(smem);

    int tid = threadIdx.x, wid = tid >> 5, lane = tid & 31;
    int g = lane >> 2, t = lane & 3;
    int lm = lane >> 3, li = lane & 7;
    int bh_ = blockIdx.y;
    int b = bh_ >> 4, h = bh_ & 15;
    int q0 = blockIdx.x * 128;
    size_t base = (size_t)b * Ss * Ee + (size_t)h * Dk;

    uint32_t qh[4][4];
    {
        size_t r0 = base + (size_t)(q0 + wid * 16 + g) * Ee;
        size_t r1 = r0 + 8 * (size_t)Ee;
#pragma unroll
        for (int ks = 0; ks < 4; ks++) {
            int c0 = ks * 16 + 2 * t;
            qh[ks][0] = *(const uint32_t*)&qhi[r0 + c0];
            qh[ks][1] = *(const uint32_t*)&qhi[r1 + c0];
            qh[ks][2] = *(const uint32_t*)&qhi[r0 + c0 + 8];
            qh[ks][3] = *(const uint32_t*)&qhi[r1 + c0 + 8];
        }
    }

    auto issue = [&](int j0, int s) {
        uint32_t b0 = sb + s * STAGEB;
#pragma unroll
        for (int u = 0; u < 2; u++) {
            int unit = tid + u * 256;
            int row = unit >> 3, seg = unit & 7;
            size_t gk = base + (size_t)(j0 + row) * Ee + seg * 8;
            uint32_t so = (uint32_t)(row * PKV + seg * 8) * 2;
            cpa16(b0 + so,       khi + gk);
            cpa16(b0 + KVB + so, vhi + gk);
        }
    };

    float l0 = 0.0f, l1 = 0.0f;
    float out[8][4] = {};

    issue(0, 0);  CPA_COMMIT();
    issue(64, 1); CPA_COMMIT();

    for (int tile = 0; tile < 32; tile++) {
        if (tile == 31) CPA_WAIT0(); else CPA_WAIT1();
        __syncthreads();
        if (tile < 30) { issue((tile + 2) * 64, (tile + 2) % 3); CPA_COMMIT(); }

        uint32_t kb = sb + (tile % 3) * STAGEB;
        uint32_t vb = kb + KVB;

        float s[8][4] = {};
#pragma unroll
        for (int ks = 0; ks < 4; ks++) {
#pragma unroll
            for (int nfp = 0; nfp < 4; nfp++) {
                uint32_t ad = kb +
                    (uint32_t)(((nfp * 2 + (lm >> 1)) * 8 + li) * PKV
                               + ks * 16 + (lm & 1) * 8) * 2;
                uint32_t bhv[4];
                ldsm_x4(bhv, ad);
                mma16816(s[nfp*2],   qh[ks], bhv);
                mma16816(s[nfp*2+1], qh[ks], bhv + 2);
            }
        }

#pragma unroll
        for (int nf = 0; nf < 8; nf++) {
            s[nf][0] = ex2(s[nf][0]);
            s[nf][1] = ex2(s[nf][1]);
            s[nf][2] = ex2(s[nf][2]);
            s[nf][3] = ex2(s[nf][3]);
            l0 += s[nf][0] + s[nf][1];
            l1 += s[nf][2] + s[nf][3];
        }

        uint32_t pa[4][4];
#pragma unroll
        for (int k2 = 0; k2 < 4; k2++) {
            pa[k2][0] = pack_hi(s[2*k2][0],   s[2*k2][1]);
            pa[k2][1] = pack_hi(s[2*k2][2],   s[2*k2][3]);
            pa[k2][2] = pack_hi(s[2*k2+1][0], s[2*k2+1][1]);
            pa[k2][3] = pack_hi(s[2*k2+1][2], s[2*k2+1][3]);
        }

#pragma unroll
        for (int ks2 = 0; ks2 < 4; ks2++) {
#pragma unroll
            for (int nfp = 0; nfp < 4; nfp++) {
                uint32_t ad = vb +
                    (uint32_t)((ks2 * 16 + (lm & 1) * 8 + li) * PKV
                               + (nfp * 2 + (lm >> 1)) * 8) * 2;
                uint32_t bvh[4];
                ldsm_x4_t(bvh, ad);
                mma16816(out[nfp*2],   pa[ks2], bvh);
                mma16816(out[nfp*2+1], pa[ks2], bvh + 2);
            }
        }
    }

    l0 += __shfl_xor_sync(0xffffffffu, l0, 1);
    l0 += __shfl_xor_sync(0xffffffffu, l0, 2);
    l1 += __shfl_xor_sync(0xffffffffu, l1, 1);
    l1 += __shfl_xor_sync(0xffffffffu, l1, 2);

    float inv0 = 1.0f / l0, inv1 = 1.0f / l1;
    size_t r0 = base + (size_t)(q0 + wid * 16 + g) * Ee;
    size_t r1 = r0 + 8 * (size_t)Ee;
#pragma unroll
    for (int nfo = 0; nfo < 8; nfo++) {
        int d = nfo * 8 + 2 * t;
        float v0 = out[nfo][0] * inv0, v1 = out[nfo][1] * inv0;
        float v2 = out[nfo][2] * inv1, v3 = out[nfo][3] * inv1;
        uint32_t h0 = pack_hi(v0, v1), h1 = pack_hi(v2, v3);
        *(uint32_t*)&chi[r0 + d] = h0;
        *(uint32_t*)&chi[r1 + d] = h1;
        *(uint32_t*)&clo[r0 + d] = pack_lo(v0, v1, h0);
        *(uint32_t*)&clo[r1 + d] = pack_lo(v2, v3, h1);
    }
}

// ---------------------------------------------------------------------------
extern "C" void kernel_launch(void* const* d_in, const int* in_sizes, int n_in,
                              void* d_out, int out_size)
{
    const float* x     = (const float*)d_in[0];
    const float* Wq    = (const float*)d_in[1];
    const float* Wk    = (const float*)d_in[2];
    const float* Wv    = (const float*)d_in[3];
    const float* Wo    = (const float*)d_in[4];
    const float* theta = (const float*)d_in[5];
    float* out = (float*)d_out;

    __nv_bfloat16 *xhi, *xlo, *qkvhi, *qkvlo, *chi, *clo, *whi, *wlo;
    cudaGetSymbolAddress((void**)&xhi, g_xhi);
    cudaGetSymbolAddress((void**)&xlo, g_xlo);
    cudaGetSymbolAddress((void**)&qkvhi, g_qkvhi);
    cudaGetSymbolAddress((void**)&qkvlo, g_qkvlo);
    cudaGetSymbolAddress((void**)&chi, g_chi);
    cudaGetSymbolAddress((void**)&clo, g_clo);
    cudaGetSymbolAddress((void**)&whi, g_whi);
    cudaGetSymbolAddress((void**)&wlo, g_wlo);

    cudaFuncSetAttribute(hmma_gemm<true>,
        cudaFuncAttributeMaxDynamicSharedMemorySize, GEMM_SMEM);
    cudaFuncSetAttribute(hmma_gemm<false>,
        cudaFuncAttributeMaxDynamicSharedMemorySize, GEMM_SMEM);
    cudaFuncSetAttribute(attn_mma,
        cudaFuncAttributeMaxDynamicSharedMemorySize, ATT_SMEM);

    int n4x = Mm * Ee / 4;
    int n4w = Ee * Ee / 4;
    split_kernel<<<(n4x + 255) / 256, 256>>>((const float4*)x, xhi, xlo, n4x);
    dim3 gw((n4w + 255) / 256, 4);
    split4_kernel<<<gw, 256>>>((const float4*)Wq, (const float4*)Wk,
                               (const float4*)Wv, (const float4*)Wo,
                               whi, wlo, n4w);

    dim3 g1(Ee / 128, Mm / 128, 3);   // 1536 CTAs, 2/SM
    hmma_gemm<true><<<g1, 256, GEMM_SMEM>>>(xhi, xlo, whi, wlo, theta,
                                            nullptr, qkvhi, qkvlo);

    size_t off = (size_t)Mm * Ee;
    dim3 g2(Ss / 128, Bb * Hh);
    attn_mma<<<g2, 256, ATT_SMEM>>>(qkvhi,
                                    qkvhi + off,
                                    qkvhi + 2*off,
                                    chi, clo);

    dim3 g3(Ee / 128, Mm / 128, 1);
    hmma_gemm<false><<<g3, 256, GEMM_SMEM>>>(chi, clo,
        whi + 3*(size_t)Ee*Ee, wlo + 3*(size_t)Ee*Ee, nullptr, out,
        nullptr, nullptr);
}

// round 15
// speedup vs baseline: 2.0287x; 1.1696x over previous
#include <cuda_runtime.h>
#include <cuda_bf16.h>
#include <math.h>
#include <stdint.h>

#define Bb 4
#define Ss 2048
#define Ee 1024
#define Hh 16
#define Dk 64
#define Mm (Bb*Ss)   /* 8192 */

#define QSCALE 0.1803368801111204f   /* 0.125 * log2(e) */

// ------------------------- device scratch (no allocs) ----------------------
__device__ __nv_bfloat16 g_xhi[Mm*Ee];
__device__ __nv_bfloat16 g_xlo[Mm*Ee];
__device__ __nv_bfloat16 g_qkvhi[3*Mm*Ee];   // q(scaled) | k | v
__device__ __nv_bfloat16 g_qkvlo[3*Mm*Ee];
__device__ __nv_bfloat16 g_chi[Mm*Ee];
__device__ __nv_bfloat16 g_clo[Mm*Ee];
__device__ __nv_bfloat16 g_whi[4*Ee*Ee];
__device__ __nv_bfloat16 g_wlo[4*Ee*Ee];

// ------------------------- helpers ------------------------------------------
__device__ __forceinline__ void mma16816(float* d, const uint32_t* a,
                                         const uint32_t* b)
{
    asm volatile(
        "mma.sync.aligned.m16n8k16.row.col.f32.bf16.bf16.f32 "
        "{%0,%1,%2,%3}, {%4,%5,%6,%7}, {%8,%9}, {%0,%1,%2,%3};"
        : "+f"(d[0]), "+f"(d[1]), "+f"(d[2]), "+f"(d[3])
        : "r"(a[0]), "r"(a[1]), "r"(a[2]), "r"(a[3]), "r"(b[0]), "r"(b[1]));
}
__device__ __forceinline__ void ldsm_x4(uint32_t* r, uint32_t addr) {
    asm volatile("ldmatrix.sync.aligned.m8n8.x4.shared.b16 {%0,%1,%2,%3}, [%4];"
        : "=r"(r[0]), "=r"(r[1]), "=r"(r[2]), "=r"(r[3]) : "r"(addr));
}
__device__ __forceinline__ void ldsm_x4_t(uint32_t* r, uint32_t addr) {
    asm volatile("ldmatrix.sync.aligned.m8n8.x4.trans.shared.b16 {%0,%1,%2,%3}, [%4];"
        : "=r"(r[0]), "=r"(r[1]), "=r"(r[2]), "=r"(r[3]) : "r"(addr));
}
__device__ __forceinline__ uint32_t smem_u32(const void* p) {
    uint32_t a;
    asm("{ .reg .u64 t; cvta.to.shared.u64 t, %1; cvt.u32.u64 %0, t; }"
        : "=r"(a) : "l"(p));
    return a;
}
__device__ __forceinline__ void cpa16(uint32_t s, const void* g) {
    asm volatile("cp.async.cg.shared.global [%0], [%1], 16;" :: "r"(s), "l"(g));
}
#define CPA_COMMIT() asm volatile("cp.async.commit_group;" ::: "memory")
#define CPA_WAIT1()  asm volatile("cp.async.wait_group 1;" ::: "memory")
#define CPA_WAIT0()  asm volatile("cp.async.wait_group 0;" ::: "memory")

__device__ __forceinline__ float ex2(float x) {
    float r;
    asm("ex2.approx.f32 %0, %1;" : "=f"(r) : "f"(x));
    return r;
}
__device__ __forceinline__ uint32_t pack_hi(float x, float y) {
    __nv_bfloat162 h = __floats2bfloat162_rn(x, y);
    return *(uint32_t*)&h;
}
__device__ __forceinline__ uint32_t pack_lo(float x, float y, uint32_t hiu) {
    __nv_bfloat162 h = *(__nv_bfloat162*)&hiu;
    __nv_bfloat162 l = __floats2bfloat162_rn(x - __bfloat162float(h.x),
                                             y - __bfloat162float(h.y));
    return *(uint32_t*)&l;
}

// ------------------------- fp32 -> bf16 hi/lo splits -------------------------
__global__ __launch_bounds__(256) void split_kernel(const float4* __restrict__ src,
                                                    __nv_bfloat16* __restrict__ hi,
                                                    __nv_bfloat16* __restrict__ lo,
                                                    int n4)
{
    int i = blockIdx.x * 256 + threadIdx.x;
    if (i >= n4) return;
    float4 v = src[i];
    uint32_t h0 = pack_hi(v.x, v.y), h1 = pack_hi(v.z, v.w);
    uint32_t l0 = pack_lo(v.x, v.y, h0), l1 = pack_lo(v.z, v.w, h1);
    uint32_t* hp = (uint32_t*)(hi + (size_t)i * 4);
    uint32_t* lp = (uint32_t*)(lo + (size_t)i * 4);
    hp[0] = h0; hp[1] = h1; lp[0] = l0; lp[1] = l1;
}

__global__ __launch_bounds__(256) void split4_kernel(
    const float4* __restrict__ s0, const float4* __restrict__ s1,
    const float4* __restrict__ s2, const float4* __restrict__ s3,
    __nv_bfloat16* __restrict__ hi, __nv_bfloat16* __restrict__ lo, int n4)
{
    int z = blockIdx.y;
    const float4* src = (z == 0) ? s0 : (z == 1) ? s1 : (z == 2) ? s2 : s3;
    int i = blockIdx.x * 256 + threadIdx.x;
    if (i >= n4) return;
    float4 v = src[i];
    uint32_t h0 = pack_hi(v.x, v.y), h1 = pack_hi(v.z, v.w);
    uint32_t l0 = pack_lo(v.x, v.y, h0), l1 = pack_lo(v.z, v.w, h1);
    size_t off = (size_t)z * Ee * Ee + (size_t)i * 4;
    uint32_t* hp = (uint32_t*)(hi + off);
    uint32_t* lp = (uint32_t*)(lo + off);
    hp[0] = h0; hp[1] = h1; lp[0] = l0; lp[1] = l1;
}

// ------------------------- HMMA split-bf16 GEMM ------------------------------
// 128x128 CTA tile, 256 threads (8 warps, warp tile 64x32), K-chunk 32,
// pitch 40, 2 stages, 2 CTAs/SM.
// DO_COS (QKV): 2-term (A_hi*W_hi + A_hi*W_lo) — A_lo term dropped & not loaded.
// !DO_COS (Wo): full 3-term.
#define PG 40
#define GT_B (128 * PG * 2)               /* 10240 per array */
#define GSTAGE (GT_B * 4)                 /* 40960 */
#define GEMM_SMEM (GSTAGE * 2)            /* 81920 -> 2 CTAs/SM */

template<bool DO_COS>
__global__ __launch_bounds__(256, 2) void hmma_gemm(
    const __nv_bfloat16* __restrict__ Ahi, const __nv_bfloat16* __restrict__ Alo,
    const __nv_bfloat16* __restrict__ WhiB, const __nv_bfloat16* __restrict__ WloB,
    const float* __restrict__ theta,
    float* __restrict__ C,
    __nv_bfloat16* __restrict__ OHB, __nv_bfloat16* __restrict__ OLB)
{
    extern __shared__ __align__(16) char smem[];
    uint32_t sb = smem_u32(smem);

    int z = blockIdx.z;
    const __nv_bfloat16* Whi = WhiB + (size_t)z * Ee * Ee;
    const __nv_bfloat16* Wlo = WloB + (size_t)z * Ee * Ee;

    int tid = threadIdx.x, wid = tid >> 5, lane = tid & 31;
    int wm = wid & 1, wn = wid >> 1;          // 2 x 4 warp grid, tiles 64x32
    int g = lane >> 2, t = lane & 3;
    int lm = lane >> 3, li = lane & 7;
    int m0 = blockIdx.y * 128, n0 = blockIdx.x * 128;

    float acc[4][4][4] = {};

    auto issue = [&](int c, int bs) {
        uint32_t b0 = sb + bs * GSTAGE;
#pragma unroll
        for (int u = 0; u < 2; u++) {
            int unit = tid + u * 256;
            int row = unit >> 2, seg = unit & 3;
            size_t gA = (size_t)(m0 + row) * Ee + c * 32 + seg * 8;
            size_t gW = (size_t)(n0 + row) * Ee + c * 32 + seg * 8;
            uint32_t so = (uint32_t)(row * PG + seg * 8) * 2;
            cpa16(b0 + so,            Ahi + gA);
            if (!DO_COS) cpa16(b0 + GT_B + so, Alo + gA);
            cpa16(b0 + 2 * GT_B + so, Whi + gW);
            cpa16(b0 + 3 * GT_B + so, Wlo + gW);
        }
    };

    issue(0, 0); CPA_COMMIT();
    issue(1, 1); CPA_COMMIT();

    for (int c = 0; c < 32; c++) {
        if (c == 31) CPA_WAIT0(); else CPA_WAIT1();
        __syncthreads();

        uint32_t bufA = sb + (c & 1) * GSTAGE;
        uint32_t bufW = bufA + 2 * GT_B;

#pragma unroll
        for (int ks = 0; ks < 2; ks++) {
            uint32_t ah[4][4], al[4][4];
#pragma unroll
            for (int mf = 0; mf < 4; mf++) {
                uint32_t ad = bufA +
                    (uint32_t)(((wm * 64 + mf * 16 + (lm & 1) * 8 + li) * PG)
                               + ks * 16 + (lm >> 1) * 8) * 2;
                ldsm_x4(ah[mf], ad);
                if (!DO_COS) ldsm_x4(al[mf], ad + GT_B);
            }
#pragma unroll
            for (int nfp = 0; nfp < 2; nfp++) {
                uint32_t bd = bufW +
                    (uint32_t)(((wn * 32 + (nfp * 2 + (lm >> 1)) * 8 + li) * PG)
                               + ks * 16 + (lm & 1) * 8) * 2;
                uint32_t bh[4], bl[4];
                ldsm_x4(bh, bd);
                ldsm_x4(bl, bd + GT_B);
#pragma unroll
                for (int mf = 0; mf < 4; mf++) {
                    mma16816(acc[mf][nfp*2],   ah[mf], bh);
                    mma16816(acc[mf][nfp*2+1], ah[mf], bh + 2);
                }
#pragma unroll
                for (int mf = 0; mf < 4; mf++) {
                    mma16816(acc[mf][nfp*2],   ah[mf], bl);
                    mma16816(acc[mf][nfp*2+1], ah[mf], bl + 2);
                }
                if (!DO_COS) {
#pragma unroll
                    for (int mf = 0; mf < 4; mf++) {
                        mma16816(acc[mf][nfp*2],   al[mf], bh);
                        mma16816(acc[mf][nfp*2+1], al[mf], bh + 2);
                    }
                }
            }
        }
        __syncthreads();
        if (c < 30) { issue(c + 2, c & 1); CPA_COMMIT(); }
    }

    __nv_bfloat16* OH = DO_COS ? OHB + (size_t)z * Mm * Ee : nullptr;
    __nv_bfloat16* OL = DO_COS ? OLB + (size_t)z * Mm * Ee : nullptr;
    float osc = (DO_COS && z == 0) ? QSCALE : 1.0f;   // pre-scale Q for softmax
#pragma unroll
    for (int mf = 0; mf < 4; mf++) {
#pragma unroll
        for (int nf = 0; nf < 4; nf++) {
            int r = m0 + wm * 64 + mf * 16 + g;
            int cb = n0 + wn * 32 + nf * 8 + 2 * t;
            float v0 = acc[mf][nf][0], v1 = acc[mf][nf][1];
            float v2 = acc[mf][nf][2], v3 = acc[mf][nf][3];
            if (DO_COS) {
                float t0 = theta[cb & 63], t1 = theta[(cb + 1) & 63];
                v0 = __cosf(v0 + t0) * osc; v1 = __cosf(v1 + t1) * osc;
                v2 = __cosf(v2 + t0) * osc; v3 = __cosf(v3 + t1) * osc;
                uint32_t h0 = pack_hi(v0, v1), h1 = pack_hi(v2, v3);
                *(uint32_t*)&OH[(size_t)r * Ee + cb]       = h0;
                *(uint32_t*)&OH[(size_t)(r + 8) * Ee + cb] = h1;
                *(uint32_t*)&OL[(size_t)r * Ee + cb]       = pack_lo(v0, v1, h0);
                *(uint32_t*)&OL[(size_t)(r + 8) * Ee + cb] = pack_lo(v2, v3, h1);
            } else {
                *(float2*)&C[(size_t)r * Ee + cb]       = float2{v0, v1};
                *(float2*)&C[(size_t)(r + 8) * Ee + cb] = float2{v2, v3};
            }
        }
    }
}

// ------------------------- HMMA flash attention (unchanged from R13) ---------
#define PKV 72
#define KVB (64 * PKV * 2)               /* 9216 */
#define STAGEB (KVB * 2)                 /* 18432 */
#define ATT_SMEM (STAGEB * 3)            /* 55296 */

__global__ __launch_bounds__(256, 2) void attn_mma(
    const __nv_bfloat16* __restrict__ qhi,
    const __nv_bfloat16* __restrict__ khi,
    const __nv_bfloat16* __restrict__ vhi,
    __nv_bfloat16* __restrict__ chi, __nv_bfloat16* __restrict__ clo)
{
    extern __shared__ __align__(16) char smem[];
    uint32_t sb = smem_u32(smem);

    int tid = threadIdx.x, wid = tid >> 5, lane = tid & 31;
    int g = lane >> 2, t = lane & 3;
    int lm = lane >> 3, li = lane & 7;
    int bh_ = blockIdx.y;
    int b = bh_ >> 4, h = bh_ & 15;
    int q0 = blockIdx.x * 128;
    size_t base = (size_t)b * Ss * Ee + (size_t)h * Dk;

    uint32_t qh[4][4];
    {
        size_t r0 = base + (size_t)(q0 + wid * 16 + g) * Ee;
        size_t r1 = r0 + 8 * (size_t)Ee;
#pragma unroll
        for (int ks = 0; ks < 4; ks++) {
            int c0 = ks * 16 + 2 * t;
            qh[ks][0] = *(const uint32_t*)&qhi[r0 + c0];
            qh[ks][1] = *(const uint32_t*)&qhi[r1 + c0];
            qh[ks][2] = *(const uint32_t*)&qhi[r0 + c0 + 8];
            qh[ks][3] = *(const uint32_t*)&qhi[r1 + c0 + 8];
        }
    }

    auto issue = [&](int j0, int s) {
        uint32_t b0 = sb + s * STAGEB;
#pragma unroll
        for (int u = 0; u < 2; u++) {
            int unit = tid + u * 256;
            int row = unit >> 3, seg = unit & 7;
            size_t gk = base + (size_t)(j0 + row) * Ee + seg * 8;
            uint32_t so = (uint32_t)(row * PKV + seg * 8) * 2;
            cpa16(b0 + so,       khi + gk);
            cpa16(b0 + KVB + so, vhi + gk);
        }
    };

    float l0 = 0.0f, l1 = 0.0f;
    float out[8][4] = {};

    issue(0, 0);  CPA_COMMIT();
    issue(64, 1); CPA_COMMIT();

    for (int tile = 0; tile < 32; tile++) {
        if (tile == 31) CPA_WAIT0(); else CPA_WAIT1();
        __syncthreads();
        if (tile < 30) { issue((tile + 2) * 64, (tile + 2) % 3); CPA_COMMIT(); }

        uint32_t kb = sb + (tile % 3) * STAGEB;
        uint32_t vb = kb + KVB;

        float s[8][4] = {};
#pragma unroll
        for (int ks = 0; ks < 4; ks++) {
#pragma unroll
            for (int nfp = 0; nfp < 4; nfp++) {
                uint32_t ad = kb +
                    (uint32_t)(((nfp * 2 + (lm >> 1)) * 8 + li) * PKV
                               + ks * 16 + (lm & 1) * 8) * 2;
                uint32_t bhv[4];
                ldsm_x4(bhv, ad);
                mma16816(s[nfp*2],   qh[ks], bhv);
                mma16816(s[nfp*2+1], qh[ks], bhv + 2);
            }
        }

#pragma unroll
        for (int nf = 0; nf < 8; nf++) {
            s[nf][0] = ex2(s[nf][0]);
            s[nf][1] = ex2(s[nf][1]);
            s[nf][2] = ex2(s[nf][2]);
            s[nf][3] = ex2(s[nf][3]);
            l0 += s[nf][0] + s[nf][1];
            l1 += s[nf][2] + s[nf][3];
        }

        uint32_t pa[4][4];
#pragma unroll
        for (int k2 = 0; k2 < 4; k2++) {
            pa[k2][0] = pack_hi(s[2*k2][0],   s[2*k2][1]);
            pa[k2][1] = pack_hi(s[2*k2][2],   s[2*k2][3]);
            pa[k2][2] = pack_hi(s[2*k2+1][0], s[2*k2+1][1]);
            pa[k2][3] = pack_hi(s[2*k2+1][2], s[2*k2+1][3]);
        }

#pragma unroll
        for (int ks2 = 0; ks2 < 4; ks2++) {
#pragma unroll
            for (int nfp = 0; nfp < 4; nfp++) {
                uint32_t ad = vb +
                    (uint32_t)((ks2 * 16 + (lm & 1) * 8 + li) * PKV
                               + (nfp * 2 + (lm >> 1)) * 8) * 2;
                uint32_t bvh[4];
                ldsm_x4_t(bvh, ad);
                mma16816(out[nfp*2],   pa[ks2], bvh);
                mma16816(out[nfp*2+1], pa[ks2], bvh + 2);
            }
        }
    }

    l0 += __shfl_xor_sync(0xffffffffu, l0, 1);
    l0 += __shfl_xor_sync(0xffffffffu, l0, 2);
    l1 += __shfl_xor_sync(0xffffffffu, l1, 1);
    l1 += __shfl_xor_sync(0xffffffffu, l1, 2);

    float inv0 = 1.0f / l0, inv1 = 1.0f / l1;
    size_t r0 = base + (size_t)(q0 + wid * 16 + g) * Ee;
    size_t r1 = r0 + 8 * (size_t)Ee;
#pragma unroll
    for (int nfo = 0; nfo < 8; nfo++) {
        int d = nfo * 8 + 2 * t;
        float v0 = out[nfo][0] * inv0, v1 = out[nfo][1] * inv0;
        float v2 = out[nfo][2] * inv1, v3 = out[nfo][3] * inv1;
        uint32_t h0 = pack_hi(v0, v1), h1 = pack_hi(v2, v3);
        *(uint32_t*)&chi[r0 + d] = h0;
        *(uint32_t*)&chi[r1 + d] = h1;
        *(uint32_t*)&clo[r0 + d] = pack_lo(v0, v1, h0);
        *(uint32_t*)&clo[r1 + d] = pack_lo(v2, v3, h1);
    }
}

// ---------------------------------------------------------------------------
extern "C" void kernel_launch(void* const* d_in, const int* in_sizes, int n_in,
                              void* d_out, int out_size)
{
    const float* x     = (const float*)d_in[0];
    const float* Wq    = (const float*)d_in[1];
    const float* Wk    = (const float*)d_in[2];
    const float* Wv    = (const float*)d_in[3];
    const float* Wo    = (const float*)d_in[4];
    const float* theta = (const float*)d_in[5];
    float* out = (float*)d_out;

    __nv_bfloat16 *xhi, *xlo, *qkvhi, *qkvlo, *chi, *clo, *whi, *wlo;
    cudaGetSymbolAddress((void**)&xhi, g_xhi);
    cudaGetSymbolAddress((void**)&xlo, g_xlo);
    cudaGetSymbolAddress((void**)&qkvhi, g_qkvhi);
    cudaGetSymbolAddress((void**)&qkvlo, g_qkvlo);
    cudaGetSymbolAddress((void**)&chi, g_chi);
    cudaGetSymbolAddress((void**)&clo, g_clo);
    cudaGetSymbolAddress((void**)&whi, g_whi);
    cudaGetSymbolAddress((void**)&wlo, g_wlo);

    cudaFuncSetAttribute(hmma_gemm<true>,
        cudaFuncAttributeMaxDynamicSharedMemorySize, GEMM_SMEM);
    cudaFuncSetAttribute(hmma_gemm<false>,
        cudaFuncAttributeMaxDynamicSharedMemorySize, GEMM_SMEM);
    cudaFuncSetAttribute(attn_mma,
        cudaFuncAttributeMaxDynamicSharedMemorySize, ATT_SMEM);

    int n4x = Mm * Ee / 4;
    int n4w = Ee * Ee / 4;
    split_kernel<<<(n4x + 255) / 256, 256>>>((const float4*)x, xhi, xlo, n4x);
    dim3 gw((n4w + 255) / 256, 4);
    split4_kernel<<<gw, 256>>>((const float4*)Wq, (const float4*)Wk,
                               (const float4*)Wv, (const float4*)Wo,
                               whi, wlo, n4w);

    dim3 g1(Ee / 128, Mm / 128, 3);   // 1536 CTAs, 2/SM, 2-term QKV
    hmma_gemm<true><<<g1, 256, GEMM_SMEM>>>(xhi, xlo, whi, wlo, theta,
                                            nullptr, qkvhi, qkvlo);

    size_t off = (size_t)Mm * Ee;
    dim3 g2(Ss / 128, Bb * Hh);
    attn_mma<<<g2, 256, ATT_SMEM>>>(qkvhi,
                                    qkvhi + off,
                                    qkvhi + 2*off,
                                    chi, clo);

    dim3 g3(Ee / 128, Mm / 128, 1);   // Wo stays 3-term
    hmma_gemm<false><<<g3, 256, GEMM_SMEM>>>(chi, clo,
        whi + 3*(size_t)Ee*Ee, wlo + 3*(size_t)Ee*Ee, nullptr, out,
        nullptr, nullptr);
}

// round 16
// speedup vs baseline: 2.2371x; 1.1027x over previous
#include <cuda_runtime.h>
#include <cuda_bf16.h>
#include <math.h>
#include <stdint.h>

#define Bb 4
#define Ss 2048
#define Ee 1024
#define Hh 16
#define Dk 64
#define Mm (Bb*Ss)   /* 8192 */

#define QSCALE 0.1803368801111204f   /* 0.125 * log2(e) */

// ------------------------- device scratch (no allocs) ----------------------
__device__ __nv_bfloat16 g_xhi[Mm*Ee];
__device__ __nv_bfloat16 g_qkvhi[3*Mm*Ee];   // q(scaled) | k | v
__device__ float         g_ctx32[Mm*Ee];     // ctx, tf32-rounded fp32
__device__ __nv_bfloat16 g_whi[3*Ee*Ee];     // Wq,Wk,Wv hi
__device__ __nv_bfloat16 g_wlo[3*Ee*Ee];     // Wq,Wk,Wv lo
__device__ float         g_wo32[Ee*Ee];      // Wo, tf32-rounded fp32

// ------------------------- helpers ------------------------------------------
__device__ __forceinline__ void mma16816(float* d, const uint32_t* a,
                                         const uint32_t* b)
{
    asm volatile(
        "mma.sync.aligned.m16n8k16.row.col.f32.bf16.bf16.f32 "
        "{%0,%1,%2,%3}, {%4,%5,%6,%7}, {%8,%9}, {%0,%1,%2,%3};"
        : "+f"(d[0]), "+f"(d[1]), "+f"(d[2]), "+f"(d[3])
        : "r"(a[0]), "r"(a[1]), "r"(a[2]), "r"(a[3]), "r"(b[0]), "r"(b[1]));
}
__device__ __forceinline__ void mma1688_tf32(float* d, const uint32_t* a,
                                             const uint32_t* b)
{
    asm volatile(
        "mma.sync.aligned.m16n8k8.row.col.f32.tf32.tf32.f32 "
        "{%0,%1,%2,%3}, {%4,%5,%6,%7}, {%8,%9}, {%0,%1,%2,%3};"
        : "+f"(d[0]), "+f"(d[1]), "+f"(d[2]), "+f"(d[3])
        : "r"(a[0]), "r"(a[1]), "r"(a[2]), "r"(a[3]), "r"(b[0]), "r"(b[1]));
}
__device__ __forceinline__ void ldsm_x4(uint32_t* r, uint32_t addr) {
    asm volatile("ldmatrix.sync.aligned.m8n8.x4.shared.b16 {%0,%1,%2,%3}, [%4];"
        : "=r"(r[0]), "=r"(r[1]), "=r"(r[2]), "=r"(r[3]) : "r"(addr));
}
__device__ __forceinline__ void ldsm_x4_t(uint32_t* r, uint32_t addr) {
    asm volatile("ldmatrix.sync.aligned.m8n8.x4.trans.shared.b16 {%0,%1,%2,%3}, [%4];"
        : "=r"(r[0]), "=r"(r[1]), "=r"(r[2]), "=r"(r[3]) : "r"(addr));
}
__device__ __forceinline__ uint32_t smem_u32(const void* p) {
    uint32_t a;
    asm("{ .reg .u64 t; cvta.to.shared.u64 t, %1; cvt.u32.u64 %0, t; }"
        : "=r"(a) : "l"(p));
    return a;
}
__device__ __forceinline__ void cpa16(uint32_t s, const void* g) {
    asm volatile("cp.async.cg.shared.global [%0], [%1], 16;" :: "r"(s), "l"(g));
}
#define CPA_COMMIT() asm volatile("cp.async.commit_group;" ::: "memory")
#define CPA_WAIT1()  asm volatile("cp.async.wait_group 1;" ::: "memory")
#define CPA_WAIT0()  asm volatile("cp.async.wait_group 0;" ::: "memory")

__device__ __forceinline__ float ex2(float x) {
    float r;
    asm("ex2.approx.f32 %0, %1;" : "=f"(r) : "f"(x));
    return r;
}
__device__ __forceinline__ float tf32r(float x) {
    float r;
    asm("cvt.rna.tf32.f32 %0, %1;" : "=f"(r) : "f"(x));
    return r;
}
__device__ __forceinline__ uint32_t pack_hi(float x, float y) {
    __nv_bfloat162 h = __floats2bfloat162_rn(x, y);
    return *(uint32_t*)&h;
}
__device__ __forceinline__ uint32_t pack_lo(float x, float y, uint32_t hiu) {
    __nv_bfloat162 h = *(__nv_bfloat162*)&hiu;
    __nv_bfloat162 l = __floats2bfloat162_rn(x - __bfloat162float(h.x),
                                             y - __bfloat162float(h.y));
    return *(uint32_t*)&l;
}

// ------------------------- conversion kernels --------------------------------
// x -> bf16 hi only (lo unused by 2-term QKV)
__global__ __launch_bounds__(256) void split_hi_kernel(
    const float4* __restrict__ src, __nv_bfloat16* __restrict__ hi, int n4)
{
    int i = blockIdx.x * 256 + threadIdx.x;
    if (i >= n4) return;
    float4 v = src[i];
    uint32_t* hp = (uint32_t*)(hi + (size_t)i * 4);
    hp[0] = pack_hi(v.x, v.y); hp[1] = pack_hi(v.z, v.w);
}

// Wq/Wk/Wv -> bf16 hi/lo
__global__ __launch_bounds__(256) void split3_kernel(
    const float4* __restrict__ s0, const float4* __restrict__ s1,
    const float4* __restrict__ s2,
    __nv_bfloat16* __restrict__ hi, __nv_bfloat16* __restrict__ lo, int n4)
{
    int z = blockIdx.y;
    const float4* src = (z == 0) ? s0 : (z == 1) ? s1 : s2;
    int i = blockIdx.x * 256 + threadIdx.x;
    if (i >= n4) return;
    float4 v = src[i];
    uint32_t h0 = pack_hi(v.x, v.y), h1 = pack_hi(v.z, v.w);
    uint32_t l0 = pack_lo(v.x, v.y, h0), l1 = pack_lo(v.z, v.w, h1);
    size_t off = (size_t)z * Ee * Ee + (size_t)i * 4;
    uint32_t* hp = (uint32_t*)(hi + off);
    uint32_t* lp = (uint32_t*)(lo + off);
    hp[0] = h0; hp[1] = h1; lp[0] = l0; lp[1] = l1;
}

// Wo -> tf32-rounded fp32
__global__ __launch_bounds__(256) void cvt_tf32_kernel(
    const float4* __restrict__ src, float4* __restrict__ dst, int n4)
{
    int i = blockIdx.x * 256 + threadIdx.x;
    if (i >= n4) return;
    float4 v = src[i];
    dst[i] = float4{tf32r(v.x), tf32r(v.y), tf32r(v.z), tf32r(v.w)};
}

// ------------------------- QKV: HMMA 2-term bf16 GEMM ------------------------
// 128x128 CTA tile, 256 threads (8 warps, 64x32 warp tile), K-chunk 32,
// pitch 40 bf16, 2 stages, 2 CTAs/SM. C = cos(A_hi*(W_hi+W_lo) + theta).
#define PG 40
#define GT_B (128 * PG * 2)               /* 10240 per array */
#define GSTAGE (GT_B * 3)                 /* Ahi | Whi | Wlo = 30720 */
#define GEMM_SMEM (GSTAGE * 2)            /* 61440 -> 2 CTAs/SM */

__global__ __launch_bounds__(256, 2) void qkv_gemm(
    const __nv_bfloat16* __restrict__ Ahi,
    const __nv_bfloat16* __restrict__ WhiB, const __nv_bfloat16* __restrict__ WloB,
    const float* __restrict__ theta,
    __nv_bfloat16* __restrict__ OHB)
{
    extern __shared__ __align__(16) char smem[];
    uint32_t sb = smem_u32(smem);

    int z = blockIdx.z;
    const __nv_bfloat16* Whi = WhiB + (size_t)z * Ee * Ee;
    const __nv_bfloat16* Wlo = WloB + (size_t)z * Ee * Ee;

    int tid = threadIdx.x, wid = tid >> 5, lane = tid & 31;
    int wm = wid & 1, wn = wid >> 1;
    int g = lane >> 2, t = lane & 3;
    int lm = lane >> 3, li = lane & 7;
    int m0 = blockIdx.y * 128, n0 = blockIdx.x * 128;

    float acc[4][4][4] = {};

    auto issue = [&](int c, int bs) {
        uint32_t b0 = sb + bs * GSTAGE;
#pragma unroll
        for (int u = 0; u < 2; u++) {
            int unit = tid + u * 256;
            int row = unit >> 2, seg = unit & 3;
            size_t gA = (size_t)(m0 + row) * Ee + c * 32 + seg * 8;
            size_t gW = (size_t)(n0 + row) * Ee + c * 32 + seg * 8;
            uint32_t so = (uint32_t)(row * PG + seg * 8) * 2;
            cpa16(b0 + so,            Ahi + gA);
            cpa16(b0 + GT_B + so,     Whi + gW);
            cpa16(b0 + 2 * GT_B + so, Wlo + gW);
        }
    };

    issue(0, 0); CPA_COMMIT();
    issue(1, 1); CPA_COMMIT();

    for (int c = 0; c < 32; c++) {
        if (c == 31) CPA_WAIT0(); else CPA_WAIT1();
        __syncthreads();

        uint32_t bufA = sb + (c & 1) * GSTAGE;
        uint32_t bufW = bufA + GT_B;

#pragma unroll
        for (int ks = 0; ks < 2; ks++) {
            uint32_t ah[4][4];
#pragma unroll
            for (int mf = 0; mf < 4; mf++) {
                uint32_t ad = bufA +
                    (uint32_t)(((wm * 64 + mf * 16 + (lm & 1) * 8 + li) * PG)
                               + ks * 16 + (lm >> 1) * 8) * 2;
                ldsm_x4(ah[mf], ad);
            }
#pragma unroll
            for (int nfp = 0; nfp < 2; nfp++) {
                uint32_t bd = bufW +
                    (uint32_t)(((wn * 32 + (nfp * 2 + (lm >> 1)) * 8 + li) * PG)
                               + ks * 16 + (lm & 1) * 8) * 2;
                uint32_t bh[4], bl[4];
                ldsm_x4(bh, bd);
                ldsm_x4(bl, bd + GT_B);
#pragma unroll
                for (int mf = 0; mf < 4; mf++) {
                    mma16816(acc[mf][nfp*2],   ah[mf], bh);
                    mma16816(acc[mf][nfp*2+1], ah[mf], bh + 2);
                }
#pragma unroll
                for (int mf = 0; mf < 4; mf++) {
                    mma16816(acc[mf][nfp*2],   ah[mf], bl);
                    mma16816(acc[mf][nfp*2+1], ah[mf], bl + 2);
                }
            }
        }
        __syncthreads();
        if (c < 30) { issue(c + 2, c & 1); CPA_COMMIT(); }
    }

    __nv_bfloat16* OH = OHB + (size_t)z * Mm * Ee;
    float osc = (z == 0) ? QSCALE : 1.0f;   // pre-scale Q for softmax
#pragma unroll
    for (int mf = 0; mf < 4; mf++) {
#pragma unroll
        for (int nf = 0; nf < 4; nf++) {
            int r = m0 + wm * 64 + mf * 16 + g;
            int cb = n0 + wn * 32 + nf * 8 + 2 * t;
            float t0 = theta[cb & 63], t1 = theta[(cb + 1) & 63];
            float v0 = __cosf(acc[mf][nf][0] + t0) * osc;
            float v1 = __cosf(acc[mf][nf][1] + t1) * osc;
            float v2 = __cosf(acc[mf][nf][2] + t0) * osc;
            float v3 = __cosf(acc[mf][nf][3] + t1) * osc;
            *(uint32_t*)&OH[(size_t)r * Ee + cb]       = pack_hi(v0, v1);
            *(uint32_t*)&OH[(size_t)(r + 8) * Ee + cb] = pack_hi(v2, v3);
        }
    }
}

// ------------------------- Wo: TF32 1-term GEMM ------------------------------
// 128x128 CTA tile, 256 threads (8 warps, 64x32 warp tile), K-chunk 32,
// pitch 36 tf32 (144B rows), 2 stages, 2 CTAs/SM. out = ctx @ Wo^T.
#define PW 36
#define WT_B (128 * PW * 4)               /* 18432 per array */
#define WSTAGE (WT_B * 2)                 /* 36864 */
#define WO_SMEM (WSTAGE * 2)              /* 73728 -> 2 CTAs/SM */

__global__ __launch_bounds__(256, 2) void wo_gemm(
    const float* __restrict__ A,          // ctx, tf32-rounded fp32
    const float* __restrict__ W,          // Wo,  tf32-rounded fp32
    float* __restrict__ C)
{
    extern __shared__ __align__(16) char smem[];
    uint32_t sb = smem_u32(smem);

    int tid = threadIdx.x, wid = tid >> 5, lane = tid & 31;
    int wm = wid & 1, wn = wid >> 1;
    int g = lane >> 2, t = lane & 3;
    int lm = lane >> 3, li = lane & 7;
    int m0 = blockIdx.y * 128, n0 = blockIdx.x * 128;

    float acc[4][4][4] = {};

    auto issue = [&](int c, int bs) {
        uint32_t b0 = sb + bs * WSTAGE;
#pragma unroll
        for (int u = 0; u < 4; u++) {
            int unit = tid + u * 256;         // 0..1023
            int row = unit >> 3, seg = unit & 7;
            size_t gA = (size_t)(m0 + row) * Ee + c * 32 + seg * 4;
            size_t gW = (size_t)(n0 + row) * Ee + c * 32 + seg * 4;
            uint32_t so = (uint32_t)(row * PW + seg * 4) * 4;
            cpa16(b0 + so,        A + gA);
            cpa16(b0 + WT_B + so, W + gW);
        }
    };

    issue(0, 0); CPA_COMMIT();
    issue(1, 1); CPA_COMMIT();

    for (int c = 0; c < 32; c++) {
        if (c == 31) CPA_WAIT0(); else CPA_WAIT1();
        __syncthreads();

        uint32_t bufA = sb + (c & 1) * WSTAGE;
        uint32_t bufW = bufA + WT_B;

#pragma unroll
        for (int ks = 0; ks < 4; ks++) {      // 4 x k8 steps
            uint32_t av[4][4];
#pragma unroll
            for (int mf = 0; mf < 4; mf++) {
                uint32_t ad = bufA +
                    (uint32_t)((wm * 64 + mf * 16 + (lm & 1) * 8 + li) * PW) * 4
                    + ks * 32 + (lm >> 1) * 16;
                ldsm_x4(av[mf], ad);
            }
#pragma unroll
            for (int np = 0; np < 2; np++) {  // each covers 2 n-frags
                uint32_t bd = bufW +
                    (uint32_t)((wn * 32 + np * 16 + (lm >> 1) * 8 + li) * PW) * 4
                    + ks * 32 + (lm & 1) * 16;
                uint32_t bv[4];
                ldsm_x4(bv, bd);
#pragma unroll
                for (int mf = 0; mf < 4; mf++) {
                    mma1688_tf32(acc[mf][np*2],   av[mf], bv);
                    mma1688_tf32(acc[mf][np*2+1], av[mf], bv + 2);
                }
            }
        }
        __syncthreads();
        if (c < 30) { issue(c + 2, c & 1); CPA_COMMIT(); }
    }

#pragma unroll
    for (int mf = 0; mf < 4; mf++) {
#pragma unroll
        for (int nf = 0; nf < 4; nf++) {
            int r = m0 + wm * 64 + mf * 16 + g;
            int cb = n0 + wn * 32 + nf * 8 + 2 * t;
            *(float2*)&C[(size_t)r * Ee + cb] =
                float2{acc[mf][nf][0], acc[mf][nf][1]};
            *(float2*)&C[(size_t)(r + 8) * Ee + cb] =
                float2{acc[mf][nf][2], acc[mf][nf][3]};
        }
    }
}

// ------------------------- HMMA flash attention -------------------------------
// 1-term QK / 1-term PV, fixed-base softmax; ctx written as tf32 fp32.
#define PKV 72
#define KVB (64 * PKV * 2)               /* 9216 */
#define STAGEB (KVB * 2)                 /* 18432 */
#define ATT_SMEM (STAGEB * 3)            /* 55296 */

__global__ __launch_bounds__(256, 2) void attn_mma(
    const __nv_bfloat16* __restrict__ qhi,
    const __nv_bfloat16* __restrict__ khi,
    const __nv_bfloat16* __restrict__ vhi,
    float* __restrict__ ctx)
{
    extern __shared__ __align__(16) char smem[];
    uint32_t sb = smem_u32(smem);

    int tid = threadIdx.x, wid = tid >> 5, lane = tid & 31;
    int g = lane >> 2, t = lane & 3;
    int lm = lane >> 3, li = lane & 7;
    int bh_ = blockIdx.y;
    int b = bh_ >> 4, h = bh_ & 15;
    int q0 = blockIdx.x * 128;
    size_t base = (size_t)b * Ss * Ee + (size_t)h * Dk;

    uint32_t qh[4][4];
    {
        size_t r0 = base + (size_t)(q0 + wid * 16 + g) * Ee;
        size_t r1 = r0 + 8 * (size_t)Ee;
#pragma unroll
        for (int ks = 0; ks < 4; ks++) {
            int c0 = ks * 16 + 2 * t;
            qh[ks][0] = *(const uint32_t*)&qhi[r0 + c0];
            qh[ks][1] = *(const uint32_t*)&qhi[r1 + c0];
            qh[ks][2] = *(const uint32_t*)&qhi[r0 + c0 + 8];
            qh[ks][3] = *(const uint32_t*)&qhi[r1 + c0 + 8];
        }
    }

    auto issue = [&](int j0, int s) {
        uint32_t b0 = sb + s * STAGEB;
#pragma unroll
        for (int u = 0; u < 2; u++) {
            int unit = tid + u * 256;
            int row = unit >> 3, seg = unit & 7;
            size_t gk = base + (size_t)(j0 + row) * Ee + seg * 8;
            uint32_t so = (uint32_t)(row * PKV + seg * 8) * 2;
            cpa16(b0 + so,       khi + gk);
            cpa16(b0 + KVB + so, vhi + gk);
        }
    };

    float l0 = 0.0f, l1 = 0.0f;
    float out[8][4] = {};

    issue(0, 0);  CPA_COMMIT();
    issue(64, 1); CPA_COMMIT();

    for (int tile = 0; tile < 32; tile++) {
        if (tile == 31) CPA_WAIT0(); else CPA_WAIT1();
        __syncthreads();
        if (tile < 30) { issue((tile + 2) * 64, (tile + 2) % 3); CPA_COMMIT(); }

        uint32_t kb = sb + (tile % 3) * STAGEB;
        uint32_t vb = kb + KVB;

        float s[8][4] = {};
#pragma unroll
        for (int ks = 0; ks < 4; ks++) {
#pragma unroll
            for (int nfp = 0; nfp < 4; nfp++) {
                uint32_t ad = kb +
                    (uint32_t)(((nfp * 2 + (lm >> 1)) * 8 + li) * PKV
                               + ks * 16 + (lm & 1) * 8) * 2;
                uint32_t bhv[4];
                ldsm_x4(bhv, ad);
                mma16816(s[nfp*2],   qh[ks], bhv);
                mma16816(s[nfp*2+1], qh[ks], bhv + 2);
            }
        }

#pragma unroll
        for (int nf = 0; nf < 8; nf++) {
            s[nf][0] = ex2(s[nf][0]);
            s[nf][1] = ex2(s[nf][1]);
            s[nf][2] = ex2(s[nf][2]);
            s[nf][3] = ex2(s[nf][3]);
            l0 += s[nf][0] + s[nf][1];
            l1 += s[nf][2] + s[nf][3];
        }

        uint32_t pa[4][4];
#pragma unroll
        for (int k2 = 0; k2 < 4; k2++) {
            pa[k2][0] = pack_hi(s[2*k2][0],   s[2*k2][1]);
            pa[k2][1] = pack_hi(s[2*k2][2],   s[2*k2][3]);
            pa[k2][2] = pack_hi(s[2*k2+1][0], s[2*k2+1][1]);
            pa[k2][3] = pack_hi(s[2*k2+1][2], s[2*k2+1][3]);
        }

#pragma unroll
        for (int ks2 = 0; ks2 < 4; ks2++) {
#pragma unroll
            for (int nfp = 0; nfp < 4; nfp++) {
                uint32_t ad = vb +
                    (uint32_t)((ks2 * 16 + (lm & 1) * 8 + li) * PKV
                               + (nfp * 2 + (lm >> 1)) * 8) * 2;
                uint32_t bvh[4];
                ldsm_x4_t(bvh, ad);
                mma16816(out[nfp*2],   pa[ks2], bvh);
                mma16816(out[nfp*2+1], pa[ks2], bvh + 2);
            }
        }
    }

    l0 += __shfl_xor_sync(0xffffffffu, l0, 1);
    l0 += __shfl_xor_sync(0xffffffffu, l0, 2);
    l1 += __shfl_xor_sync(0xffffffffu, l1, 1);
    l1 += __shfl_xor_sync(0xffffffffu, l1, 2);

    float inv0 = 1.0f / l0, inv1 = 1.0f / l1;
    size_t r0 = base + (size_t)(q0 + wid * 16 + g) * Ee;
    size_t r1 = r0 + 8 * (size_t)Ee;
#pragma unroll
    for (int nfo = 0; nfo < 8; nfo++) {
        int d = nfo * 8 + 2 * t;
        *(float2*)&ctx[r0 + d] = float2{tf32r(out[nfo][0] * inv0),
                                        tf32r(out[nfo][1] * inv0)};
        *(float2*)&ctx[r1 + d] = float2{tf32r(out[nfo][2] * inv1),
                                        tf32r(out[nfo][3] * inv1)};
    }
}

// ---------------------------------------------------------------------------
extern "C" void kernel_launch(void* const* d_in, const int* in_sizes, int n_in,
                              void* d_out, int out_size)
{
    const float* x     = (const float*)d_in[0];
    const float* Wq    = (const float*)d_in[1];
    const float* Wk    = (const float*)d_in[2];
    const float* Wv    = (const float*)d_in[3];
    const float* Wo    = (const float*)d_in[4];
    const float* theta = (const float*)d_in[5];
    float* out = (float*)d_out;

    __nv_bfloat16 *xhi, *qkvhi, *whi, *wlo;
    float *ctx32, *wo32;
    cudaGetSymbolAddress((void**)&xhi, g_xhi);
    cudaGetSymbolAddress((void**)&qkvhi, g_qkvhi);
    cudaGetSymbolAddress((void**)&ctx32, g_ctx32);
    cudaGetSymbolAddress((void**)&whi, g_whi);
    cudaGetSymbolAddress((void**)&wlo, g_wlo);
    cudaGetSymbolAddress((void**)&wo32, g_wo32);

    cudaFuncSetAttribute(qkv_gemm,
        cudaFuncAttributeMaxDynamicSharedMemorySize, GEMM_SMEM);
    cudaFuncSetAttribute(wo_gemm,
        cudaFuncAttributeMaxDynamicSharedMemorySize, WO_SMEM);
    cudaFuncSetAttribute(attn_mma,
        cudaFuncAttributeMaxDynamicSharedMemorySize, ATT_SMEM);

    int n4x = Mm * Ee / 4;
    int n4w = Ee * Ee / 4;
    split_hi_kernel<<<(n4x + 255) / 256, 256>>>((const float4*)x, xhi, n4x);
    dim3 gw((n4w + 255) / 256, 3);
    split3_kernel<<<gw, 256>>>((const float4*)Wq, (const float4*)Wk,
                               (const float4*)Wv, whi, wlo, n4w);
    cvt_tf32_kernel<<<(n4w + 255) / 256, 256>>>((const float4*)Wo,
                                                (float4*)wo32, n4w);

    dim3 g1(Ee / 128, Mm / 128, 3);
    qkv_gemm<<<g1, 256, GEMM_SMEM>>>(xhi, whi, wlo, theta, qkvhi);

    size_t off = (size_t)Mm * Ee;
    dim3 g2(Ss / 128, Bb * Hh);
    attn_mma<<<g2, 256, ATT_SMEM>>>(qkvhi,
                                    qkvhi + off,
                                    qkvhi + 2*off,
                                    ctx32);

    dim3 g3(Ee / 128, Mm / 128);
    wo_gemm<<<g3, 256, WO_SMEM>>>(ctx32, wo32, out);
}

// round 17
// speedup vs baseline: 2.2656x; 1.0127x over previous
#include <cuda_runtime.h>
#include <cuda_bf16.h>
#include <math.h>
#include <stdint.h>

#define Bb 4
#define Ss 2048
#define Ee 1024
#define Hh 16
#define Dk 64
#define Mm (Bb*Ss)   /* 8192 */

#define QSCALE 0.1803368801111204f   /* 0.125 * log2(e) */

// ------------------------- device scratch (no allocs) ----------------------
__device__ __nv_bfloat16 g_xhi[Mm*Ee];
__device__ __nv_bfloat16 g_qkvhi[3*Mm*Ee];   // q(scaled) | k | v
__device__ float         g_ctx32[Mm*Ee];     // ctx, tf32-rounded fp32
__device__ __nv_bfloat16 g_whi[3*Ee*Ee];     // Wq,Wk,Wv hi
__device__ __nv_bfloat16 g_wlo[3*Ee*Ee];     // Wq,Wk,Wv lo
__device__ float         g_wo32[Ee*Ee];      // Wo, tf32-rounded fp32

// ------------------------- helpers ------------------------------------------
__device__ __forceinline__ void mma16816(float* d, const uint32_t* a,
                                         const uint32_t* b)
{
    asm volatile(
        "mma.sync.aligned.m16n8k16.row.col.f32.bf16.bf16.f32 "
        "{%0,%1,%2,%3}, {%4,%5,%6,%7}, {%8,%9}, {%0,%1,%2,%3};"
        : "+f"(d[0]), "+f"(d[1]), "+f"(d[2]), "+f"(d[3])
        : "r"(a[0]), "r"(a[1]), "r"(a[2]), "r"(a[3]), "r"(b[0]), "r"(b[1]));
}
__device__ __forceinline__ void mma1688_tf32(float* d, const uint32_t* a,
                                             const uint32_t* b)
{
    asm volatile(
        "mma.sync.aligned.m16n8k8.row.col.f32.tf32.tf32.f32 "
        "{%0,%1,%2,%3}, {%4,%5,%6,%7}, {%8,%9}, {%0,%1,%2,%3};"
        : "+f"(d[0]), "+f"(d[1]), "+f"(d[2]), "+f"(d[3])
        : "r"(a[0]), "r"(a[1]), "r"(a[2]), "r"(a[3]), "r"(b[0]), "r"(b[1]));
}
__device__ __forceinline__ void ldsm_x4(uint32_t* r, uint32_t addr) {
    asm volatile("ldmatrix.sync.aligned.m8n8.x4.shared.b16 {%0,%1,%2,%3}, [%4];"
        : "=r"(r[0]), "=r"(r[1]), "=r"(r[2]), "=r"(r[3]) : "r"(addr));
}
__device__ __forceinline__ void ldsm_x4_t(uint32_t* r, uint32_t addr) {
    asm volatile("ldmatrix.sync.aligned.m8n8.x4.trans.shared.b16 {%0,%1,%2,%3}, [%4];"
        : "=r"(r[0]), "=r"(r[1]), "=r"(r[2]), "=r"(r[3]) : "r"(addr));
}
__device__ __forceinline__ uint32_t smem_u32(const void* p) {
    uint32_t a;
    asm("{ .reg .u64 t; cvta.to.shared.u64 t, %1; cvt.u32.u64 %0, t; }"
        : "=r"(a) : "l"(p));
    return a;
}
__device__ __forceinline__ void cpa16(uint32_t s, const void* g) {
    asm volatile("cp.async.cg.shared.global [%0], [%1], 16;" :: "r"(s), "l"(g));
}
#define CPA_COMMIT() asm volatile("cp.async.commit_group;" ::: "memory")
#define CPA_WAIT1()  asm volatile("cp.async.wait_group 1;" ::: "memory")
#define CPA_WAIT0()  asm volatile("cp.async.wait_group 0;" ::: "memory")

__device__ __forceinline__ float ex2(float x) {
    float r;
    asm("ex2.approx.f32 %0, %1;" : "=f"(r) : "f"(x));
    return r;
}
__device__ __forceinline__ float tf32r(float x) {
    float r;
    asm("cvt.rna.tf32.f32 %0, %1;" : "=f"(r) : "f"(x));
    return r;
}
__device__ __forceinline__ uint32_t pack_hi(float x, float y) {
    __nv_bfloat162 h = __floats2bfloat162_rn(x, y);
    return *(uint32_t*)&h;
}
__device__ __forceinline__ uint32_t pack_lo(float x, float y, uint32_t hiu) {
    __nv_bfloat162 h = *(__nv_bfloat162*)&hiu;
    __nv_bfloat162 l = __floats2bfloat162_rn(x - __bfloat162float(h.x),
                                             y - __bfloat162float(h.y));
    return *(uint32_t*)&l;
}

// ------------------------- conversion kernels --------------------------------
__global__ __launch_bounds__(256) void split_hi_kernel(
    const float4* __restrict__ src, __nv_bfloat16* __restrict__ hi, int n4)
{
    int i = blockIdx.x * 256 + threadIdx.x;
    if (i >= n4) return;
    float4 v = src[i];
    uint32_t* hp = (uint32_t*)(hi + (size_t)i * 4);
    hp[0] = pack_hi(v.x, v.y); hp[1] = pack_hi(v.z, v.w);
}

__global__ __launch_bounds__(256) void split3_kernel(
    const float4* __restrict__ s0, const float4* __restrict__ s1,
    const float4* __restrict__ s2,
    __nv_bfloat16* __restrict__ hi, __nv_bfloat16* __restrict__ lo, int n4)
{
    int z = blockIdx.y;
    const float4* src = (z == 0) ? s0 : (z == 1) ? s1 : s2;
    int i = blockIdx.x * 256 + threadIdx.x;
    if (i >= n4) return;
    float4 v = src[i];
    uint32_t h0 = pack_hi(v.x, v.y), h1 = pack_hi(v.z, v.w);
    uint32_t l0 = pack_lo(v.x, v.y, h0), l1 = pack_lo(v.z, v.w, h1);
    size_t off = (size_t)z * Ee * Ee + (size_t)i * 4;
    uint32_t* hp = (uint32_t*)(hi + off);
    uint32_t* lp = (uint32_t*)(lo + off);
    hp[0] = h0; hp[1] = h1; lp[0] = l0; lp[1] = l1;
}

__global__ __launch_bounds__(256) void cvt_tf32_kernel(
    const float4* __restrict__ src, float4* __restrict__ dst, int n4)
{
    int i = blockIdx.x * 256 + threadIdx.x;
    if (i >= n4) return;
    float4 v = src[i];
    dst[i] = float4{tf32r(v.x), tf32r(v.y), tf32r(v.z), tf32r(v.w)};
}

// ------------------------- QKV: HMMA 2-term bf16 GEMM ------------------------
// 128x128 CTA tile, 8 warps (64x32 tile), K-chunk 32, pitch 40, 3-stage
// cp.async ring with ONE __syncthreads per chunk. 2 CTAs/SM.
#define PG 40
#define GT_B (128 * PG * 2)               /* 10240 per array */
#define GSTAGE (GT_B * 3)                 /* Ahi | Whi | Wlo = 30720 */
#define GEMM_SMEM (GSTAGE * 3)            /* 92160 -> 2 CTAs/SM */

__global__ __launch_bounds__(256, 2) void qkv_gemm(
    const __nv_bfloat16* __restrict__ Ahi,
    const __nv_bfloat16* __restrict__ WhiB, const __nv_bfloat16* __restrict__ WloB,
    const float* __restrict__ theta,
    __nv_bfloat16* __restrict__ OHB)
{
    extern __shared__ __align__(16) char smem[];
    uint32_t sb = smem_u32(smem);

    int z = blockIdx.z;
    const __nv_bfloat16* Whi = WhiB + (size_t)z * Ee * Ee;
    const __nv_bfloat16* Wlo = WloB + (size_t)z * Ee * Ee;

    int tid = threadIdx.x, wid = tid >> 5, lane = tid & 31;
    int wm = wid & 1, wn = wid >> 1;
    int g = lane >> 2, t = lane & 3;
    int lm = lane >> 3, li = lane & 7;
    int m0 = blockIdx.y * 128, n0 = blockIdx.x * 128;

    float acc[4][4][4] = {};

    auto issue = [&](int c) {
        uint32_t b0 = sb + (c % 3) * GSTAGE;
#pragma unroll
        for (int u = 0; u < 2; u++) {
            int unit = tid + u * 256;
            int row = unit >> 2, seg = unit & 3;
            size_t gA = (size_t)(m0 + row) * Ee + c * 32 + seg * 8;
            size_t gW = (size_t)(n0 + row) * Ee + c * 32 + seg * 8;
            uint32_t so = (uint32_t)(row * PG + seg * 8) * 2;
            cpa16(b0 + so,            Ahi + gA);
            cpa16(b0 + GT_B + so,     Whi + gW);
            cpa16(b0 + 2 * GT_B + so, Wlo + gW);
        }
    };

    issue(0); CPA_COMMIT();
    issue(1); CPA_COMMIT();

    for (int c = 0; c < 32; c++) {
        if (c == 31) CPA_WAIT0(); else CPA_WAIT1();
        __syncthreads();
        if (c < 30) { issue(c + 2); CPA_COMMIT(); }

        uint32_t bufA = sb + (c % 3) * GSTAGE;
        uint32_t bufW = bufA + GT_B;

#pragma unroll
        for (int ks = 0; ks < 2; ks++) {
            uint32_t ah[4][4];
#pragma unroll
            for (int mf = 0; mf < 4; mf++) {
                uint32_t ad = bufA +
                    (uint32_t)(((wm * 64 + mf * 16 + (lm & 1) * 8 + li) * PG)
                               + ks * 16 + (lm >> 1) * 8) * 2;
                ldsm_x4(ah[mf], ad);
            }
#pragma unroll
            for (int nfp = 0; nfp < 2; nfp++) {
                uint32_t bd = bufW +
                    (uint32_t)(((wn * 32 + (nfp * 2 + (lm >> 1)) * 8 + li) * PG)
                               + ks * 16 + (lm & 1) * 8) * 2;
                uint32_t bh[4], bl[4];
                ldsm_x4(bh, bd);
                ldsm_x4(bl, bd + GT_B);
#pragma unroll
                for (int mf = 0; mf < 4; mf++) {
                    mma16816(acc[mf][nfp*2],   ah[mf], bh);
                    mma16816(acc[mf][nfp*2+1], ah[mf], bh + 2);
                }
#pragma unroll
                for (int mf = 0; mf < 4; mf++) {
                    mma16816(acc[mf][nfp*2],   ah[mf], bl);
                    mma16816(acc[mf][nfp*2+1], ah[mf], bl + 2);
                }
            }
        }
    }

    __nv_bfloat16* OH = OHB + (size_t)z * Mm * Ee;
    float osc = (z == 0) ? QSCALE : 1.0f;
#pragma unroll
    for (int mf = 0; mf < 4; mf++) {
#pragma unroll
        for (int nf = 0; nf < 4; nf++) {
            int r = m0 + wm * 64 + mf * 16 + g;
            int cb = n0 + wn * 32 + nf * 8 + 2 * t;
            float t0 = theta[cb & 63], t1 = theta[(cb + 1) & 63];
            float v0 = __cosf(acc[mf][nf][0] + t0) * osc;
            float v1 = __cosf(acc[mf][nf][1] + t1) * osc;
            float v2 = __cosf(acc[mf][nf][2] + t0) * osc;
            float v3 = __cosf(acc[mf][nf][3] + t1) * osc;
            *(uint32_t*)&OH[(size_t)r * Ee + cb]       = pack_hi(v0, v1);
            *(uint32_t*)&OH[(size_t)(r + 8) * Ee + cb] = pack_hi(v2, v3);
        }
    }
}

// ------------------------- Wo: TF32 1-term GEMM ------------------------------
// 128x128 CTA tile, K-chunk 32, pitch 36 fp32, 3-stage single-sync ring.
#define PW 36
#define WT_B (128 * PW * 4)               /* 18432 per array */
#define WSTAGE (WT_B * 2)                 /* 36864 */
#define WO_SMEM (WSTAGE * 3)              /* 110592 */

__global__ __launch_bounds__(256, 2) void wo_gemm(
    const float* __restrict__ A,
    const float* __restrict__ W,
    float* __restrict__ C)
{
    extern __shared__ __align__(16) char smem[];
    uint32_t sb = smem_u32(smem);

    int tid = threadIdx.x, wid = tid >> 5, lane = tid & 31;
    int wm = wid & 1, wn = wid >> 1;
    int g = lane >> 2, t = lane & 3;
    int lm = lane >> 3, li = lane & 7;
    int m0 = blockIdx.y * 128, n0 = blockIdx.x * 128;

    float acc[4][4][4] = {};

    auto issue = [&](int c) {
        uint32_t b0 = sb + (c % 3) * WSTAGE;
#pragma unroll
        for (int u = 0; u < 4; u++) {
            int unit = tid + u * 256;
            int row = unit >> 3, seg = unit & 7;
            size_t gA = (size_t)(m0 + row) * Ee + c * 32 + seg * 4;
            size_t gW = (size_t)(n0 + row) * Ee + c * 32 + seg * 4;
            uint32_t so = (uint32_t)(row * PW + seg * 4) * 4;
            cpa16(b0 + so,        A + gA);
            cpa16(b0 + WT_B + so, W + gW);
        }
    };

    issue(0); CPA_COMMIT();
    issue(1); CPA_COMMIT();

    for (int c = 0; c < 32; c++) {
        if (c == 31) CPA_WAIT0(); else CPA_WAIT1();
        __syncthreads();
        if (c < 30) { issue(c + 2); CPA_COMMIT(); }

        uint32_t bufA = sb + (c % 3) * WSTAGE;
        uint32_t bufW = bufA + WT_B;

#pragma unroll
        for (int ks = 0; ks < 4; ks++) {
            uint32_t av[4][4];
#pragma unroll
            for (int mf = 0; mf < 4; mf++) {
                uint32_t ad = bufA +
                    (uint32_t)((wm * 64 + mf * 16 + (lm & 1) * 8 + li) * PW) * 4
                    + ks * 32 + (lm >> 1) * 16;
                ldsm_x4(av[mf], ad);
            }
#pragma unroll
            for (int np = 0; np < 2; np++) {
                uint32_t bd = bufW +
                    (uint32_t)((wn * 32 + np * 16 + (lm >> 1) * 8 + li) * PW) * 4
                    + ks * 32 + (lm & 1) * 16;
                uint32_t bv[4];
                ldsm_x4(bv, bd);
#pragma unroll
                for (int mf = 0; mf < 4; mf++) {
                    mma1688_tf32(acc[mf][np*2],   av[mf], bv);
                    mma1688_tf32(acc[mf][np*2+1], av[mf], bv + 2);
                }
            }
        }
    }

#pragma unroll
    for (int mf = 0; mf < 4; mf++) {
#pragma unroll
        for (int nf = 0; nf < 4; nf++) {
            int r = m0 + wm * 64 + mf * 16 + g;
            int cb = n0 + wn * 32 + nf * 8 + 2 * t;
            *(float2*)&C[(size_t)r * Ee + cb] =
                float2{acc[mf][nf][0], acc[mf][nf][1]};
            *(float2*)&C[(size_t)(r + 8) * Ee + cb] =
                float2{acc[mf][nf][2], acc[mf][nf][3]};
        }
    }
}

// ------------------------- HMMA flash attention (unchanged from R16) ---------
#define PKV 72
#define KVB (64 * PKV * 2)               /* 9216 */
#define STAGEB (KVB * 2)                 /* 18432 */
#define ATT_SMEM (STAGEB * 3)            /* 55296 */

__global__ __launch_bounds__(256, 2) void attn_mma(
    const __nv_bfloat16* __restrict__ qhi,
    const __nv_bfloat16* __restrict__ khi,
    const __nv_bfloat16* __restrict__ vhi,
    float* __restrict__ ctx)
{
    extern __shared__ __align__(16) char smem[];
    uint32_t sb = smem_u32(smem);

    int tid = threadIdx.x, wid = tid >> 5, lane = tid & 31;
    int g = lane >> 2, t = lane & 3;
    int lm = lane >> 3, li = lane & 7;
    int bh_ = blockIdx.y;
    int b = bh_ >> 4, h = bh_ & 15;
    int q0 = blockIdx.x * 128;
    size_t base = (size_t)b * Ss * Ee + (size_t)h * Dk;

    uint32_t qh[4][4];
    {
        size_t r0 = base + (size_t)(q0 + wid * 16 + g) * Ee;
        size_t r1 = r0 + 8 * (size_t)Ee;
#pragma unroll
        for (int ks = 0; ks < 4; ks++) {
            int c0 = ks * 16 + 2 * t;
            qh[ks][0] = *(const uint32_t*)&qhi[r0 + c0];
            qh[ks][1] = *(const uint32_t*)&qhi[r1 + c0];
            qh[ks][2] = *(const uint32_t*)&qhi[r0 + c0 + 8];
            qh[ks][3] = *(const uint32_t*)&qhi[r1 + c0 + 8];
        }
    }

    auto issue = [&](int j0, int s) {
        uint32_t b0 = sb + s * STAGEB;
#pragma unroll
        for (int u = 0; u < 2; u++) {
            int unit = tid + u * 256;
            int row = unit >> 3, seg = unit & 7;
            size_t gk = base + (size_t)(j0 + row) * Ee + seg * 8;
            uint32_t so = (uint32_t)(row * PKV + seg * 8) * 2;
            cpa16(b0 + so,       khi + gk);
            cpa16(b0 + KVB + so, vhi + gk);
        }
    };

    float l0 = 0.0f, l1 = 0.0f;
    float out[8][4] = {};

    issue(0, 0);  CPA_COMMIT();
    issue(64, 1); CPA_COMMIT();

    for (int tile = 0; tile < 32; tile++) {
        if (tile == 31) CPA_WAIT0(); else CPA_WAIT1();
        __syncthreads();
        if (tile < 30) { issue((tile + 2) * 64, (tile + 2) % 3); CPA_COMMIT(); }

        uint32_t kb = sb + (tile % 3) * STAGEB;
        uint32_t vb = kb + KVB;

        float s[8][4] = {};
#pragma unroll
        for (int ks = 0; ks < 4; ks++) {
#pragma unroll
            for (int nfp = 0; nfp < 4; nfp++) {
                uint32_t ad = kb +
                    (uint32_t)(((nfp * 2 + (lm >> 1)) * 8 + li) * PKV
                               + ks * 16 + (lm & 1) * 8) * 2;
                uint32_t bhv[4];
                ldsm_x4(bhv, ad);
                mma16816(s[nfp*2],   qh[ks], bhv);
                mma16816(s[nfp*2+1], qh[ks], bhv + 2);
            }
        }

#pragma unroll
        for (int nf = 0; nf < 8; nf++) {
            s[nf][0] = ex2(s[nf][0]);
            s[nf][1] = ex2(s[nf][1]);
            s[nf][2] = ex2(s[nf][2]);
            s[nf][3] = ex2(s[nf][3]);
            l0 += s[nf][0] + s[nf][1];
            l1 += s[nf][2] + s[nf][3];
        }

        uint32_t pa[4][4];
#pragma unroll
        for (int k2 = 0; k2 < 4; k2++) {
            pa[k2][0] = pack_hi(s[2*k2][0],   s[2*k2][1]);
            pa[k2][1] = pack_hi(s[2*k2][2],   s[2*k2][3]);
            pa[k2][2] = pack_hi(s[2*k2+1][0], s[2*k2+1][1]);
            pa[k2][3] = pack_hi(s[2*k2+1][2], s[2*k2+1][3]);
        }

#pragma unroll
        for (int ks2 = 0; ks2 < 4; ks2++) {
#pragma unroll
            for (int nfp = 0; nfp < 4; nfp++) {
                uint32_t ad = vb +
                    (uint32_t)((ks2 * 16 + (lm & 1) * 8 + li) * PKV
                               + (nfp * 2 + (lm >> 1)) * 8) * 2;
                uint32_t bvh[4];
                ldsm_x4_t(bvh, ad);
                mma16816(out[nfp*2],   pa[ks2], bvh);
                mma16816(out[nfp*2+1], pa[ks2], bvh + 2);
            }
        }
    }

    l0 += __shfl_xor_sync(0xffffffffu, l0, 1);
    l0 += __shfl_xor_sync(0xffffffffu, l0, 2);
    l1 += __shfl_xor_sync(0xffffffffu, l1, 1);
    l1 += __shfl_xor_sync(0xffffffffu, l1, 2);

    float inv0 = 1.0f / l0, inv1 = 1.0f / l1;
    size_t r0 = base + (size_t)(q0 + wid * 16 + g) * Ee;
    size_t r1 = r0 + 8 * (size_t)Ee;
#pragma unroll
    for (int nfo = 0; nfo < 8; nfo++) {
        int d = nfo * 8 + 2 * t;
        *(float2*)&ctx[r0 + d] = float2{tf32r(out[nfo][0] * inv0),
                                        tf32r(out[nfo][1] * inv0)};
        *(float2*)&ctx[r1 + d] = float2{tf32r(out[nfo][2] * inv1),
                                        tf32r(out[nfo][3] * inv1)};
    }
}

// ---------------------------------------------------------------------------
extern "C" void kernel_launch(void* const* d_in, const int* in_sizes, int n_in,
                              void* d_out, int out_size)
{
    const float* x     = (const float*)d_in[0];
    const float* Wq    = (const float*)d_in[1];
    const float* Wk    = (const float*)d_in[2];
    const float* Wv    = (const float*)d_in[3];
    const float* Wo    = (const float*)d_in[4];
    const float* theta = (const float*)d_in[5];
    float* out = (float*)d_out;

    __nv_bfloat16 *xhi, *qkvhi, *whi, *wlo;
    float *ctx32, *wo32;
    cudaGetSymbolAddress((void**)&xhi, g_xhi);
    cudaGetSymbolAddress((void**)&qkvhi, g_qkvhi);
    cudaGetSymbolAddress((void**)&ctx32, g_ctx32);
    cudaGetSymbolAddress((void**)&whi, g_whi);
    cudaGetSymbolAddress((void**)&wlo, g_wlo);
    cudaGetSymbolAddress((void**)&wo32, g_wo32);

    cudaFuncSetAttribute(qkv_gemm,
        cudaFuncAttributeMaxDynamicSharedMemorySize, GEMM_SMEM);
    cudaFuncSetAttribute(wo_gemm,
        cudaFuncAttributeMaxDynamicSharedMemorySize, WO_SMEM);
    cudaFuncSetAttribute(attn_mma,
        cudaFuncAttributeMaxDynamicSharedMemorySize, ATT_SMEM);

    int n4x = Mm * Ee / 4;
    int n4w = Ee * Ee / 4;
    split_hi_kernel<<<(n4x + 255) / 256, 256>>>((const float4*)x, xhi, n4x);
    dim3 gw((n4w + 255) / 256, 3);
    split3_kernel<<<gw, 256>>>((const float4*)Wq, (const float4*)Wk,
                               (const float4*)Wv, whi, wlo, n4w);
    cvt_tf32_kernel<<<(n4w + 255) / 256, 256>>>((const float4*)Wo,
                                                (float4*)wo32, n4w);

    dim3 g1(Ee / 128, Mm / 128, 3);
    qkv_gemm<<<g1, 256, GEMM_SMEM>>>(xhi, whi, wlo, theta, qkvhi);

    size_t off = (size_t)Mm * Ee;
    dim3 g2(Ss / 128, Bb * Hh);
    attn_mma<<<g2, 256, ATT_SMEM>>>(qkvhi,
                                    qkvhi + off,
                                    qkvhi + 2*off,
                                    ctx32);

    dim3 g3(Ee / 128, Mm / 128);
    wo_gemm<<<g3, 256, WO_SMEM>>>(ctx32, wo32, out);
}